// round 5
// baseline (speedup 1.0000x reference)
#include <cuda_runtime.h>
#include <math.h>

#define S_LEN 2048
#define DMODEL 2048
#define NHQ 32
#define NHKV 4
#define HDIM 128
#define NEXP 8
#define FDIM 768
#define EPSV 1e-6f

// ---------------- scratch (device globals; no allocations allowed) ----------------
__device__ float g_x[S_LEN * DMODEL];          // rmsnorm1 output
__device__ float g_q[S_LEN * NHQ * HDIM];
__device__ float g_k[S_LEN * NHKV * HDIM];
__device__ float g_v[S_LEN * NHKV * HDIM];
__device__ float g_attn[S_LEN * NHQ * HDIM];   // attention output (pre-Wo)
__device__ float g_attnout[S_LEN * DMODEL];    // attn @ Wo
__device__ float g_hidden2[S_LEN * DMODEL];    // residual after attention
__device__ float g_xf[S_LEN * DMODEL];         // rmsnorm2 output
__device__ float g_h[S_LEN * 2 * FDIM];        // expert hidden (silu) per slot
__device__ float g_moepart[S_LEN * 2 * DMODEL];// per-slot expert output (gated)
__device__ float g_gate[S_LEN * 2];
__device__ int   g_cnt[NEXP];
__device__ int   g_list[NEXP][S_LEN];

// ---------------- rmsnorm over last dim D (float4 vectorized) ----------------
__global__ void rmsnorm_k(const float* __restrict__ in, const float* __restrict__ sc,
                          float* __restrict__ out) {
    int row = blockIdx.x;
    const float4* r4 = (const float4*)(in + (size_t)row * DMODEL);
    const float4* s4 = (const float4*)sc;
    float4* o4 = (float4*)(out + (size_t)row * DMODEL);
    float ss = 0.f;
    for (int i = threadIdx.x; i < DMODEL / 4; i += 256) {
        float4 v = r4[i];
        ss += v.x * v.x + v.y * v.y + v.z * v.z + v.w * v.w;
    }
    for (int o = 16; o; o >>= 1) ss += __shfl_xor_sync(0xffffffffu, ss, o);
    __shared__ float red[8];
    if ((threadIdx.x & 31) == 0) red[threadIdx.x >> 5] = ss;
    __syncthreads();
    float tot = 0.f;
#pragma unroll
    for (int i = 0; i < 8; i++) tot += red[i];
    float inv = rsqrtf(tot / (float)DMODEL + EPSV);
    for (int i = threadIdx.x; i < DMODEL / 4; i += 256) {
        float4 v = r4[i], s = s4[i];
        float4 w;
        w.x = v.x * inv * s.x; w.y = v.y * inv * s.y;
        w.z = v.z * inv * s.z; w.w = v.w * inv * s.w;
        o4[i] = w;
    }
}

// ---------------- per-head rmsnorm + rope, in place ----------------
__global__ void qknorm_rope_k(float* __restrict__ q, const float* __restrict__ sc, int H) {
    int s = blockIdx.x, h = blockIdx.y;
    float* row = q + ((size_t)s * H + h) * HDIM;
    int d = threadIdx.x;   // 128 threads
    float v = row[d];
    float ss = v * v;
    for (int o = 16; o; o >>= 1) ss += __shfl_xor_sync(0xffffffffu, ss, o);
    __shared__ float red[4];
    if ((d & 31) == 0) red[d >> 5] = ss;
    __syncthreads();
    float tot = red[0] + red[1] + red[2] + red[3];
    float n = v * rsqrtf(tot / (float)HDIM + EPSV) * sc[d];
    __shared__ float ns[HDIM];
    ns[d] = n;
    __syncthreads();
    int j = d & 63;
    float invf = 1.0f / powf(1.0e6f, (float)j / 64.0f);
    float ang = (float)s * invf;
    float si, c;
    sincosf(ang, &si, &c);
    float rot = (d < 64) ? -ns[d + 64] : ns[d - 64];
    row[d] = n * c + rot * si;
}

// ---------------- generic fp32 GEMM: C[M,N] = A[M,K] @ B[K,N], 128x128x16, 8x8 microtile ----------------
__global__ void gemm128_k(const float* __restrict__ A, const float* __restrict__ B,
                          float* __restrict__ C, int M, int Kd, int N) {
    __shared__ float As[128][17];
    __shared__ float4 Bs4[16][32];
    float* Bs = (float*)Bs4;
    int tid = threadIdx.x;
    int tx = tid & 15, ty = tid >> 4;
    int m0 = blockIdx.y * 128, n0 = blockIdx.x * 128;
    float c[8][8] = {};
    for (int k0 = 0; k0 < Kd; k0 += 16) {
#pragma unroll
        for (int l = tid; l < 128 * 16; l += 256) {
            int mm = l >> 4, kk = l & 15;
            As[mm][kk] = A[(size_t)(m0 + mm) * Kd + k0 + kk];
        }
#pragma unroll
        for (int l = tid; l < 16 * 128; l += 256) {
            int kk = l >> 7, nn = l & 127;
            Bs[kk * 128 + nn] = B[(size_t)(k0 + kk) * N + n0 + nn];
        }
        __syncthreads();
#pragma unroll
        for (int kk = 0; kk < 16; kk++) {
            float a[8], b[8];
#pragma unroll
            for (int i = 0; i < 8; i++) a[i] = As[ty * 8 + i][kk];
            float4 b0 = Bs4[kk][tx * 2];
            float4 b1 = Bs4[kk][tx * 2 + 1];
            b[0] = b0.x; b[1] = b0.y; b[2] = b0.z; b[3] = b0.w;
            b[4] = b1.x; b[5] = b1.y; b[6] = b1.z; b[7] = b1.w;
#pragma unroll
            for (int i = 0; i < 8; i++)
#pragma unroll
                for (int jj = 0; jj < 8; jj++) c[i][jj] += a[i] * b[jj];
        }
        __syncthreads();
    }
#pragma unroll
    for (int i = 0; i < 8; i++)
#pragma unroll
        for (int jj = 0; jj < 8; jj++)
            C[(size_t)(m0 + ty * 8 + i) * N + n0 + tx * 8 + jj] = c[i][jj];
}

// ---------------- causal GQA flash attention, 64q x 64k tiles, fp32 ----------------
#define ATTN_SMEM ((2 * 64 * 129 + 64 * 65 + 3 * 64) * 4)
__global__ void attn_k() {
    extern __shared__ float sm[];
    float* Qs  = sm;                  // 64 x 129
    float* KVs = Qs + 64 * 129;       // 64 x 129
    float* Ss  = KVs + 64 * 129;      // 64 x 65
    float* mrow = Ss + 64 * 65;
    float* lrow = mrow + 64;
    float* arow = lrow + 64;
    int h = blockIdx.y;
    int q0 = blockIdx.x * 64;
    int kvh = h >> 3;                 // HQ/HKV = 8
    int tid = threadIdx.x, tx = tid & 15, ty = tid >> 4;
    const float scale = 0.08838834764831845f;  // 1/sqrt(128)

#pragma unroll
    for (int l = tid; l < 64 * HDIM; l += 256) {
        int i = l >> 7, d = l & 127;
        Qs[i * 129 + d] = g_q[((size_t)(q0 + i) * NHQ + h) * HDIM + d] * scale;
    }
    if (tid < 64) { mrow[tid] = -3e38f; lrow[tid] = 0.f; }
    float o[4][8];
#pragma unroll
    for (int i = 0; i < 4; i++)
#pragma unroll
        for (int jj = 0; jj < 8; jj++) o[i][jj] = 0.f;
    __syncthreads();

    int ntiles = q0 / 64;
    for (int t = 0; t <= ntiles; t++) {
        int k0 = t * 64;
        // load K tile
#pragma unroll
        for (int l = tid; l < 64 * HDIM; l += 256) {
            int i = l >> 7, d = l & 127;
            KVs[i * 129 + d] = g_k[((size_t)(k0 + i) * NHKV + kvh) * HDIM + d];
        }
        __syncthreads();
        // scores: 4x4 per thread
        float sacc[4][4] = {};
        for (int kk = 0; kk < HDIM; kk++) {
            float a[4], b[4];
#pragma unroll
            for (int i = 0; i < 4; i++) a[i] = Qs[(ty * 4 + i) * 129 + kk];
#pragma unroll
            for (int jj = 0; jj < 4; jj++) b[jj] = KVs[(tx * 4 + jj) * 129 + kk];
#pragma unroll
            for (int i = 0; i < 4; i++)
#pragma unroll
                for (int jj = 0; jj < 4; jj++) sacc[i][jj] += a[i] * b[jj];
        }
#pragma unroll
        for (int i = 0; i < 4; i++)
#pragma unroll
            for (int jj = 0; jj < 4; jj++) {
                int qg = q0 + ty * 4 + i, kg = k0 + tx * 4 + jj;
                Ss[(ty * 4 + i) * 65 + tx * 4 + jj] = (kg > qg) ? -1e9f : sacc[i][jj];
            }
        __syncthreads();
        // online softmax per query row
        if (tid < 64) {
            float mo = mrow[tid], mx = mo;
            float* sr = Ss + tid * 65;
            for (int k2 = 0; k2 < 64; k2++) mx = fmaxf(mx, sr[k2]);
            float al = expf(mo - mx);
            float sum = 0.f;
            for (int k2 = 0; k2 < 64; k2++) { float p = expf(sr[k2] - mx); sr[k2] = p; sum += p; }
            lrow[tid] = lrow[tid] * al + sum;
            mrow[tid] = mx;
            arow[tid] = al;
        }
        __syncthreads();
        float al4[4];
#pragma unroll
        for (int i = 0; i < 4; i++) al4[i] = arow[ty * 4 + i];
#pragma unroll
        for (int i = 0; i < 4; i++)
#pragma unroll
            for (int jj = 0; jj < 8; jj++) o[i][jj] *= al4[i];
        // load V tile (overwrites K tile)
#pragma unroll
        for (int l = tid; l < 64 * HDIM; l += 256) {
            int i = l >> 7, d = l & 127;
            KVs[i * 129 + d] = g_v[((size_t)(k0 + i) * NHKV + kvh) * HDIM + d];
        }
        __syncthreads();
        // O += P @ V : thread owns 4 queries x 8 dims
        for (int kk = 0; kk < 64; kk++) {
            float p[4];
#pragma unroll
            for (int i = 0; i < 4; i++) p[i] = Ss[(ty * 4 + i) * 65 + kk];
            float vv[8];
#pragma unroll
            for (int jj = 0; jj < 8; jj++) vv[jj] = KVs[kk * 129 + tx * 8 + jj];
#pragma unroll
            for (int i = 0; i < 4; i++)
#pragma unroll
                for (int jj = 0; jj < 8; jj++) o[i][jj] += p[i] * vv[jj];
        }
        __syncthreads();
    }
#pragma unroll
    for (int i = 0; i < 4; i++) {
        float linv = 1.0f / lrow[ty * 4 + i];
#pragma unroll
        for (int jj = 0; jj < 8; jj++)
            g_attn[((size_t)(q0 + ty * 4 + i) * NHQ + h) * HDIM + tx * 8 + jj] = o[i][jj] * linv;
    }
}

// ---------------- residual add after attention (float4) ----------------
__global__ void addres_k(const float* __restrict__ hs) {
    int i = blockIdx.x * 256 + threadIdx.x;
    const float4* a = (const float4*)hs;
    const float4* b = (const float4*)g_attnout;
    float4* o = (float4*)g_hidden2;
    float4 va = a[i], vb = b[i];
    float4 w;
    w.x = va.x + vb.x; w.y = va.y + vb.y; w.z = va.z + vb.z; w.w = va.w + vb.w;
    o[i] = w;
}

// ---------------- init: zero expert counts, write constant aux_loss ----------------
__global__ void init_k(float* __restrict__ out) {
    if (threadIdx.x < NEXP) g_cnt[threadIdx.x] = 0;
    if (threadIdx.x == 0) out[(size_t)S_LEN * DMODEL + S_LEN * NEXP] = 1.0f;
}

// ---------------- router: logits, softmax, top-2, build expert lists ----------------
__global__ void router_k(const float* __restrict__ rW, float* __restrict__ out) {
    int t = blockIdx.x;
    const float* xr = g_xf + (size_t)t * DMODEL;
    int w = threadIdx.x >> 5, lane = threadIdx.x & 31;
    float sum = 0.f;
    for (int dd = lane; dd < DMODEL; dd += 32) sum += xr[dd] * rW[dd * NEXP + w];
    for (int o = 16; o; o >>= 1) sum += __shfl_xor_sync(0xffffffffu, sum, o);
    __shared__ float lg[NEXP];
    if (lane == 0) lg[w] = sum;
    __syncthreads();
    if (threadIdx.x == 0) {
        float* lo = out + (size_t)S_LEN * DMODEL + (size_t)t * NEXP;
        float mx = lg[0];
#pragma unroll
        for (int e = 1; e < NEXP; e++) mx = fmaxf(mx, lg[e]);
        float p[NEXP];
#pragma unroll
        for (int e = 0; e < NEXP; e++) { p[e] = expf(lg[e] - mx); lo[e] = lg[e]; }
        int i1 = 0;
#pragma unroll
        for (int e = 1; e < NEXP; e++) if (lg[e] > lg[i1]) i1 = e;
        int i2 = -1;
#pragma unroll
        for (int e = 0; e < NEXP; e++) {
            if (e == i1) continue;
            if (i2 < 0 || lg[e] > lg[i2]) i2 = e;
        }
        float denom = p[i1] + p[i2];
        g_gate[t * 2]     = p[i1] / denom;
        g_gate[t * 2 + 1] = p[i2] / denom;
        int pos = atomicAdd(&g_cnt[i1], 1);
        g_list[i1][pos] = t * 2;
        pos = atomicAdd(&g_cnt[i2], 1);
        g_list[i2][pos] = t * 2 + 1;
    }
}

// ---------------- MoE up: h[idx] = silu(xf[t] @ up_W[e] + up_b[e]) ----------------
__global__ void moe_up_k(const float* __restrict__ W, const float* __restrict__ bia) {
    int e = blockIdx.z;
    int cnt = g_cnt[e];
    int m0 = blockIdx.y * 64;
    if (m0 >= cnt) return;
    int n0 = blockIdx.x * 64;
    __shared__ int rows[64];
    __shared__ float As[64][17];
    __shared__ float Bs[16][65];
    int tid = threadIdx.x, tx = tid & 15, ty = tid >> 4;
    if (tid < 64) rows[tid] = (m0 + tid < cnt) ? g_list[e][m0 + tid] : -1;
    __syncthreads();
    const float* B = W + (size_t)e * DMODEL * FDIM;
    float c[4][4] = {};
    for (int k0 = 0; k0 < DMODEL; k0 += 16) {
#pragma unroll
        for (int l = tid; l < 64 * 16; l += 256) {
            int mm = l >> 4, kk = l & 15;
            int idx = rows[mm];
            As[mm][kk] = (idx >= 0) ? g_xf[(size_t)(idx >> 1) * DMODEL + k0 + kk] : 0.f;
        }
#pragma unroll
        for (int l = tid; l < 16 * 64; l += 256) {
            int kk = l >> 6, nn = l & 63;
            Bs[kk][nn] = B[(size_t)(k0 + kk) * FDIM + n0 + nn];
        }
        __syncthreads();
#pragma unroll
        for (int kk = 0; kk < 16; kk++) {
            float a[4], b[4];
#pragma unroll
            for (int i = 0; i < 4; i++) a[i] = As[ty * 4 + i][kk];
#pragma unroll
            for (int jj = 0; jj < 4; jj++) b[jj] = Bs[kk][tx * 4 + jj];
#pragma unroll
            for (int i = 0; i < 4; i++)
#pragma unroll
                for (int jj = 0; jj < 4; jj++) c[i][jj] += a[i] * b[jj];
        }
        __syncthreads();
    }
#pragma unroll
    for (int i = 0; i < 4; i++) {
        int r = ty * 4 + i;
        int idx = rows[r];
        if (idx < 0) continue;
#pragma unroll
        for (int jj = 0; jj < 4; jj++) {
            int f = n0 + tx * 4 + jj;
            float v = c[i][jj] + bia[e * FDIM + f];
            g_h[(size_t)idx * FDIM + f] = v / (1.0f + expf(-v));
        }
    }
}

// ---------------- MoE down: part[idx] = gate * (h[idx] @ down_W[e] + down_b[e]) ----------------
__global__ void moe_down_k(const float* __restrict__ W, const float* __restrict__ bia) {
    int e = blockIdx.z;
    int cnt = g_cnt[e];
    int m0 = blockIdx.y * 64;
    if (m0 >= cnt) return;
    int n0 = blockIdx.x * 64;
    __shared__ int rows[64];
    __shared__ float As[64][17];
    __shared__ float Bs[16][65];
    int tid = threadIdx.x, tx = tid & 15, ty = tid >> 4;
    if (tid < 64) rows[tid] = (m0 + tid < cnt) ? g_list[e][m0 + tid] : -1;
    __syncthreads();
    const float* B = W + (size_t)e * FDIM * DMODEL;
    float c[4][4] = {};
    for (int k0 = 0; k0 < FDIM; k0 += 16) {
#pragma unroll
        for (int l = tid; l < 64 * 16; l += 256) {
            int mm = l >> 4, kk = l & 15;
            int idx = rows[mm];
            As[mm][kk] = (idx >= 0) ? g_h[(size_t)idx * FDIM + k0 + kk] : 0.f;
        }
#pragma unroll
        for (int l = tid; l < 16 * 64; l += 256) {
            int kk = l >> 6, nn = l & 63;
            Bs[kk][nn] = B[(size_t)(k0 + kk) * DMODEL + n0 + nn];
        }
        __syncthreads();
#pragma unroll
        for (int kk = 0; kk < 16; kk++) {
            float a[4], b[4];
#pragma unroll
            for (int i = 0; i < 4; i++) a[i] = As[ty * 4 + i][kk];
#pragma unroll
            for (int jj = 0; jj < 4; jj++) b[jj] = Bs[kk][tx * 4 + jj];
#pragma unroll
            for (int i = 0; i < 4; i++)
#pragma unroll
                for (int jj = 0; jj < 4; jj++) c[i][jj] += a[i] * b[jj];
        }
        __syncthreads();
    }
#pragma unroll
    for (int i = 0; i < 4; i++) {
        int r = ty * 4 + i;
        int idx = rows[r];
        if (idx < 0) continue;
        float gt = g_gate[idx];
#pragma unroll
        for (int jj = 0; jj < 4; jj++) {
            int dcol = n0 + tx * 4 + jj;
            g_moepart[(size_t)idx * DMODEL + dcol] = gt * (c[i][jj] + bia[e * DMODEL + dcol]);
        }
    }
}

// ---------------- final: out = residual + both expert-slot contributions ----------------
__global__ void final_k(float* __restrict__ out) {
    int i = blockIdx.x * 256 + threadIdx.x;   // float4 index
    int t = i / (DMODEL / 4);
    int d = i - t * (DMODEL / 4);
    const float4* h2 = (const float4*)g_hidden2;
    const float4* mp = (const float4*)g_moepart;
    float4 a = h2[i];
    float4 b = mp[(size_t)(2 * t) * (DMODEL / 4) + d];
    float4 c = mp[(size_t)(2 * t + 1) * (DMODEL / 4) + d];
    float4 w;
    w.x = a.x + b.x + c.x; w.y = a.y + b.y + c.y;
    w.z = a.z + b.z + c.z; w.w = a.w + b.w + c.w;
    ((float4*)out)[i] = w;
}

// ---------------- launch ----------------
extern "C" void kernel_launch(void* const* d_in, const int* in_sizes, int n_in,
                              void* d_out, int out_size) {
    const float* hs  = (const float*)d_in[0];
    const float* ln1 = (const float*)d_in[1];
    const float* ln2 = (const float*)d_in[2];
    const float* Wq  = (const float*)d_in[3];
    const float* Wk  = (const float*)d_in[4];
    const float* Wv  = (const float*)d_in[5];
    const float* Wo  = (const float*)d_in[6];
    const float* qns = (const float*)d_in[7];
    const float* kns = (const float*)d_in[8];
    const float* rW  = (const float*)d_in[9];
    const float* upW = (const float*)d_in[10];
    const float* upb = (const float*)d_in[11];
    const float* dnW = (const float*)d_in[12];
    const float* dnb = (const float*)d_in[13];
    float* out = (float*)d_out;

    float *px, *pq, *pk, *pv, *pattn, *pao, *ph2, *pxf;
    cudaGetSymbolAddress((void**)&px,    g_x);
    cudaGetSymbolAddress((void**)&pq,    g_q);
    cudaGetSymbolAddress((void**)&pk,    g_k);
    cudaGetSymbolAddress((void**)&pv,    g_v);
    cudaGetSymbolAddress((void**)&pattn, g_attn);
    cudaGetSymbolAddress((void**)&pao,   g_attnout);
    cudaGetSymbolAddress((void**)&ph2,   g_hidden2);
    cudaGetSymbolAddress((void**)&pxf,   g_xf);

    cudaFuncSetAttribute(attn_k, cudaFuncAttributeMaxDynamicSharedMemorySize, ATTN_SMEM);

    // 1. rmsnorm1
    rmsnorm_k<<<S_LEN, 256>>>(hs, ln1, px);
    // 2. QKV projections
    gemm128_k<<<dim3(32, 16), 256>>>(px, Wq, pq, S_LEN, DMODEL, NHQ * HDIM);
    gemm128_k<<<dim3(4, 16), 256>>>(px, Wk, pk, S_LEN, DMODEL, NHKV * HDIM);
    gemm128_k<<<dim3(4, 16), 256>>>(px, Wv, pv, S_LEN, DMODEL, NHKV * HDIM);
    // 3. per-head norm + rope
    qknorm_rope_k<<<dim3(S_LEN, NHQ), 128>>>(pq, qns, NHQ);
    qknorm_rope_k<<<dim3(S_LEN, NHKV), 128>>>(pk, kns, NHKV);
    // 4. attention
    attn_k<<<dim3(S_LEN / 64, NHQ), 256, ATTN_SMEM>>>();
    // 5. output projection
    gemm128_k<<<dim3(16, 16), 256>>>(pattn, Wo, pao, S_LEN, NHQ * HDIM, DMODEL);
    // 6. residual
    addres_k<<<(S_LEN * DMODEL / 4) / 256, 256>>>(hs);
    // 7. rmsnorm2
    rmsnorm_k<<<S_LEN, 256>>>(ph2, ln2, pxf);
    // 8. router
    init_k<<<1, 32>>>(out);
    router_k<<<S_LEN, 256>>>(rW, out);
    // 9. MoE
    moe_up_k<<<dim3(FDIM / 64, S_LEN / 64, NEXP), 256>>>(upW, upb);
    moe_down_k<<<dim3(DMODEL / 64, S_LEN / 64, NEXP), 256>>>(dnW, dnb);
    // 10. final residual + MoE sum
    final_k<<<(S_LEN * DMODEL / 4) / 256, 256>>>(out);
}

// round 8
// speedup vs baseline: 2.5422x; 2.5422x over previous
#include <cuda_runtime.h>
#include <cuda_bf16.h>
#include <cuda_pipeline.h>
#include <math.h>
#include <stdint.h>

#define S_LEN 2048
#define DMODEL 2048
#define QKV_N 5120
#define NHQ 32
#define NHKV 4
#define HDIM 128
#define NEXP 8
#define FDIM 768
#define EPSV 1e-6f
#define ATTN_D (NHQ * HDIM)   // 4096

typedef __nv_bfloat16 bf16;

// ================= scratch (device globals; no allocations allowed) =================
__device__ __align__(256) bf16  g_x_hi[S_LEN * DMODEL];
__device__ __align__(256) bf16  g_x_lo[S_LEN * DMODEL];
__device__ __align__(256) float g_qkv[S_LEN * QKV_N];
__device__ __align__(256) float g_attn[S_LEN * ATTN_D];
__device__ __align__(256) bf16  g_attn_hi[S_LEN * ATTN_D];
__device__ __align__(256) bf16  g_attn_lo[S_LEN * ATTN_D];
__device__ __align__(256) float g_hidden2[S_LEN * DMODEL];
__device__ __align__(256) float g_xf[S_LEN * DMODEL];
__device__ __align__(256) bf16  g_xf_hi[S_LEN * DMODEL];
__device__ __align__(256) bf16  g_xf_lo[S_LEN * DMODEL];
__device__ __align__(256) bf16  g_h_hi[S_LEN * 2 * FDIM];
__device__ __align__(256) bf16  g_h_lo[S_LEN * 2 * FDIM];
__device__ __align__(256) float g_moepart[S_LEN * 2 * DMODEL];
__device__ float g_gate[S_LEN * 2];
__device__ int   g_cnt[NEXP];
__device__ int   g_list[NEXP][S_LEN];
// transposed + split weights: [N, K] row-major bf16
__device__ __align__(256) bf16 g_wqkv_hi[QKV_N * DMODEL];
__device__ __align__(256) bf16 g_wqkv_lo[QKV_N * DMODEL];
__device__ __align__(256) bf16 g_wo_hi[DMODEL * ATTN_D];
__device__ __align__(256) bf16 g_wo_lo[DMODEL * ATTN_D];
__device__ __align__(256) bf16 g_wup_hi[NEXP * FDIM * DMODEL];
__device__ __align__(256) bf16 g_wup_lo[NEXP * FDIM * DMODEL];
__device__ __align__(256) bf16 g_wdn_hi[NEXP * DMODEL * FDIM];
__device__ __align__(256) bf16 g_wdn_lo[NEXP * DMODEL * FDIM];

// ================= PTX helpers (sm_80-class only; no tcgen05) =================
__device__ __forceinline__ uint32_t smem_u32(const void* p) {
    uint32_t a;
    asm("{ .reg .u64 t; cvta.to.shared.u64 t, %1; cvt.u32.u64 %0, t; }" : "=r"(a) : "l"(p));
    return a;
}
__device__ __forceinline__ void ldsm4(uint32_t a, uint32_t r[4]) {
    asm volatile("ldmatrix.sync.aligned.m8n8.x4.shared.b16 {%0,%1,%2,%3}, [%4];"
                 : "=r"(r[0]), "=r"(r[1]), "=r"(r[2]), "=r"(r[3]) : "r"(a));
}
__device__ __forceinline__ void ldsm2(uint32_t a, uint32_t r[2]) {
    asm volatile("ldmatrix.sync.aligned.m8n8.x2.shared.b16 {%0,%1}, [%2];"
                 : "=r"(r[0]), "=r"(r[1]) : "r"(a));
}
__device__ __forceinline__ void mma16816(float c[4], const uint32_t a[4], const uint32_t b[2]) {
    asm volatile(
        "mma.sync.aligned.m16n8k16.row.col.f32.bf16.bf16.f32 "
        "{%0,%1,%2,%3}, {%4,%5,%6,%7}, {%8,%9}, {%0,%1,%2,%3};"
        : "+f"(c[0]), "+f"(c[1]), "+f"(c[2]), "+f"(c[3])
        : "r"(a[0]), "r"(a[1]), "r"(a[2]), "r"(a[3]), "r"(b[0]), "r"(b[1]));
}
// swizzled smem address: 128B rows, 16B segment XOR (row%8)
__device__ __forceinline__ uint32_t lds_addr(uint32_t base, int row, int kbyte) {
    int seg = kbyte >> 4;
    return base + row * 128 + (((uint32_t)(seg ^ (row & 7))) << 4);
}

// ================= weight transpose + bf16 hi/lo split =================
__global__ void tsplit_k(const float* __restrict__ in, bf16* __restrict__ hi,
                         bf16* __restrict__ lo, int R, int C,
                         size_t in_batch, size_t out_batch) {
    __shared__ float t[32][33];
    const float* inp = in + (size_t)blockIdx.z * in_batch;
    bf16* ho = hi + (size_t)blockIdx.z * out_batch;
    bf16* lo2 = lo + (size_t)blockIdx.z * out_batch;
    int r0 = blockIdx.y * 32, c0 = blockIdx.x * 32;
    int tx = threadIdx.x, ty = threadIdx.y;
    for (int i = ty; i < 32; i += 8)
        t[i][tx] = inp[(size_t)(r0 + i) * C + c0 + tx];
    __syncthreads();
    for (int i = ty; i < 32; i += 8) {
        float v = t[tx][i];
        bf16 h = __float2bfloat16(v);
        size_t o = (size_t)(c0 + i) * R + r0 + tx;
        ho[o] = h;
        lo2[o] = __float2bfloat16(v - __bfloat162float(h));
    }
}

// ================= rmsnorm variants =================
__global__ void rmsnorm1_split_k(const float* __restrict__ in, const float* __restrict__ sc) {
    int row = blockIdx.x;
    const float* r = in + (size_t)row * DMODEL;
    float ss = 0.f;
    for (int i = threadIdx.x; i < DMODEL; i += 256) { float v = r[i]; ss += v * v; }
    for (int o = 16; o; o >>= 1) ss += __shfl_xor_sync(0xffffffffu, ss, o);
    __shared__ float red[8];
    if ((threadIdx.x & 31) == 0) red[threadIdx.x >> 5] = ss;
    __syncthreads();
    float tot = 0.f;
#pragma unroll
    for (int i = 0; i < 8; i++) tot += red[i];
    float inv = rsqrtf(tot / (float)DMODEL + EPSV);
    for (int i = threadIdx.x; i < DMODEL; i += 256) {
        float w = r[i] * inv * sc[i];
        bf16 h = __float2bfloat16(w);
        size_t o = (size_t)row * DMODEL + i;
        g_x_hi[o] = h;
        g_x_lo[o] = __float2bfloat16(w - __bfloat162float(h));
    }
}

__global__ void rmsnorm2_split_k(const float* __restrict__ sc) {
    int row = blockIdx.x;
    const float* r = g_hidden2 + (size_t)row * DMODEL;
    float ss = 0.f;
    for (int i = threadIdx.x; i < DMODEL; i += 256) { float v = r[i]; ss += v * v; }
    for (int o = 16; o; o >>= 1) ss += __shfl_xor_sync(0xffffffffu, ss, o);
    __shared__ float red[8];
    if ((threadIdx.x & 31) == 0) red[threadIdx.x >> 5] = ss;
    __syncthreads();
    float tot = 0.f;
#pragma unroll
    for (int i = 0; i < 8; i++) tot += red[i];
    float inv = rsqrtf(tot / (float)DMODEL + EPSV);
    for (int i = threadIdx.x; i < DMODEL; i += 256) {
        float w = r[i] * inv * sc[i];
        size_t o = (size_t)row * DMODEL + i;
        g_xf[o] = w;
        bf16 h = __float2bfloat16(w);
        g_xf_hi[o] = h;
        g_xf_lo[o] = __float2bfloat16(w - __bfloat162float(h));
    }
}

// ================= per-head rmsnorm + rope, in place on g_qkv =================
__global__ void qknorm_rope_k(int col0, const float* __restrict__ sc) {
    int s = blockIdx.x, h = blockIdx.y;
    float* row = g_qkv + (size_t)s * QKV_N + col0 + h * HDIM;
    int d = threadIdx.x;   // 128 threads
    float v = row[d];
    float ss = v * v;
    for (int o = 16; o; o >>= 1) ss += __shfl_xor_sync(0xffffffffu, ss, o);
    __shared__ float red[4];
    if ((d & 31) == 0) red[d >> 5] = ss;
    __syncthreads();
    float tot = red[0] + red[1] + red[2] + red[3];
    float n = v * rsqrtf(tot / (float)HDIM + EPSV) * sc[d];
    __shared__ float ns[HDIM];
    ns[d] = n;
    __syncthreads();
    int j = d & 63;
    float invf = 1.0f / powf(1.0e6f, (float)j / 64.0f);
    float ang = (float)s * invf;
    float si, c;
    sincosf(ang, &si, &c);
    float rot = (d < 64) ? -ns[d + 64] : ns[d - 64];
    row[d] = n * c + rot * si;
}

// ================= HMMA split-bf16 GEMM =================
// MODE 0: QKV   : A=g_x (M=2048, K=2048), B=g_wqkv [5120,2048], C=g_qkv
// MODE 1: Wo    : A=g_attn (K=4096), B=g_wo [2048,4096], C=g_hidden2 (+residual)
// MODE 2: MoE up: A=g_xf gathered by slot>>1, B=g_wup[e], epi bias+silu -> g_h hi/lo
// MODE 3: MoE dn: A=g_h gathered by slot (K=768), B=g_wdn[e], epi gate*(acc+bias) -> g_moepart
#define STAGE_BYTES 65536
#define DSMEM (2 * STAGE_BYTES + 1024)

template<int MODE>
__global__ __launch_bounds__(256, 1) void mma_gemm_k(const float* __restrict__ residual,
                                                     const float* __restrict__ bias) {
    constexpr int K   = (MODE == 1) ? ATTN_D : (MODE == 3) ? FDIM : DMODEL;
    constexpr int NCH = K / 64;

    extern __shared__ char dyn[];
    __shared__ int rows_s[128];

    int tid = threadIdx.x, wid = tid >> 5, lane = tid & 31;
    int e = blockIdx.z;
    int m0 = blockIdx.y * 128;
    int n0 = blockIdx.x * 128;

    int cnt = 0;
    if (MODE >= 2) {
        cnt = g_cnt[e];
        if (m0 >= cnt) return;
        if (tid < 128)
            rows_s[tid] = (m0 + tid < cnt) ? g_list[e][m0 + tid] : g_list[e][0];
        __syncthreads();
    }

    const bf16 *Ahi, *Alo, *Bhi, *Blo;
    if (MODE == 0)      { Ahi = g_x_hi;    Alo = g_x_lo;    Bhi = g_wqkv_hi; Blo = g_wqkv_lo; }
    else if (MODE == 1) { Ahi = g_attn_hi; Alo = g_attn_lo; Bhi = g_wo_hi;   Blo = g_wo_lo; }
    else if (MODE == 2) { Ahi = g_xf_hi;   Alo = g_xf_lo;
                          Bhi = g_wup_hi + (size_t)e * FDIM * DMODEL;
                          Blo = g_wup_lo + (size_t)e * FDIM * DMODEL; }
    else                { Ahi = g_h_hi;    Alo = g_h_lo;
                          Bhi = g_wdn_hi + (size_t)e * DMODEL * FDIM;
                          Blo = g_wdn_lo + (size_t)e * DMODEL * FDIM; }

    uint32_t dyn_u = smem_u32(dyn);
    uint32_t tile0 = (dyn_u + 1023u) & ~1023u;
    char* tile0p = dyn + (tile0 - dyn_u);

    auto load_chunk = [&](int c, int s) {
        char* st = tile0p + s * STAGE_BYTES;
        for (int l = tid; l < 1024; l += 256) {
            int row = l >> 3, seg = l & 7;
            uint32_t off = (uint32_t)(row * 128 + seg * 16);
            uint32_t sw = off ^ ((off >> 3) & 0x70);
            size_t ar;
            if (MODE == 2)      ar = (size_t)(rows_s[row] >> 1) * K;
            else if (MODE == 3) ar = (size_t)rows_s[row] * K;
            else                ar = (size_t)(m0 + row) * K;
            size_t br = (size_t)(n0 + row) * K;
            __pipeline_memcpy_async(st + 0 * 16384 + sw, (const char*)(Ahi + ar + (size_t)c * 64) + seg * 16, 16);
            __pipeline_memcpy_async(st + 1 * 16384 + sw, (const char*)(Alo + ar + (size_t)c * 64) + seg * 16, 16);
            __pipeline_memcpy_async(st + 2 * 16384 + sw, (const char*)(Bhi + br + (size_t)c * 64) + seg * 16, 16);
            __pipeline_memcpy_async(st + 3 * 16384 + sw, (const char*)(Blo + br + (size_t)c * 64) + seg * 16, 16);
        }
    };

    // warp tile: 64x32 (4 m16-tiles x 4 n8-tiles); warps arranged 2 rows x 4 cols
    int warp_m0 = (wid >> 2) * 64;
    int warp_n0 = (wid & 3) * 32;
    int g = lane >> 2, tig = lane & 3;

    float c[4][4][4];
#pragma unroll
    for (int mi = 0; mi < 4; mi++)
#pragma unroll
        for (int nj = 0; nj < 4; nj++)
#pragma unroll
            for (int q = 0; q < 4; q++) c[mi][nj][q] = 0.f;

    load_chunk(0, 0);
    __pipeline_commit();

    for (int i = 0; i < NCH; i++) {
        if (i + 1 < NCH) load_chunk(i + 1, (i + 1) & 1);
        __pipeline_commit();
        __pipeline_wait_prior(1);
        __syncthreads();

        uint32_t su  = tile0 + (uint32_t)(i & 1) * STAGE_BYTES;
        uint32_t aHiB = su, aLoB = su + 16384, bHiB = su + 32768, bLoB = su + 49152;

#pragma unroll
        for (int kk = 0; kk < 4; kk++) {
            uint32_t Ah[4][4], Al[4][4], Bh[4][2], Bl[4][2];
            int a_row = lane & 15;
            int a_kb  = 32 * kk + ((lane >> 4) << 4);
#pragma unroll
            for (int mi = 0; mi < 4; mi++) {
                int row = warp_m0 + 16 * mi + a_row;
                ldsm4(lds_addr(aHiB, row, a_kb), Ah[mi]);
                ldsm4(lds_addr(aLoB, row, a_kb), Al[mi]);
            }
            int b_row = lane & 7;
            int b_kb  = 32 * kk + (((lane >> 3) & 1) << 4);
#pragma unroll
            for (int nj = 0; nj < 4; nj++) {
                int row = warp_n0 + 8 * nj + b_row;
                ldsm2(lds_addr(bHiB, row, b_kb), Bh[nj]);
                ldsm2(lds_addr(bLoB, row, b_kb), Bl[nj]);
            }
#pragma unroll
            for (int mi = 0; mi < 4; mi++)
#pragma unroll
                for (int nj = 0; nj < 4; nj++) {
                    mma16816(c[mi][nj], Ah[mi], Bh[nj]);
                    mma16816(c[mi][nj], Al[mi], Bh[nj]);
                    mma16816(c[mi][nj], Ah[mi], Bl[nj]);
                }
        }
        __syncthreads();
    }

    // ---------------- epilogue from register accumulators ----------------
#pragma unroll
    for (int mi = 0; mi < 4; mi++) {
#pragma unroll
        for (int half = 0; half < 2; half++) {
            int rl = warp_m0 + 16 * mi + 8 * half + g;
            int grow = m0 + rl;
            bool valid = true;
            int slot = 0;
            if (MODE >= 2) { valid = grow < cnt; slot = rows_s[rl]; }
#pragma unroll
            for (int nj = 0; nj < 4; nj++) {
                int col = n0 + warp_n0 + 8 * nj + 2 * tig;
                float v0 = c[mi][nj][2 * half];
                float v1 = c[mi][nj][2 * half + 1];
                if (MODE == 0) {
                    float* dst = g_qkv + (size_t)grow * QKV_N + col;
                    dst[0] = v0; dst[1] = v1;
                } else if (MODE == 1) {
                    size_t base = (size_t)grow * DMODEL + col;
                    g_hidden2[base]     = v0 + residual[base];
                    g_hidden2[base + 1] = v1 + residual[base + 1];
                } else if (MODE == 2) {
                    if (valid) {
                        const float* bia = bias + e * FDIM;
#pragma unroll
                        for (int d = 0; d < 2; d++) {
                            int f = col + d;
                            float v = (d ? v1 : v0) + bia[f];
                            float sact = v / (1.0f + expf(-v));
                            bf16 h = __float2bfloat16(sact);
                            size_t o = (size_t)slot * FDIM + f;
                            g_h_hi[o] = h;
                            g_h_lo[o] = __float2bfloat16(sact - __bfloat162float(h));
                        }
                    }
                } else {
                    if (valid) {
                        const float* bia = bias + e * DMODEL;
                        float gt = g_gate[slot];
                        g_moepart[(size_t)slot * DMODEL + col]     = gt * (v0 + bia[col]);
                        g_moepart[(size_t)slot * DMODEL + col + 1] = gt * (v1 + bia[col + 1]);
                    }
                }
            }
        }
    }
}

// ================= causal GQA flash attention (fp32 SIMT, reads g_qkv) =================
#define ATTN_SMEM ((2 * 64 * 129 + 64 * 65 + 3 * 64) * 4)
__global__ void attn_k() {
    extern __shared__ float sm[];
    float* Qs  = sm;
    float* KVs = Qs + 64 * 129;
    float* Ss  = KVs + 64 * 129;
    float* mrow = Ss + 64 * 65;
    float* lrow = mrow + 64;
    float* arow = lrow + 64;
    int h = blockIdx.y;
    int q0 = blockIdx.x * 64;
    int kvh = h >> 3;
    int tid = threadIdx.x, tx = tid & 15, ty = tid >> 4;
    const float scale = 0.08838834764831845f;

#pragma unroll
    for (int l = tid; l < 64 * HDIM; l += 256) {
        int i = l >> 7, d = l & 127;
        Qs[i * 129 + d] = g_qkv[(size_t)(q0 + i) * QKV_N + h * HDIM + d] * scale;
    }
    if (tid < 64) { mrow[tid] = -3e38f; lrow[tid] = 0.f; }
    float o[4][8];
#pragma unroll
    for (int i = 0; i < 4; i++)
#pragma unroll
        for (int jj = 0; jj < 8; jj++) o[i][jj] = 0.f;
    __syncthreads();

    int ntiles = q0 / 64;
    for (int t = 0; t <= ntiles; t++) {
        int k0 = t * 64;
#pragma unroll
        for (int l = tid; l < 64 * HDIM; l += 256) {
            int i = l >> 7, d = l & 127;
            KVs[i * 129 + d] = g_qkv[(size_t)(k0 + i) * QKV_N + 4096 + kvh * HDIM + d];
        }
        __syncthreads();
        float sacc[4][4] = {};
        for (int kk = 0; kk < HDIM; kk++) {
            float a[4], b[4];
#pragma unroll
            for (int i = 0; i < 4; i++) a[i] = Qs[(ty * 4 + i) * 129 + kk];
#pragma unroll
            for (int jj = 0; jj < 4; jj++) b[jj] = KVs[(tx * 4 + jj) * 129 + kk];
#pragma unroll
            for (int i = 0; i < 4; i++)
#pragma unroll
                for (int jj = 0; jj < 4; jj++) sacc[i][jj] += a[i] * b[jj];
        }
#pragma unroll
        for (int i = 0; i < 4; i++)
#pragma unroll
            for (int jj = 0; jj < 4; jj++) {
                int qg = q0 + ty * 4 + i, kg = k0 + tx * 4 + jj;
                Ss[(ty * 4 + i) * 65 + tx * 4 + jj] = (kg > qg) ? -1e9f : sacc[i][jj];
            }
        __syncthreads();
        if (tid < 64) {
            float mo = mrow[tid], mx = mo;
            float* sr = Ss + tid * 65;
            for (int k2 = 0; k2 < 64; k2++) mx = fmaxf(mx, sr[k2]);
            float al = __expf(mo - mx);
            float sum = 0.f;
            for (int k2 = 0; k2 < 64; k2++) { float p = __expf(sr[k2] - mx); sr[k2] = p; sum += p; }
            lrow[tid] = lrow[tid] * al + sum;
            mrow[tid] = mx;
            arow[tid] = al;
        }
        __syncthreads();
        float al4[4];
#pragma unroll
        for (int i = 0; i < 4; i++) al4[i] = arow[ty * 4 + i];
#pragma unroll
        for (int i = 0; i < 4; i++)
#pragma unroll
            for (int jj = 0; jj < 8; jj++) o[i][jj] *= al4[i];
#pragma unroll
        for (int l = tid; l < 64 * HDIM; l += 256) {
            int i = l >> 7, d = l & 127;
            KVs[i * 129 + d] = g_qkv[(size_t)(k0 + i) * QKV_N + 4608 + kvh * HDIM + d];
        }
        __syncthreads();
        for (int kk = 0; kk < 64; kk++) {
            float p[4];
#pragma unroll
            for (int i = 0; i < 4; i++) p[i] = Ss[(ty * 4 + i) * 65 + kk];
            float vv[8];
#pragma unroll
            for (int jj = 0; jj < 8; jj++) vv[jj] = KVs[kk * 129 + tx * 8 + jj];
#pragma unroll
            for (int i = 0; i < 4; i++)
#pragma unroll
                for (int jj = 0; jj < 8; jj++) o[i][jj] += p[i] * vv[jj];
        }
        __syncthreads();
    }
#pragma unroll
    for (int i = 0; i < 4; i++) {
        float linv = 1.0f / lrow[ty * 4 + i];
#pragma unroll
        for (int jj = 0; jj < 8; jj++)
            g_attn[(size_t)(q0 + ty * 4 + i) * ATTN_D + h * HDIM + tx * 8 + jj] = o[i][jj] * linv;
    }
}

// ================= split attn output to bf16 hi/lo =================
__global__ void split_attn_k() {
    size_t i = (size_t)blockIdx.x * 256 + threadIdx.x;
    float v = g_attn[i];
    bf16 h = __float2bfloat16(v);
    g_attn_hi[i] = h;
    g_attn_lo[i] = __float2bfloat16(v - __bfloat162float(h));
}

// ================= init / router / final =================
__global__ void init_k(float* __restrict__ out) {
    if (threadIdx.x < NEXP) g_cnt[threadIdx.x] = 0;
    if (threadIdx.x == 0) out[(size_t)S_LEN * DMODEL + S_LEN * NEXP] = 1.0f;
}

__global__ void router_k(const float* __restrict__ rW, float* __restrict__ out) {
    int t = blockIdx.x;
    const float* xr = g_xf + (size_t)t * DMODEL;
    int w = threadIdx.x >> 5, lane = threadIdx.x & 31;
    float sum = 0.f;
    for (int dd = lane; dd < DMODEL; dd += 32) sum += xr[dd] * rW[dd * NEXP + w];
    for (int o = 16; o; o >>= 1) sum += __shfl_xor_sync(0xffffffffu, sum, o);
    __shared__ float lg[NEXP];
    if (lane == 0) lg[w] = sum;
    __syncthreads();
    if (threadIdx.x == 0) {
        float* lo = out + (size_t)S_LEN * DMODEL + (size_t)t * NEXP;
        float mx = lg[0];
#pragma unroll
        for (int e = 1; e < NEXP; e++) mx = fmaxf(mx, lg[e]);
        float p[NEXP];
#pragma unroll
        for (int e = 0; e < NEXP; e++) { p[e] = expf(lg[e] - mx); lo[e] = lg[e]; }
        int i1 = 0;
#pragma unroll
        for (int e = 1; e < NEXP; e++) if (lg[e] > lg[i1]) i1 = e;
        int i2 = -1;
#pragma unroll
        for (int e = 0; e < NEXP; e++) {
            if (e == i1) continue;
            if (i2 < 0 || lg[e] > lg[i2]) i2 = e;
        }
        float denom = p[i1] + p[i2];
        g_gate[t * 2]     = p[i1] / denom;
        g_gate[t * 2 + 1] = p[i2] / denom;
        int pos = atomicAdd(&g_cnt[i1], 1);
        g_list[i1][pos] = t * 2;
        pos = atomicAdd(&g_cnt[i2], 1);
        g_list[i2][pos] = t * 2 + 1;
    }
}

__global__ void final_k(float* __restrict__ out) {
    int i = blockIdx.x * 256 + threadIdx.x;   // float4 index
    int t = i / (DMODEL / 4);
    int d = i - t * (DMODEL / 4);
    const float4* h2 = (const float4*)g_hidden2;
    const float4* mp = (const float4*)g_moepart;
    float4 a = h2[i];
    float4 b = mp[(size_t)(2 * t) * (DMODEL / 4) + d];
    float4 c = mp[(size_t)(2 * t + 1) * (DMODEL / 4) + d];
    float4 w;
    w.x = a.x + b.x + c.x; w.y = a.y + b.y + c.y;
    w.z = a.z + b.z + c.z; w.w = a.w + b.w + c.w;
    ((float4*)out)[i] = w;
}

// ================= launch =================
extern "C" void kernel_launch(void* const* d_in, const int* in_sizes, int n_in,
                              void* d_out, int out_size) {
    const float* hs  = (const float*)d_in[0];
    const float* ln1 = (const float*)d_in[1];
    const float* ln2 = (const float*)d_in[2];
    const float* Wq  = (const float*)d_in[3];
    const float* Wk  = (const float*)d_in[4];
    const float* Wv  = (const float*)d_in[5];
    const float* Wo  = (const float*)d_in[6];
    const float* qns = (const float*)d_in[7];
    const float* kns = (const float*)d_in[8];
    const float* rW  = (const float*)d_in[9];
    const float* upW = (const float*)d_in[10];
    const float* upb = (const float*)d_in[11];
    const float* dnW = (const float*)d_in[12];
    const float* dnb = (const float*)d_in[13];
    float* out = (float*)d_out;

    bf16 *wqkv_hi, *wqkv_lo, *wo_hi, *wo_lo, *wup_hi, *wup_lo, *wdn_hi, *wdn_lo;
    cudaGetSymbolAddress((void**)&wqkv_hi, g_wqkv_hi);
    cudaGetSymbolAddress((void**)&wqkv_lo, g_wqkv_lo);
    cudaGetSymbolAddress((void**)&wo_hi,   g_wo_hi);
    cudaGetSymbolAddress((void**)&wo_lo,   g_wo_lo);
    cudaGetSymbolAddress((void**)&wup_hi,  g_wup_hi);
    cudaGetSymbolAddress((void**)&wup_lo,  g_wup_lo);
    cudaGetSymbolAddress((void**)&wdn_hi,  g_wdn_hi);
    cudaGetSymbolAddress((void**)&wdn_lo,  g_wdn_lo);

    cudaFuncSetAttribute(attn_k, cudaFuncAttributeMaxDynamicSharedMemorySize, ATTN_SMEM);
    cudaFuncSetAttribute(mma_gemm_k<0>, cudaFuncAttributeMaxDynamicSharedMemorySize, DSMEM);
    cudaFuncSetAttribute(mma_gemm_k<1>, cudaFuncAttributeMaxDynamicSharedMemorySize, DSMEM);
    cudaFuncSetAttribute(mma_gemm_k<2>, cudaFuncAttributeMaxDynamicSharedMemorySize, DSMEM);
    cudaFuncSetAttribute(mma_gemm_k<3>, cudaFuncAttributeMaxDynamicSharedMemorySize, DSMEM);

    dim3 tb(32, 8);
    // weight transpose + split
    tsplit_k<<<dim3(128, 64), tb>>>(Wq, wqkv_hi,                       wqkv_lo,                       DMODEL, 4096, 0, 0);
    tsplit_k<<<dim3(16, 64),  tb>>>(Wk, wqkv_hi + (size_t)4096*DMODEL, wqkv_lo + (size_t)4096*DMODEL, DMODEL, 512, 0, 0);
    tsplit_k<<<dim3(16, 64),  tb>>>(Wv, wqkv_hi + (size_t)4608*DMODEL, wqkv_lo + (size_t)4608*DMODEL, DMODEL, 512, 0, 0);
    tsplit_k<<<dim3(64, 128), tb>>>(Wo, wo_hi, wo_lo, ATTN_D, DMODEL, 0, 0);
    tsplit_k<<<dim3(24, 64, NEXP), tb>>>(upW, wup_hi, wup_lo, DMODEL, FDIM,
                                         (size_t)DMODEL * FDIM, (size_t)DMODEL * FDIM);
    tsplit_k<<<dim3(64, 24, NEXP), tb>>>(dnW, wdn_hi, wdn_lo, FDIM, DMODEL,
                                         (size_t)FDIM * DMODEL, (size_t)FDIM * DMODEL);

    // 1. rmsnorm1 -> bf16 hi/lo
    rmsnorm1_split_k<<<S_LEN, 256>>>(hs, ln1);
    // 2. fused QKV projection (tensor cores via mma.sync)
    mma_gemm_k<0><<<dim3(QKV_N / 128, S_LEN / 128), 256, DSMEM>>>(nullptr, nullptr);
    // 3. per-head norm + rope (in place on g_qkv)
    qknorm_rope_k<<<dim3(S_LEN, NHQ), 128>>>(0, qns);
    qknorm_rope_k<<<dim3(S_LEN, NHKV), 128>>>(4096, kns);
    // 4. attention
    attn_k<<<dim3(S_LEN / 64, NHQ), 256, ATTN_SMEM>>>();
    // 5. split attn to bf16, output projection + residual
    split_attn_k<<<(S_LEN * ATTN_D) / 256, 256>>>();
    mma_gemm_k<1><<<dim3(DMODEL / 128, S_LEN / 128), 256, DSMEM>>>(hs, nullptr);
    // 6. rmsnorm2 -> f32 + bf16 hi/lo
    rmsnorm2_split_k<<<S_LEN, 256>>>(ln2);
    // 7. router
    init_k<<<1, 32>>>(out);
    router_k<<<S_LEN, 256>>>(rW, out);
    // 8. MoE (gathered rows; per-expert max 2048 rows -> 16 row blocks)
    mma_gemm_k<2><<<dim3(FDIM / 128, 16, NEXP), 256, DSMEM>>>(nullptr, upb);
    mma_gemm_k<3><<<dim3(DMODEL / 128, 16, NEXP), 256, DSMEM>>>(nullptr, dnb);
    // 9. final residual + MoE sum
    final_k<<<(S_LEN * DMODEL / 4) / 256, 256>>>(out);
}

// round 9
// speedup vs baseline: 5.1507x; 2.0261x over previous
#include <cuda_runtime.h>
#include <cuda_bf16.h>
#include <cuda_pipeline.h>
#include <math.h>
#include <stdint.h>

#define S_LEN 2048
#define DMODEL 2048
#define QKV_N 5120
#define NHQ 32
#define NHKV 4
#define HDIM 128
#define NEXP 8
#define FDIM 768
#define EPSV 1e-6f
#define ATTN_D (NHQ * HDIM)   // 4096

typedef __nv_bfloat16 bf16;

// ================= scratch (device globals; no allocations allowed) =================
__device__ __align__(256) bf16  g_x_hi[S_LEN * DMODEL];
__device__ __align__(256) bf16  g_x_lo[S_LEN * DMODEL];
__device__ __align__(256) float g_qkv[S_LEN * QKV_N];
__device__ __align__(256) bf16  g_qh[S_LEN * NHQ * HDIM];
__device__ __align__(256) bf16  g_ql[S_LEN * NHQ * HDIM];
__device__ __align__(256) bf16  g_kh[NHKV * S_LEN * HDIM];
__device__ __align__(256) bf16  g_kl[NHKV * S_LEN * HDIM];
__device__ __align__(256) bf16  g_vh[NHKV * S_LEN * HDIM];
__device__ __align__(256) bf16  g_vl[NHKV * S_LEN * HDIM];
__device__ __align__(256) bf16  g_attn_hi[S_LEN * ATTN_D];
__device__ __align__(256) bf16  g_attn_lo[S_LEN * ATTN_D];
__device__ __align__(256) float g_hidden2[S_LEN * DMODEL];
__device__ __align__(256) float g_xf[S_LEN * DMODEL];
__device__ __align__(256) bf16  g_xf_hi[S_LEN * DMODEL];
__device__ __align__(256) bf16  g_xf_lo[S_LEN * DMODEL];
__device__ __align__(256) bf16  g_h_hi[S_LEN * 2 * FDIM];
__device__ __align__(256) bf16  g_h_lo[S_LEN * 2 * FDIM];
__device__ __align__(256) float g_moepart[S_LEN * 2 * DMODEL];
__device__ float g_gate[S_LEN * 2];
__device__ int   g_cnt[NEXP];
__device__ int   g_list[NEXP][S_LEN];
// transposed + split weights: [N, K] row-major bf16
__device__ __align__(256) bf16 g_wqkv_hi[QKV_N * DMODEL];
__device__ __align__(256) bf16 g_wqkv_lo[QKV_N * DMODEL];
__device__ __align__(256) bf16 g_wo_hi[DMODEL * ATTN_D];
__device__ __align__(256) bf16 g_wo_lo[DMODEL * ATTN_D];
__device__ __align__(256) bf16 g_wup_hi[NEXP * FDIM * DMODEL];
__device__ __align__(256) bf16 g_wup_lo[NEXP * FDIM * DMODEL];
__device__ __align__(256) bf16 g_wdn_hi[NEXP * DMODEL * FDIM];
__device__ __align__(256) bf16 g_wdn_lo[NEXP * DMODEL * FDIM];

// ================= PTX helpers (sm_80-class only; no tcgen05) =================
__device__ __forceinline__ uint32_t smem_u32(const void* p) {
    uint32_t a;
    asm("{ .reg .u64 t; cvta.to.shared.u64 t, %1; cvt.u32.u64 %0, t; }" : "=r"(a) : "l"(p));
    return a;
}
__device__ __forceinline__ void ldsm4(uint32_t a, uint32_t r[4]) {
    asm volatile("ldmatrix.sync.aligned.m8n8.x4.shared.b16 {%0,%1,%2,%3}, [%4];"
                 : "=r"(r[0]), "=r"(r[1]), "=r"(r[2]), "=r"(r[3]) : "r"(a));
}
__device__ __forceinline__ void ldsm2(uint32_t a, uint32_t r[2]) {
    asm volatile("ldmatrix.sync.aligned.m8n8.x2.shared.b16 {%0,%1}, [%2];"
                 : "=r"(r[0]), "=r"(r[1]) : "r"(a));
}
__device__ __forceinline__ void ldsm2t(uint32_t a, uint32_t r[2]) {
    asm volatile("ldmatrix.sync.aligned.m8n8.x2.trans.shared.b16 {%0,%1}, [%2];"
                 : "=r"(r[0]), "=r"(r[1]) : "r"(a));
}
__device__ __forceinline__ void mma16816(float c[4], const uint32_t a[4], const uint32_t b[2]) {
    asm volatile(
        "mma.sync.aligned.m16n8k16.row.col.f32.bf16.bf16.f32 "
        "{%0,%1,%2,%3}, {%4,%5,%6,%7}, {%8,%9}, {%0,%1,%2,%3};"
        : "+f"(c[0]), "+f"(c[1]), "+f"(c[2]), "+f"(c[3])
        : "r"(a[0]), "r"(a[1]), "r"(a[2]), "r"(a[3]), "r"(b[0]), "r"(b[1]));
}
// swizzled smem address: 128B rows, 16B segment XOR (row%8)
__device__ __forceinline__ uint32_t lds_addr(uint32_t base, int row, int kbyte) {
    int seg = kbyte >> 4;
    return base + row * 128 + (((uint32_t)(seg ^ (row & 7))) << 4);
}
// 256B-row variant (attention tiles: 128 bf16 per row)
__device__ __forceinline__ int off256(int row, int seg) {
    return row * 256 + ((seg ^ (row & 7)) << 4);
}
__device__ __forceinline__ uint32_t pkbf(float x, float y) {
    __nv_bfloat162 t = __floats2bfloat162_rn(x, y);
    return *reinterpret_cast<uint32_t*>(&t);
}
__device__ __forceinline__ float bhi(float x, float& r) {
    float h = __bfloat162float(__float2bfloat16(x));
    r = x - h;
    return h;
}

// ================= weight transpose + bf16 hi/lo split =================
__global__ void tsplit_k(const float* __restrict__ in, bf16* __restrict__ hi,
                         bf16* __restrict__ lo, int R, int C,
                         size_t in_batch, size_t out_batch) {
    __shared__ float t[32][33];
    const float* inp = in + (size_t)blockIdx.z * in_batch;
    bf16* ho = hi + (size_t)blockIdx.z * out_batch;
    bf16* lo2 = lo + (size_t)blockIdx.z * out_batch;
    int r0 = blockIdx.y * 32, c0 = blockIdx.x * 32;
    int tx = threadIdx.x, ty = threadIdx.y;
    for (int i = ty; i < 32; i += 8)
        t[i][tx] = inp[(size_t)(r0 + i) * C + c0 + tx];
    __syncthreads();
    for (int i = ty; i < 32; i += 8) {
        float v = t[tx][i];
        bf16 h = __float2bfloat16(v);
        size_t o = (size_t)(c0 + i) * R + r0 + tx;
        ho[o] = h;
        lo2[o] = __float2bfloat16(v - __bfloat162float(h));
    }
}

// ================= rmsnorm variants =================
__global__ void rmsnorm1_split_k(const float* __restrict__ in, const float* __restrict__ sc) {
    int row = blockIdx.x;
    const float* r = in + (size_t)row * DMODEL;
    float ss = 0.f;
    for (int i = threadIdx.x; i < DMODEL; i += 256) { float v = r[i]; ss += v * v; }
    for (int o = 16; o; o >>= 1) ss += __shfl_xor_sync(0xffffffffu, ss, o);
    __shared__ float red[8];
    if ((threadIdx.x & 31) == 0) red[threadIdx.x >> 5] = ss;
    __syncthreads();
    float tot = 0.f;
#pragma unroll
    for (int i = 0; i < 8; i++) tot += red[i];
    float inv = rsqrtf(tot / (float)DMODEL + EPSV);
    for (int i = threadIdx.x; i < DMODEL; i += 256) {
        float w = r[i] * inv * sc[i];
        bf16 h = __float2bfloat16(w);
        size_t o = (size_t)row * DMODEL + i;
        g_x_hi[o] = h;
        g_x_lo[o] = __float2bfloat16(w - __bfloat162float(h));
    }
}

__global__ void rmsnorm2_split_k(const float* __restrict__ sc) {
    int row = blockIdx.x;
    const float* r = g_hidden2 + (size_t)row * DMODEL;
    float ss = 0.f;
    for (int i = threadIdx.x; i < DMODEL; i += 256) { float v = r[i]; ss += v * v; }
    for (int o = 16; o; o >>= 1) ss += __shfl_xor_sync(0xffffffffu, ss, o);
    __shared__ float red[8];
    if ((threadIdx.x & 31) == 0) red[threadIdx.x >> 5] = ss;
    __syncthreads();
    float tot = 0.f;
#pragma unroll
    for (int i = 0; i < 8; i++) tot += red[i];
    float inv = rsqrtf(tot / (float)DMODEL + EPSV);
    for (int i = threadIdx.x; i < DMODEL; i += 256) {
        float w = r[i] * inv * sc[i];
        size_t o = (size_t)row * DMODEL + i;
        g_xf[o] = w;
        bf16 h = __float2bfloat16(w);
        g_xf_hi[o] = h;
        g_xf_lo[o] = __float2bfloat16(w - __bfloat162float(h));
    }
}

// ================= per-head rmsnorm + rope; writes split bf16 Q or K =================
__global__ void qk_rope_split_k(int isK, const float* __restrict__ sc) {
    int s = blockIdx.x, h = blockIdx.y;
    int col0 = isK ? (4096 + h * HDIM) : (h * HDIM);
    const float* row = g_qkv + (size_t)s * QKV_N + col0;
    int d = threadIdx.x;   // 128 threads
    float v = row[d];
    float ss = v * v;
    for (int o = 16; o; o >>= 1) ss += __shfl_xor_sync(0xffffffffu, ss, o);
    __shared__ float red[4];
    if ((d & 31) == 0) red[d >> 5] = ss;
    __syncthreads();
    float tot = red[0] + red[1] + red[2] + red[3];
    float n = v * rsqrtf(tot / (float)HDIM + EPSV) * sc[d];
    __shared__ float ns[HDIM];
    ns[d] = n;
    __syncthreads();
    int j = d & 63;
    float invf = 1.0f / powf(1.0e6f, (float)j / 64.0f);
    float ang = (float)s * invf;
    float si, c;
    sincosf(ang, &si, &c);
    float rot = (d < 64) ? -ns[d + 64] : ns[d - 64];
    float val = n * c + rot * si;
    if (!isK) val *= 0.08838834764831845f;   // fold 1/sqrt(128) into Q
    float rem;
    float hv = bhi(val, rem);
    if (isK) {
        size_t o = ((size_t)h * S_LEN + s) * HDIM + d;
        g_kh[o] = __float2bfloat16(hv);
        g_kl[o] = __float2bfloat16(rem);
    } else {
        size_t o = ((size_t)s * NHQ + h) * HDIM + d;
        g_qh[o] = __float2bfloat16(hv);
        g_ql[o] = __float2bfloat16(rem);
    }
}

// ================= HMMA split-bf16 GEMM =================
#define STAGE_BYTES 65536
#define DSMEM (2 * STAGE_BYTES + 1024)

template<int MODE>
__global__ __launch_bounds__(256, 1) void mma_gemm_k(const float* __restrict__ residual,
                                                     const float* __restrict__ bias) {
    constexpr int K   = (MODE == 1) ? ATTN_D : (MODE == 3) ? FDIM : DMODEL;
    constexpr int NCH = K / 64;

    extern __shared__ char dyn[];
    __shared__ int rows_s[128];

    int tid = threadIdx.x, wid = tid >> 5, lane = tid & 31;
    int e = blockIdx.z;
    int m0 = blockIdx.y * 128;
    int n0 = blockIdx.x * 128;

    int cnt = 0;
    if (MODE >= 2) {
        cnt = g_cnt[e];
        if (m0 >= cnt) return;
        if (tid < 128)
            rows_s[tid] = (m0 + tid < cnt) ? g_list[e][m0 + tid] : g_list[e][0];
        __syncthreads();
    }

    const bf16 *Ahi, *Alo, *Bhi, *Blo;
    if (MODE == 0)      { Ahi = g_x_hi;    Alo = g_x_lo;    Bhi = g_wqkv_hi; Blo = g_wqkv_lo; }
    else if (MODE == 1) { Ahi = g_attn_hi; Alo = g_attn_lo; Bhi = g_wo_hi;   Blo = g_wo_lo; }
    else if (MODE == 2) { Ahi = g_xf_hi;   Alo = g_xf_lo;
                          Bhi = g_wup_hi + (size_t)e * FDIM * DMODEL;
                          Blo = g_wup_lo + (size_t)e * FDIM * DMODEL; }
    else                { Ahi = g_h_hi;    Alo = g_h_lo;
                          Bhi = g_wdn_hi + (size_t)e * DMODEL * FDIM;
                          Blo = g_wdn_lo + (size_t)e * DMODEL * FDIM; }

    uint32_t dyn_u = smem_u32(dyn);
    uint32_t tile0 = (dyn_u + 1023u) & ~1023u;
    char* tile0p = dyn + (tile0 - dyn_u);

    auto load_chunk = [&](int c, int s) {
        char* st = tile0p + s * STAGE_BYTES;
        for (int l = tid; l < 1024; l += 256) {
            int row = l >> 3, seg = l & 7;
            uint32_t off = (uint32_t)(row * 128 + seg * 16);
            uint32_t sw = off ^ ((off >> 3) & 0x70);
            size_t ar;
            if (MODE == 2)      ar = (size_t)(rows_s[row] >> 1) * K;
            else if (MODE == 3) ar = (size_t)rows_s[row] * K;
            else                ar = (size_t)(m0 + row) * K;
            size_t br = (size_t)(n0 + row) * K;
            __pipeline_memcpy_async(st + 0 * 16384 + sw, (const char*)(Ahi + ar + (size_t)c * 64) + seg * 16, 16);
            __pipeline_memcpy_async(st + 1 * 16384 + sw, (const char*)(Alo + ar + (size_t)c * 64) + seg * 16, 16);
            __pipeline_memcpy_async(st + 2 * 16384 + sw, (const char*)(Bhi + br + (size_t)c * 64) + seg * 16, 16);
            __pipeline_memcpy_async(st + 3 * 16384 + sw, (const char*)(Blo + br + (size_t)c * 64) + seg * 16, 16);
        }
    };

    int warp_m0 = (wid >> 2) * 64;
    int warp_n0 = (wid & 3) * 32;
    int g = lane >> 2, tig = lane & 3;

    float c[4][4][4];
#pragma unroll
    for (int mi = 0; mi < 4; mi++)
#pragma unroll
        for (int nj = 0; nj < 4; nj++)
#pragma unroll
            for (int q = 0; q < 4; q++) c[mi][nj][q] = 0.f;

    load_chunk(0, 0);
    __pipeline_commit();

    for (int i = 0; i < NCH; i++) {
        if (i + 1 < NCH) load_chunk(i + 1, (i + 1) & 1);
        __pipeline_commit();
        __pipeline_wait_prior(1);
        __syncthreads();

        uint32_t su  = tile0 + (uint32_t)(i & 1) * STAGE_BYTES;
        uint32_t aHiB = su, aLoB = su + 16384, bHiB = su + 32768, bLoB = su + 49152;

#pragma unroll
        for (int kk = 0; kk < 4; kk++) {
            uint32_t Ah[4][4], Al[4][4], Bh[4][2], Bl[4][2];
            int a_row = lane & 15;
            int a_kb  = 32 * kk + ((lane >> 4) << 4);
#pragma unroll
            for (int mi = 0; mi < 4; mi++) {
                int row = warp_m0 + 16 * mi + a_row;
                ldsm4(lds_addr(aHiB, row, a_kb), Ah[mi]);
                ldsm4(lds_addr(aLoB, row, a_kb), Al[mi]);
            }
            int b_row = lane & 7;
            int b_kb  = 32 * kk + (((lane >> 3) & 1) << 4);
#pragma unroll
            for (int nj = 0; nj < 4; nj++) {
                int row = warp_n0 + 8 * nj + b_row;
                ldsm2(lds_addr(bHiB, row, b_kb), Bh[nj]);
                ldsm2(lds_addr(bLoB, row, b_kb), Bl[nj]);
            }
#pragma unroll
            for (int mi = 0; mi < 4; mi++)
#pragma unroll
                for (int nj = 0; nj < 4; nj++) {
                    mma16816(c[mi][nj], Ah[mi], Bh[nj]);
                    mma16816(c[mi][nj], Al[mi], Bh[nj]);
                    mma16816(c[mi][nj], Ah[mi], Bl[nj]);
                }
        }
        __syncthreads();
    }

    // ---------------- epilogue ----------------
#pragma unroll
    for (int mi = 0; mi < 4; mi++) {
#pragma unroll
        for (int half = 0; half < 2; half++) {
            int rl = warp_m0 + 16 * mi + 8 * half + g;
            int grow = m0 + rl;
            bool valid = true;
            int slot = 0;
            if (MODE >= 2) { valid = grow < cnt; slot = rows_s[rl]; }
#pragma unroll
            for (int nj = 0; nj < 4; nj++) {
                int col = n0 + warp_n0 + 8 * nj + 2 * tig;
                float v0 = c[mi][nj][2 * half];
                float v1 = c[mi][nj][2 * half + 1];
                if (MODE == 0) {
                    if (col < 4608) {
                        float* dst = g_qkv + (size_t)grow * QKV_N + col;
                        dst[0] = v0; dst[1] = v1;
                    } else {
                        // V columns: split straight to bf16 hi/lo, per-kv-head layout
                        int cc = col - 4608;
                        int kvh = cc >> 7, d = cc & 127;
                        size_t o = ((size_t)kvh * S_LEN + grow) * HDIM + d;
                        float r0, r1;
                        float h0 = bhi(v0, r0), h1 = bhi(v1, r1);
                        *(uint32_t*)(g_vh + o) = pkbf(h0, h1);
                        *(uint32_t*)(g_vl + o) = pkbf(r0, r1);
                    }
                } else if (MODE == 1) {
                    size_t base = (size_t)grow * DMODEL + col;
                    g_hidden2[base]     = v0 + residual[base];
                    g_hidden2[base + 1] = v1 + residual[base + 1];
                } else if (MODE == 2) {
                    if (valid) {
                        const float* bia = bias + e * FDIM;
#pragma unroll
                        for (int d = 0; d < 2; d++) {
                            int f = col + d;
                            float v = (d ? v1 : v0) + bia[f];
                            float sact = v / (1.0f + expf(-v));
                            bf16 h = __float2bfloat16(sact);
                            size_t o = (size_t)slot * FDIM + f;
                            g_h_hi[o] = h;
                            g_h_lo[o] = __float2bfloat16(sact - __bfloat162float(h));
                        }
                    }
                } else {
                    if (valid) {
                        const float* bia = bias + e * DMODEL;
                        float gt = g_gate[slot];
                        g_moepart[(size_t)slot * DMODEL + col]     = gt * (v0 + bia[col]);
                        g_moepart[(size_t)slot * DMODEL + col + 1] = gt * (v1 + bia[col + 1]);
                    }
                }
            }
        }
    }
}

// ================= HMMA flash attention =================
// CTA = (q-tile of 128, head). 8 warps x 16 q-rows. KV tiles of 64, double buffered.
// smem: Qh 32KB @0, Ql 32KB @32768; stages @65536 + s*65536: Kh,Kl,Vh,Vl 16KB each.
#define ATT_SMEM (65536 + 2 * 65536)
__global__ __launch_bounds__(256, 1) void attn_mma_k() {
    extern __shared__ char sm[];
    uint32_t sb = smem_u32(sm);
    int qi = blockIdx.x, h = blockIdx.y;
    int q0 = qi * 128, kvh = h >> 3;
    int nkv = 2 * (qi + 1);
    int tid = threadIdx.x, wid = tid >> 5, lane = tid & 31;
    int g = lane >> 2, tig = lane & 3;
    int wq0 = wid * 16;

    // fill Q (hi at 0, lo at +32768)
    for (int l = tid; l < 2048; l += 256) {
        int row = l >> 4, seg = l & 15;
        int off = off256(row, seg);
        size_t src = ((size_t)(q0 + row) * NHQ + h) * HDIM + seg * 8;
        __pipeline_memcpy_async(sm + off,         g_qh + src, 16);
        __pipeline_memcpy_async(sm + 32768 + off, g_ql + src, 16);
    }

    auto fill_kv = [&](int t, int st) {
        char* base = sm + 65536 + st * 65536;
        int kv0 = t * 64;
        for (int l = tid; l < 1024; l += 256) {
            int row = l >> 4, seg = l & 15;
            int off = off256(row, seg);
            size_t src = ((size_t)kvh * S_LEN + kv0 + row) * HDIM + seg * 8;
            __pipeline_memcpy_async(base + off,         g_kh + src, 16);
            __pipeline_memcpy_async(base + 16384 + off, g_kl + src, 16);
            __pipeline_memcpy_async(base + 32768 + off, g_vh + src, 16);
            __pipeline_memcpy_async(base + 49152 + off, g_vl + src, 16);
        }
    };

    float o[16][4];
#pragma unroll
    for (int dj = 0; dj < 16; dj++)
#pragma unroll
        for (int q = 0; q < 4; q++) o[dj][q] = 0.f;
    float m0 = -3e38f, m1 = -3e38f, l0 = 0.f, l1 = 0.f;

    fill_kv(0, 0);
    __pipeline_commit();

    for (int t = 0; t < nkv; t++) {
        if (t + 1 < nkv) fill_kv(t + 1, (t + 1) & 1);
        __pipeline_commit();
        __pipeline_wait_prior(1);
        __syncthreads();

        uint32_t st  = sb + 65536 + (uint32_t)(t & 1) * 65536;
        int k0 = t * 64;

        // ---- scores S[16x64] per warp, 3-term split-bf16 ----
        float s[8][4];
#pragma unroll
        for (int nj = 0; nj < 8; nj++)
#pragma unroll
            for (int q = 0; q < 4; q++) s[nj][q] = 0.f;

#pragma unroll
        for (int kk = 0; kk < 8; kk++) {
            uint32_t aqh[4], aql[4];
            int a_row = wq0 + (lane & 15);
            int a_sb  = kk * 2 + ((lane >> 4) & 1);  // seg index (16B units): kk*32B = 2 segs
            uint32_t aaddr = sb + off256(a_row, a_sb);
            ldsm4(aaddr, aqh);
            ldsm4(aaddr + 32768, aql);
#pragma unroll
            for (int nj = 0; nj < 8; nj++) {
                uint32_t bkh[2], bkl[2];
                int b_row = nj * 8 + (lane & 7);
                int b_sb  = kk * 2 + ((lane >> 3) & 1);
                uint32_t baddr = st + off256(b_row, b_sb);
                ldsm2(baddr, bkh);
                ldsm2(baddr + 16384, bkl);
                mma16816(s[nj], aqh, bkh);
                mma16816(s[nj], aql, bkh);
                mma16816(s[nj], aqh, bkl);
            }
        }

        // ---- causal mask ----
        if (k0 + 63 > q0 + wq0) {
            int r0 = q0 + wq0 + g, r1 = r0 + 8;
#pragma unroll
            for (int nj = 0; nj < 8; nj++) {
                int col = k0 + nj * 8 + 2 * tig;
                if (col > r0)     s[nj][0] = -1e9f;
                if (col + 1 > r0) s[nj][1] = -1e9f;
                if (col > r1)     s[nj][2] = -1e9f;
                if (col + 1 > r1) s[nj][3] = -1e9f;
            }
        }

        // ---- online softmax ----
        float mx0 = m0, mx1 = m1;
#pragma unroll
        for (int nj = 0; nj < 8; nj++) {
            mx0 = fmaxf(mx0, fmaxf(s[nj][0], s[nj][1]));
            mx1 = fmaxf(mx1, fmaxf(s[nj][2], s[nj][3]));
        }
        mx0 = fmaxf(mx0, __shfl_xor_sync(0xffffffffu, mx0, 1));
        mx0 = fmaxf(mx0, __shfl_xor_sync(0xffffffffu, mx0, 2));
        mx1 = fmaxf(mx1, __shfl_xor_sync(0xffffffffu, mx1, 1));
        mx1 = fmaxf(mx1, __shfl_xor_sync(0xffffffffu, mx1, 2));
        float a0 = __expf(m0 - mx0), a1 = __expf(m1 - mx1);
        m0 = mx0; m1 = mx1;
        l0 *= a0; l1 *= a1;
#pragma unroll
        for (int dj = 0; dj < 16; dj++) {
            o[dj][0] *= a0; o[dj][1] *= a0;
            o[dj][2] *= a1; o[dj][3] *= a1;
        }

        uint32_t phi[8][2], plo[8][2];
#pragma unroll
        for (int nj = 0; nj < 8; nj++) {
            float p00 = __expf(s[nj][0] - mx0), p01 = __expf(s[nj][1] - mx0);
            float p10 = __expf(s[nj][2] - mx1), p11 = __expf(s[nj][3] - mx1);
            l0 += p00 + p01; l1 += p10 + p11;
            float r00, r01, r10, r11;
            float h00 = bhi(p00, r00), h01 = bhi(p01, r01);
            float h10 = bhi(p10, r10), h11 = bhi(p11, r11);
            phi[nj][0] = pkbf(h00, h01); phi[nj][1] = pkbf(h10, h11);
            plo[nj][0] = pkbf(r00, r01); plo[nj][1] = pkbf(r10, r11);
        }

        // ---- O += P @ V, 3-term ----
        uint32_t vh_b = st + 32768;
#pragma unroll
        for (int kc = 0; kc < 4; kc++) {
            uint32_t aph[4] = { phi[2 * kc][0], phi[2 * kc][1], phi[2 * kc + 1][0], phi[2 * kc + 1][1] };
            uint32_t apl[4] = { plo[2 * kc][0], plo[2 * kc][1], plo[2 * kc + 1][0], plo[2 * kc + 1][1] };
#pragma unroll
            for (int dj = 0; dj < 16; dj++) {
                uint32_t bvh[2], bvl[2];
                int v_row = kc * 16 + (lane & 15);
                uint32_t vaddr = vh_b + off256(v_row, dj);
                ldsm2t(vaddr, bvh);
                ldsm2t(vaddr + 16384, bvl);
                mma16816(o[dj], aph, bvh);
                mma16816(o[dj], apl, bvh);
                mma16816(o[dj], aph, bvl);
            }
        }
        __syncthreads();   // compute done before next fill overwrites this stage
    }

    // ---- epilogue: normalize, split, store ----
    l0 += __shfl_xor_sync(0xffffffffu, l0, 1);
    l0 += __shfl_xor_sync(0xffffffffu, l0, 2);
    l1 += __shfl_xor_sync(0xffffffffu, l1, 1);
    l1 += __shfl_xor_sync(0xffffffffu, l1, 2);
    float i0 = 1.0f / l0, i1 = 1.0f / l1;
    int r0 = q0 + wq0 + g, r1 = r0 + 8;
#pragma unroll
    for (int dj = 0; dj < 16; dj++) {
        int cc = dj * 8 + 2 * tig;
        size_t o0 = (size_t)r0 * ATTN_D + h * HDIM + cc;
        size_t o1 = (size_t)r1 * ATTN_D + h * HDIM + cc;
        float ra, rb;
        float v0 = o[dj][0] * i0, v1 = o[dj][1] * i0;
        float h0 = bhi(v0, ra), h1 = bhi(v1, rb);
        *(uint32_t*)(g_attn_hi + o0) = pkbf(h0, h1);
        *(uint32_t*)(g_attn_lo + o0) = pkbf(ra, rb);
        float w0 = o[dj][2] * i1, w1 = o[dj][3] * i1;
        h0 = bhi(w0, ra); h1 = bhi(w1, rb);
        *(uint32_t*)(g_attn_hi + o1) = pkbf(h0, h1);
        *(uint32_t*)(g_attn_lo + o1) = pkbf(ra, rb);
    }
}

// ================= init / router / final =================
__global__ void init_k(float* __restrict__ out) {
    if (threadIdx.x < NEXP) g_cnt[threadIdx.x] = 0;
    if (threadIdx.x == 0) out[(size_t)S_LEN * DMODEL + S_LEN * NEXP] = 1.0f;
}

__global__ void router_k(const float* __restrict__ rW, float* __restrict__ out) {
    int t = blockIdx.x;
    const float* xr = g_xf + (size_t)t * DMODEL;
    int w = threadIdx.x >> 5, lane = threadIdx.x & 31;
    float sum = 0.f;
    for (int dd = lane; dd < DMODEL; dd += 32) sum += xr[dd] * rW[dd * NEXP + w];
    for (int o = 16; o; o >>= 1) sum += __shfl_xor_sync(0xffffffffu, sum, o);
    __shared__ float lg[NEXP];
    if (lane == 0) lg[w] = sum;
    __syncthreads();
    if (threadIdx.x == 0) {
        float* lo = out + (size_t)S_LEN * DMODEL + (size_t)t * NEXP;
        float mx = lg[0];
#pragma unroll
        for (int e = 1; e < NEXP; e++) mx = fmaxf(mx, lg[e]);
        float p[NEXP];
#pragma unroll
        for (int e = 0; e < NEXP; e++) { p[e] = expf(lg[e] - mx); lo[e] = lg[e]; }
        int i1 = 0;
#pragma unroll
        for (int e = 1; e < NEXP; e++) if (lg[e] > lg[i1]) i1 = e;
        int i2 = -1;
#pragma unroll
        for (int e = 0; e < NEXP; e++) {
            if (e == i1) continue;
            if (i2 < 0 || lg[e] > lg[i2]) i2 = e;
        }
        float denom = p[i1] + p[i2];
        g_gate[t * 2]     = p[i1] / denom;
        g_gate[t * 2 + 1] = p[i2] / denom;
        int pos = atomicAdd(&g_cnt[i1], 1);
        g_list[i1][pos] = t * 2;
        pos = atomicAdd(&g_cnt[i2], 1);
        g_list[i2][pos] = t * 2 + 1;
    }
}

__global__ void final_k(float* __restrict__ out) {
    int i = blockIdx.x * 256 + threadIdx.x;   // float4 index
    int t = i / (DMODEL / 4);
    int d = i - t * (DMODEL / 4);
    const float4* h2 = (const float4*)g_hidden2;
    const float4* mp = (const float4*)g_moepart;
    float4 a = h2[i];
    float4 b = mp[(size_t)(2 * t) * (DMODEL / 4) + d];
    float4 c = mp[(size_t)(2 * t + 1) * (DMODEL / 4) + d];
    float4 w;
    w.x = a.x + b.x + c.x; w.y = a.y + b.y + c.y;
    w.z = a.z + b.z + c.z; w.w = a.w + b.w + c.w;
    ((float4*)out)[i] = w;
}

// ================= launch =================
extern "C" void kernel_launch(void* const* d_in, const int* in_sizes, int n_in,
                              void* d_out, int out_size) {
    const float* hs  = (const float*)d_in[0];
    const float* ln1 = (const float*)d_in[1];
    const float* ln2 = (const float*)d_in[2];
    const float* Wq  = (const float*)d_in[3];
    const float* Wk  = (const float*)d_in[4];
    const float* Wv  = (const float*)d_in[5];
    const float* Wo  = (const float*)d_in[6];
    const float* qns = (const float*)d_in[7];
    const float* kns = (const float*)d_in[8];
    const float* rW  = (const float*)d_in[9];
    const float* upW = (const float*)d_in[10];
    const float* upb = (const float*)d_in[11];
    const float* dnW = (const float*)d_in[12];
    const float* dnb = (const float*)d_in[13];
    float* out = (float*)d_out;

    bf16 *wqkv_hi, *wqkv_lo, *wo_hi, *wo_lo, *wup_hi, *wup_lo, *wdn_hi, *wdn_lo;
    cudaGetSymbolAddress((void**)&wqkv_hi, g_wqkv_hi);
    cudaGetSymbolAddress((void**)&wqkv_lo, g_wqkv_lo);
    cudaGetSymbolAddress((void**)&wo_hi,   g_wo_hi);
    cudaGetSymbolAddress((void**)&wo_lo,   g_wo_lo);
    cudaGetSymbolAddress((void**)&wup_hi,  g_wup_hi);
    cudaGetSymbolAddress((void**)&wup_lo,  g_wup_lo);
    cudaGetSymbolAddress((void**)&wdn_hi,  g_wdn_hi);
    cudaGetSymbolAddress((void**)&wdn_lo,  g_wdn_lo);

    cudaFuncSetAttribute(attn_mma_k, cudaFuncAttributeMaxDynamicSharedMemorySize, ATT_SMEM);
    cudaFuncSetAttribute(mma_gemm_k<0>, cudaFuncAttributeMaxDynamicSharedMemorySize, DSMEM);
    cudaFuncSetAttribute(mma_gemm_k<1>, cudaFuncAttributeMaxDynamicSharedMemorySize, DSMEM);
    cudaFuncSetAttribute(mma_gemm_k<2>, cudaFuncAttributeMaxDynamicSharedMemorySize, DSMEM);
    cudaFuncSetAttribute(mma_gemm_k<3>, cudaFuncAttributeMaxDynamicSharedMemorySize, DSMEM);

    dim3 tb(32, 8);
    // weight transpose + split
    tsplit_k<<<dim3(128, 64), tb>>>(Wq, wqkv_hi,                       wqkv_lo,                       DMODEL, 4096, 0, 0);
    tsplit_k<<<dim3(16, 64),  tb>>>(Wk, wqkv_hi + (size_t)4096*DMODEL, wqkv_lo + (size_t)4096*DMODEL, DMODEL, 512, 0, 0);
    tsplit_k<<<dim3(16, 64),  tb>>>(Wv, wqkv_hi + (size_t)4608*DMODEL, wqkv_lo + (size_t)4608*DMODEL, DMODEL, 512, 0, 0);
    tsplit_k<<<dim3(64, 128), tb>>>(Wo, wo_hi, wo_lo, ATTN_D, DMODEL, 0, 0);
    tsplit_k<<<dim3(24, 64, NEXP), tb>>>(upW, wup_hi, wup_lo, DMODEL, FDIM,
                                         (size_t)DMODEL * FDIM, (size_t)DMODEL * FDIM);
    tsplit_k<<<dim3(64, 24, NEXP), tb>>>(dnW, wdn_hi, wdn_lo, FDIM, DMODEL,
                                         (size_t)FDIM * DMODEL, (size_t)FDIM * DMODEL);

    // 1. rmsnorm1 -> bf16 hi/lo
    rmsnorm1_split_k<<<S_LEN, 256>>>(hs, ln1);
    // 2. fused QKV projection (V split to bf16 in epilogue)
    mma_gemm_k<0><<<dim3(QKV_N / 128, S_LEN / 128), 256, DSMEM>>>(nullptr, nullptr);
    // 3. per-head norm + rope -> split bf16 Q / K
    qk_rope_split_k<<<dim3(S_LEN, NHQ), 128>>>(0, qns);
    qk_rope_split_k<<<dim3(S_LEN, NHKV), 128>>>(1, kns);
    // 4. HMMA flash attention -> g_attn hi/lo
    attn_mma_k<<<dim3(S_LEN / 128, NHQ), 256, ATT_SMEM>>>();
    // 5. output projection + residual
    mma_gemm_k<1><<<dim3(DMODEL / 128, S_LEN / 128), 256, DSMEM>>>(hs, nullptr);
    // 6. rmsnorm2 -> f32 + bf16 hi/lo
    rmsnorm2_split_k<<<S_LEN, 256>>>(ln2);
    // 7. router
    init_k<<<1, 32>>>(out);
    router_k<<<S_LEN, 256>>>(rW, out);
    // 8. MoE (gathered rows)
    mma_gemm_k<2><<<dim3(FDIM / 128, 16, NEXP), 256, DSMEM>>>(nullptr, upb);
    mma_gemm_k<3><<<dim3(DMODEL / 128, 16, NEXP), 256, DSMEM>>>(nullptr, dnb);
    // 9. final residual + MoE sum
    final_k<<<(S_LEN * DMODEL / 4) / 256, 256>>>(out);
}

// round 10
// speedup vs baseline: 5.3535x; 1.0394x over previous
#include <cuda_runtime.h>
#include <cuda_bf16.h>
#include <cuda_pipeline.h>
#include <math.h>
#include <stdint.h>

#define S_LEN 2048
#define DMODEL 2048
#define QKV_N 5120
#define NHQ 32
#define NHKV 4
#define HDIM 128
#define NEXP 8
#define FDIM 768
#define EPSV 1e-6f
#define ATTN_D (NHQ * HDIM)   // 4096

typedef __nv_bfloat16 bf16;

// ================= scratch (device globals; no allocations allowed) =================
__device__ __align__(256) bf16  g_x_hi[S_LEN * DMODEL];
__device__ __align__(256) bf16  g_x_lo[S_LEN * DMODEL];
__device__ __align__(256) float g_qkv[S_LEN * QKV_N];
__device__ __align__(256) bf16  g_qh[S_LEN * NHQ * HDIM];
__device__ __align__(256) bf16  g_ql[S_LEN * NHQ * HDIM];
__device__ __align__(256) bf16  g_kh[NHKV * S_LEN * HDIM];
__device__ __align__(256) bf16  g_kl[NHKV * S_LEN * HDIM];
__device__ __align__(256) bf16  g_vh[NHKV * S_LEN * HDIM];
__device__ __align__(256) bf16  g_vl[NHKV * S_LEN * HDIM];
__device__ __align__(256) bf16  g_attn_hi[S_LEN * ATTN_D];
__device__ __align__(256) bf16  g_attn_lo[S_LEN * ATTN_D];
__device__ __align__(256) float g_hidden2[S_LEN * DMODEL];
__device__ __align__(256) float g_xf[S_LEN * DMODEL];
__device__ __align__(256) bf16  g_xf_hi[S_LEN * DMODEL];
__device__ __align__(256) bf16  g_xf_lo[S_LEN * DMODEL];
__device__ __align__(256) bf16  g_h_hi[S_LEN * 2 * FDIM];
__device__ __align__(256) bf16  g_h_lo[S_LEN * 2 * FDIM];
__device__ __align__(256) float g_moepart[S_LEN * 2 * DMODEL];
__device__ float g_gate[S_LEN * 2];
__device__ int   g_cnt[NEXP];
__device__ int   g_list[NEXP][S_LEN];
// split weights in NATIVE [K, N] layout (no transpose)
__device__ __align__(256) bf16 g_wq_hi[DMODEL * ATTN_D];
__device__ __align__(256) bf16 g_wq_lo[DMODEL * ATTN_D];
__device__ __align__(256) bf16 g_wk_hi[DMODEL * 512];
__device__ __align__(256) bf16 g_wk_lo[DMODEL * 512];
__device__ __align__(256) bf16 g_wv_hi[DMODEL * 512];
__device__ __align__(256) bf16 g_wv_lo[DMODEL * 512];
__device__ __align__(256) bf16 g_wo_hi[ATTN_D * DMODEL];
__device__ __align__(256) bf16 g_wo_lo[ATTN_D * DMODEL];
__device__ __align__(256) bf16 g_wup_hi[NEXP * DMODEL * FDIM];
__device__ __align__(256) bf16 g_wup_lo[NEXP * DMODEL * FDIM];
__device__ __align__(256) bf16 g_wdn_hi[NEXP * FDIM * DMODEL];
__device__ __align__(256) bf16 g_wdn_lo[NEXP * FDIM * DMODEL];

// ================= PTX helpers (sm_80-class only; no tcgen05) =================
__device__ __forceinline__ uint32_t smem_u32(const void* p) {
    uint32_t a;
    asm("{ .reg .u64 t; cvta.to.shared.u64 t, %1; cvt.u32.u64 %0, t; }" : "=r"(a) : "l"(p));
    return a;
}
__device__ __forceinline__ void ldsm4(uint32_t a, uint32_t r[4]) {
    asm volatile("ldmatrix.sync.aligned.m8n8.x4.shared.b16 {%0,%1,%2,%3}, [%4];"
                 : "=r"(r[0]), "=r"(r[1]), "=r"(r[2]), "=r"(r[3]) : "r"(a));
}
__device__ __forceinline__ void ldsm2(uint32_t a, uint32_t r[2]) {
    asm volatile("ldmatrix.sync.aligned.m8n8.x2.shared.b16 {%0,%1}, [%2];"
                 : "=r"(r[0]), "=r"(r[1]) : "r"(a));
}
__device__ __forceinline__ void ldsm2t(uint32_t a, uint32_t r[2]) {
    asm volatile("ldmatrix.sync.aligned.m8n8.x2.trans.shared.b16 {%0,%1}, [%2];"
                 : "=r"(r[0]), "=r"(r[1]) : "r"(a));
}
__device__ __forceinline__ void mma16816(float c[4], const uint32_t a[4], const uint32_t b[2]) {
    asm volatile(
        "mma.sync.aligned.m16n8k16.row.col.f32.bf16.bf16.f32 "
        "{%0,%1,%2,%3}, {%4,%5,%6,%7}, {%8,%9}, {%0,%1,%2,%3};"
        : "+f"(c[0]), "+f"(c[1]), "+f"(c[2]), "+f"(c[3])
        : "r"(a[0]), "r"(a[1]), "r"(a[2]), "r"(a[3]), "r"(b[0]), "r"(b[1]));
}
// swizzled smem address: 128B rows, 16B segment XOR (row%8)
__device__ __forceinline__ uint32_t lds_addr(uint32_t base, int row, int kbyte) {
    int seg = kbyte >> 4;
    return base + row * 128 + (((uint32_t)(seg ^ (row & 7))) << 4);
}
// 256B-row variant (tiles with 128 bf16 per row)
__device__ __forceinline__ int off256(int row, int seg) {
    return row * 256 + ((seg ^ (row & 7)) << 4);
}
__device__ __forceinline__ uint32_t pkbf(float x, float y) {
    __nv_bfloat162 t = __floats2bfloat162_rn(x, y);
    return *reinterpret_cast<uint32_t*>(&t);
}
__device__ __forceinline__ float bhi(float x, float& r) {
    float h = __bfloat162float(__float2bfloat16(x));
    r = x - h;
    return h;
}

// ================= fp32 -> bf16 hi/lo split, same layout (fully coalesced) =================
__global__ void split_k(const float4* __restrict__ in, uint2* __restrict__ hi,
                        uint2* __restrict__ lo) {
    size_t i = (size_t)blockIdx.x * 256 + threadIdx.x;
    float4 v = in[i];
    float r0, r1, r2, r3;
    float h0 = bhi(v.x, r0), h1 = bhi(v.y, r1), h2 = bhi(v.z, r2), h3 = bhi(v.w, r3);
    hi[i] = make_uint2(pkbf(h0, h1), pkbf(h2, h3));
    lo[i] = make_uint2(pkbf(r0, r1), pkbf(r2, r3));
}

// ================= rmsnorm variants =================
__global__ void rmsnorm1_split_k(const float* __restrict__ in, const float* __restrict__ sc) {
    int row = blockIdx.x;
    const float* r = in + (size_t)row * DMODEL;
    float ss = 0.f;
    for (int i = threadIdx.x; i < DMODEL; i += 256) { float v = r[i]; ss += v * v; }
    for (int o = 16; o; o >>= 1) ss += __shfl_xor_sync(0xffffffffu, ss, o);
    __shared__ float red[8];
    if ((threadIdx.x & 31) == 0) red[threadIdx.x >> 5] = ss;
    __syncthreads();
    float tot = 0.f;
#pragma unroll
    for (int i = 0; i < 8; i++) tot += red[i];
    float inv = rsqrtf(tot / (float)DMODEL + EPSV);
    for (int i = threadIdx.x; i < DMODEL; i += 256) {
        float w = r[i] * inv * sc[i];
        bf16 h = __float2bfloat16(w);
        size_t o = (size_t)row * DMODEL + i;
        g_x_hi[o] = h;
        g_x_lo[o] = __float2bfloat16(w - __bfloat162float(h));
    }
}

__global__ void rmsnorm2_split_k(const float* __restrict__ sc) {
    int row = blockIdx.x;
    const float* r = g_hidden2 + (size_t)row * DMODEL;
    float ss = 0.f;
    for (int i = threadIdx.x; i < DMODEL; i += 256) { float v = r[i]; ss += v * v; }
    for (int o = 16; o; o >>= 1) ss += __shfl_xor_sync(0xffffffffu, ss, o);
    __shared__ float red[8];
    if ((threadIdx.x & 31) == 0) red[threadIdx.x >> 5] = ss;
    __syncthreads();
    float tot = 0.f;
#pragma unroll
    for (int i = 0; i < 8; i++) tot += red[i];
    float inv = rsqrtf(tot / (float)DMODEL + EPSV);
    for (int i = threadIdx.x; i < DMODEL; i += 256) {
        float w = r[i] * inv * sc[i];
        size_t o = (size_t)row * DMODEL + i;
        g_xf[o] = w;
        bf16 h = __float2bfloat16(w);
        g_xf_hi[o] = h;
        g_xf_lo[o] = __float2bfloat16(w - __bfloat162float(h));
    }
}

// ================= per-head rmsnorm + rope; writes split bf16 Q or K =================
__global__ void qk_rope_split_k(int isK, const float* __restrict__ sc) {
    int s = blockIdx.x, h = blockIdx.y;
    int col0 = isK ? (4096 + h * HDIM) : (h * HDIM);
    const float* row = g_qkv + (size_t)s * QKV_N + col0;
    int d = threadIdx.x;   // 128 threads
    float v = row[d];
    float ss = v * v;
    for (int o = 16; o; o >>= 1) ss += __shfl_xor_sync(0xffffffffu, ss, o);
    __shared__ float red[4];
    if ((d & 31) == 0) red[d >> 5] = ss;
    __syncthreads();
    float tot = red[0] + red[1] + red[2] + red[3];
    float n = v * rsqrtf(tot / (float)HDIM + EPSV) * sc[d];
    __shared__ float ns[HDIM];
    ns[d] = n;
    __syncthreads();
    int j = d & 63;
    float invf = 1.0f / powf(1.0e6f, (float)j / 64.0f);
    float ang = (float)s * invf;
    float si, c;
    sincosf(ang, &si, &c);
    float rot = (d < 64) ? -ns[d + 64] : ns[d - 64];
    float val = n * c + rot * si;
    if (!isK) val *= 0.08838834764831845f;   // fold 1/sqrt(128) into Q
    float rem;
    float hv = bhi(val, rem);
    if (isK) {
        size_t o = ((size_t)h * S_LEN + s) * HDIM + d;
        g_kh[o] = __float2bfloat16(hv);
        g_kl[o] = __float2bfloat16(rem);
    } else {
        size_t o = ((size_t)s * NHQ + h) * HDIM + d;
        g_qh[o] = __float2bfloat16(hv);
        g_ql[o] = __float2bfloat16(rem);
    }
}

// ================= HMMA split-bf16 GEMM (B in native [K,N], ldmatrix.trans) =========
#define STAGE_BYTES 65536
#define DSMEM (3 * STAGE_BYTES + 1024)

template<int MODE>
__global__ __launch_bounds__(256, 1) void mma_gemm_k(const float* __restrict__ residual,
                                                     const float* __restrict__ bias) {
    constexpr int K   = (MODE == 1) ? ATTN_D : (MODE == 3) ? FDIM : DMODEL;
    constexpr int NCH = K / 64;

    extern __shared__ char dyn[];
    __shared__ int rows_s[128];

    int tid = threadIdx.x, wid = tid >> 5, lane = tid & 31;
    int e = blockIdx.z;
    int m0 = blockIdx.y * 128;
    int n0 = blockIdx.x * 128;

    int cnt = 0;
    if (MODE >= 2) {
        cnt = g_cnt[e];
        if (m0 >= cnt) return;
        if (tid < 128)
            rows_s[tid] = (m0 + tid < cnt) ? g_list[e][m0 + tid] : g_list[e][0];
        __syncthreads();
    }

    const bf16 *Ahi, *Alo, *Bhi, *Blo;
    int ldB, bn;
    if (MODE == 0) {
        Ahi = g_x_hi; Alo = g_x_lo;
        if (n0 < 4096)      { Bhi = g_wq_hi; Blo = g_wq_lo; ldB = 4096; bn = n0; }
        else if (n0 < 4608) { Bhi = g_wk_hi; Blo = g_wk_lo; ldB = 512;  bn = n0 - 4096; }
        else                { Bhi = g_wv_hi; Blo = g_wv_lo; ldB = 512;  bn = n0 - 4608; }
    } else if (MODE == 1) {
        Ahi = g_attn_hi; Alo = g_attn_lo; Bhi = g_wo_hi; Blo = g_wo_lo; ldB = DMODEL; bn = n0;
    } else if (MODE == 2) {
        Ahi = g_xf_hi; Alo = g_xf_lo;
        Bhi = g_wup_hi + (size_t)e * DMODEL * FDIM;
        Blo = g_wup_lo + (size_t)e * DMODEL * FDIM;
        ldB = FDIM; bn = n0;
    } else {
        Ahi = g_h_hi; Alo = g_h_lo;
        Bhi = g_wdn_hi + (size_t)e * FDIM * DMODEL;
        Blo = g_wdn_lo + (size_t)e * FDIM * DMODEL;
        ldB = DMODEL; bn = n0;
    }

    uint32_t dyn_u = smem_u32(dyn);
    uint32_t tile0 = (dyn_u + 1023u) & ~1023u;
    char* tile0p = dyn + (tile0 - dyn_u);

    auto load_chunk = [&](int c, int s) {
        char* st = tile0p + s * STAGE_BYTES;
        // A hi/lo: 128 rows x 64 bf16 (128B rows, swizzled)
        for (int l = tid; l < 1024; l += 256) {
            int row = l >> 3, seg = l & 7;
            uint32_t off = (uint32_t)(row * 128 + seg * 16);
            uint32_t sw = off ^ ((off >> 3) & 0x70);
            size_t ar;
            if (MODE == 2)      ar = (size_t)(rows_s[row] >> 1) * K;
            else if (MODE == 3) ar = (size_t)rows_s[row] * K;
            else                ar = (size_t)(m0 + row) * K;
            __pipeline_memcpy_async(st + sw,         (const char*)(Ahi + ar + (size_t)c * 64) + seg * 16, 16);
            __pipeline_memcpy_async(st + 16384 + sw, (const char*)(Alo + ar + (size_t)c * 64) + seg * 16, 16);
        }
        // B hi/lo: 64 K-rows x 128 N-cols (256B rows, swizzled) straight from [K,N]
        for (int l = tid; l < 1024; l += 256) {
            int row = l >> 4, seg = l & 15;
            int off = off256(row, seg);
            size_t src = (size_t)(c * 64 + row) * ldB + bn + seg * 8;
            __pipeline_memcpy_async(st + 32768 + off, (const char*)(Bhi + src), 16);
            __pipeline_memcpy_async(st + 49152 + off, (const char*)(Blo + src), 16);
        }
    };

    int warp_m0 = (wid >> 2) * 64;
    int warp_n0 = (wid & 3) * 32;
    int bseg0 = warp_n0 >> 3;
    int g = lane >> 2, tig = lane & 3;

    float c[4][4][4];
#pragma unroll
    for (int mi = 0; mi < 4; mi++)
#pragma unroll
        for (int nj = 0; nj < 4; nj++)
#pragma unroll
            for (int q = 0; q < 4; q++) c[mi][nj][q] = 0.f;

    load_chunk(0, 0);
    __pipeline_commit();
    load_chunk(1, 1);
    __pipeline_commit();

    for (int i = 0; i < NCH; i++) {
        if (i + 2 < NCH) load_chunk(i + 2, (i + 2) % 3);
        __pipeline_commit();
        __pipeline_wait_prior(2);
        __syncthreads();

        uint32_t su  = tile0 + (uint32_t)(i % 3) * STAGE_BYTES;
        uint32_t aHiB = su, aLoB = su + 16384, bHiB = su + 32768, bLoB = su + 49152;

#pragma unroll
        for (int kk = 0; kk < 4; kk++) {
            uint32_t Ah[4][4], Al[4][4], Bh[4][2], Bl[4][2];
            int a_row = lane & 15;
            int a_kb  = 32 * kk + ((lane >> 4) << 4);
#pragma unroll
            for (int mi = 0; mi < 4; mi++) {
                int row = warp_m0 + 16 * mi + a_row;
                ldsm4(lds_addr(aHiB, row, a_kb), Ah[mi]);
                ldsm4(lds_addr(aLoB, row, a_kb), Al[mi]);
            }
            int b_row = 16 * kk + (lane & 15);
#pragma unroll
            for (int nj = 0; nj < 4; nj++) {
                uint32_t baddr = bHiB + off256(b_row, bseg0 + nj);
                ldsm2t(baddr, Bh[nj]);
                ldsm2t(baddr + 16384, Bl[nj]);
            }
#pragma unroll
            for (int mi = 0; mi < 4; mi++)
#pragma unroll
                for (int nj = 0; nj < 4; nj++) {
                    mma16816(c[mi][nj], Ah[mi], Bh[nj]);
                    mma16816(c[mi][nj], Al[mi], Bh[nj]);
                    mma16816(c[mi][nj], Ah[mi], Bl[nj]);
                }
        }
        __syncthreads();
    }

    // ---------------- epilogue ----------------
#pragma unroll
    for (int mi = 0; mi < 4; mi++) {
#pragma unroll
        for (int half = 0; half < 2; half++) {
            int rl = warp_m0 + 16 * mi + 8 * half + g;
            int grow = m0 + rl;
            bool valid = true;
            int slot = 0;
            if (MODE >= 2) { valid = grow < cnt; slot = rows_s[rl]; }
#pragma unroll
            for (int nj = 0; nj < 4; nj++) {
                int col = n0 + warp_n0 + 8 * nj + 2 * tig;
                float v0 = c[mi][nj][2 * half];
                float v1 = c[mi][nj][2 * half + 1];
                if (MODE == 0) {
                    if (col < 4608) {
                        float* dst = g_qkv + (size_t)grow * QKV_N + col;
                        dst[0] = v0; dst[1] = v1;
                    } else {
                        // V columns: split straight to bf16 hi/lo, per-kv-head layout
                        int cc = col - 4608;
                        int kvh = cc >> 7, d = cc & 127;
                        size_t o = ((size_t)kvh * S_LEN + grow) * HDIM + d;
                        float r0, r1;
                        float h0 = bhi(v0, r0), h1 = bhi(v1, r1);
                        *(uint32_t*)(g_vh + o) = pkbf(h0, h1);
                        *(uint32_t*)(g_vl + o) = pkbf(r0, r1);
                    }
                } else if (MODE == 1) {
                    size_t base = (size_t)grow * DMODEL + col;
                    g_hidden2[base]     = v0 + residual[base];
                    g_hidden2[base + 1] = v1 + residual[base + 1];
                } else if (MODE == 2) {
                    if (valid) {
                        const float* bia = bias + e * FDIM;
#pragma unroll
                        for (int d = 0; d < 2; d++) {
                            int f = col + d;
                            float v = (d ? v1 : v0) + bia[f];
                            float sact = v / (1.0f + expf(-v));
                            bf16 h = __float2bfloat16(sact);
                            size_t o = (size_t)slot * FDIM + f;
                            g_h_hi[o] = h;
                            g_h_lo[o] = __float2bfloat16(sact - __bfloat162float(h));
                        }
                    }
                } else {
                    if (valid) {
                        const float* bia = bias + e * DMODEL;
                        float gt = g_gate[slot];
                        g_moepart[(size_t)slot * DMODEL + col]     = gt * (v0 + bia[col]);
                        g_moepart[(size_t)slot * DMODEL + col + 1] = gt * (v1 + bia[col + 1]);
                    }
                }
            }
        }
    }
}

// ================= HMMA flash attention =================
// CTA = (q-tile of 128, head). 8 warps x 16 q-rows. KV tiles of 64, double buffered.
#define ATT_SMEM (65536 + 2 * 65536)
__global__ __launch_bounds__(256, 1) void attn_mma_k() {
    extern __shared__ char sm[];
    uint32_t sb = smem_u32(sm);
    int qi = blockIdx.x, h = blockIdx.y;
    int q0 = qi * 128, kvh = h >> 3;
    int nkv = 2 * (qi + 1);
    int tid = threadIdx.x, wid = tid >> 5, lane = tid & 31;
    int g = lane >> 2, tig = lane & 3;
    int wq0 = wid * 16;

    // fill Q (hi at 0, lo at +32768)
    for (int l = tid; l < 2048; l += 256) {
        int row = l >> 4, seg = l & 15;
        int off = off256(row, seg);
        size_t src = ((size_t)(q0 + row) * NHQ + h) * HDIM + seg * 8;
        __pipeline_memcpy_async(sm + off,         g_qh + src, 16);
        __pipeline_memcpy_async(sm + 32768 + off, g_ql + src, 16);
    }

    auto fill_kv = [&](int t, int st) {
        char* base = sm + 65536 + st * 65536;
        int kv0 = t * 64;
        for (int l = tid; l < 1024; l += 256) {
            int row = l >> 4, seg = l & 15;
            int off = off256(row, seg);
            size_t src = ((size_t)kvh * S_LEN + kv0 + row) * HDIM + seg * 8;
            __pipeline_memcpy_async(base + off,         g_kh + src, 16);
            __pipeline_memcpy_async(base + 16384 + off, g_kl + src, 16);
            __pipeline_memcpy_async(base + 32768 + off, g_vh + src, 16);
            __pipeline_memcpy_async(base + 49152 + off, g_vl + src, 16);
        }
    };

    float o[16][4];
#pragma unroll
    for (int dj = 0; dj < 16; dj++)
#pragma unroll
        for (int q = 0; q < 4; q++) o[dj][q] = 0.f;
    float m0 = -3e38f, m1 = -3e38f, l0 = 0.f, l1 = 0.f;

    fill_kv(0, 0);
    __pipeline_commit();

    for (int t = 0; t < nkv; t++) {
        if (t + 1 < nkv) fill_kv(t + 1, (t + 1) & 1);
        __pipeline_commit();
        __pipeline_wait_prior(1);
        __syncthreads();

        uint32_t st  = sb + 65536 + (uint32_t)(t & 1) * 65536;
        int k0 = t * 64;

        // ---- scores S[16x64] per warp, 3-term split-bf16 ----
        float s[8][4];
#pragma unroll
        for (int nj = 0; nj < 8; nj++)
#pragma unroll
            for (int q = 0; q < 4; q++) s[nj][q] = 0.f;

#pragma unroll
        for (int kk = 0; kk < 8; kk++) {
            uint32_t aqh[4], aql[4];
            int a_row = wq0 + (lane & 15);
            int a_sb  = kk * 2 + ((lane >> 4) & 1);
            uint32_t aaddr = sb + off256(a_row, a_sb);
            ldsm4(aaddr, aqh);
            ldsm4(aaddr + 32768, aql);
#pragma unroll
            for (int nj = 0; nj < 8; nj++) {
                uint32_t bkh[2], bkl[2];
                int b_row = nj * 8 + (lane & 7);
                int b_sb  = kk * 2 + ((lane >> 3) & 1);
                uint32_t baddr = st + off256(b_row, b_sb);
                ldsm2(baddr, bkh);
                ldsm2(baddr + 16384, bkl);
                mma16816(s[nj], aqh, bkh);
                mma16816(s[nj], aql, bkh);
                mma16816(s[nj], aqh, bkl);
            }
        }

        // ---- causal mask ----
        if (k0 + 63 > q0 + wq0) {
            int r0 = q0 + wq0 + g, r1 = r0 + 8;
#pragma unroll
            for (int nj = 0; nj < 8; nj++) {
                int col = k0 + nj * 8 + 2 * tig;
                if (col > r0)     s[nj][0] = -1e9f;
                if (col + 1 > r0) s[nj][1] = -1e9f;
                if (col > r1)     s[nj][2] = -1e9f;
                if (col + 1 > r1) s[nj][3] = -1e9f;
            }
        }

        // ---- online softmax ----
        float mx0 = m0, mx1 = m1;
#pragma unroll
        for (int nj = 0; nj < 8; nj++) {
            mx0 = fmaxf(mx0, fmaxf(s[nj][0], s[nj][1]));
            mx1 = fmaxf(mx1, fmaxf(s[nj][2], s[nj][3]));
        }
        mx0 = fmaxf(mx0, __shfl_xor_sync(0xffffffffu, mx0, 1));
        mx0 = fmaxf(mx0, __shfl_xor_sync(0xffffffffu, mx0, 2));
        mx1 = fmaxf(mx1, __shfl_xor_sync(0xffffffffu, mx1, 1));
        mx1 = fmaxf(mx1, __shfl_xor_sync(0xffffffffu, mx1, 2));
        float a0 = __expf(m0 - mx0), a1 = __expf(m1 - mx1);
        m0 = mx0; m1 = mx1;
        l0 *= a0; l1 *= a1;
#pragma unroll
        for (int dj = 0; dj < 16; dj++) {
            o[dj][0] *= a0; o[dj][1] *= a0;
            o[dj][2] *= a1; o[dj][3] *= a1;
        }

        uint32_t phi[8][2], plo[8][2];
#pragma unroll
        for (int nj = 0; nj < 8; nj++) {
            float p00 = __expf(s[nj][0] - mx0), p01 = __expf(s[nj][1] - mx0);
            float p10 = __expf(s[nj][2] - mx1), p11 = __expf(s[nj][3] - mx1);
            l0 += p00 + p01; l1 += p10 + p11;
            float r00, r01, r10, r11;
            float h00 = bhi(p00, r00), h01 = bhi(p01, r01);
            float h10 = bhi(p10, r10), h11 = bhi(p11, r11);
            phi[nj][0] = pkbf(h00, h01); phi[nj][1] = pkbf(h10, h11);
            plo[nj][0] = pkbf(r00, r01); plo[nj][1] = pkbf(r10, r11);
        }

        // ---- O += P @ V, 3-term ----
        uint32_t vh_b = st + 32768;
#pragma unroll
        for (int kc = 0; kc < 4; kc++) {
            uint32_t aph[4] = { phi[2 * kc][0], phi[2 * kc][1], phi[2 * kc + 1][0], phi[2 * kc + 1][1] };
            uint32_t apl[4] = { plo[2 * kc][0], plo[2 * kc][1], plo[2 * kc + 1][0], plo[2 * kc + 1][1] };
#pragma unroll
            for (int dj = 0; dj < 16; dj++) {
                uint32_t bvh[2], bvl[2];
                int v_row = kc * 16 + (lane & 15);
                uint32_t vaddr = vh_b + off256(v_row, dj);
                ldsm2t(vaddr, bvh);
                ldsm2t(vaddr + 16384, bvl);
                mma16816(o[dj], aph, bvh);
                mma16816(o[dj], apl, bvh);
                mma16816(o[dj], aph, bvl);
            }
        }
        __syncthreads();
    }

    // ---- epilogue: normalize, split, store ----
    l0 += __shfl_xor_sync(0xffffffffu, l0, 1);
    l0 += __shfl_xor_sync(0xffffffffu, l0, 2);
    l1 += __shfl_xor_sync(0xffffffffu, l1, 1);
    l1 += __shfl_xor_sync(0xffffffffu, l1, 2);
    float i0 = 1.0f / l0, i1 = 1.0f / l1;
    int r0 = q0 + wq0 + g, r1 = r0 + 8;
#pragma unroll
    for (int dj = 0; dj < 16; dj++) {
        int cc = dj * 8 + 2 * tig;
        size_t o0 = (size_t)r0 * ATTN_D + h * HDIM + cc;
        size_t o1 = (size_t)r1 * ATTN_D + h * HDIM + cc;
        float ra, rb;
        float v0 = o[dj][0] * i0, v1 = o[dj][1] * i0;
        float h0 = bhi(v0, ra), h1 = bhi(v1, rb);
        *(uint32_t*)(g_attn_hi + o0) = pkbf(h0, h1);
        *(uint32_t*)(g_attn_lo + o0) = pkbf(ra, rb);
        float w0 = o[dj][2] * i1, w1 = o[dj][3] * i1;
        h0 = bhi(w0, ra); h1 = bhi(w1, rb);
        *(uint32_t*)(g_attn_hi + o1) = pkbf(h0, h1);
        *(uint32_t*)(g_attn_lo + o1) = pkbf(ra, rb);
    }
}

// ================= init / router / final =================
__global__ void init_k(float* __restrict__ out) {
    if (threadIdx.x < NEXP) g_cnt[threadIdx.x] = 0;
    if (threadIdx.x == 0) out[(size_t)S_LEN * DMODEL + S_LEN * NEXP] = 1.0f;
}

__global__ void router_k(const float* __restrict__ rW, float* __restrict__ out) {
    int t = blockIdx.x;
    const float* xr = g_xf + (size_t)t * DMODEL;
    int w = threadIdx.x >> 5, lane = threadIdx.x & 31;
    float sum = 0.f;
    for (int dd = lane; dd < DMODEL; dd += 32) sum += xr[dd] * rW[dd * NEXP + w];
    for (int o = 16; o; o >>= 1) sum += __shfl_xor_sync(0xffffffffu, sum, o);
    __shared__ float lg[NEXP];
    if (lane == 0) lg[w] = sum;
    __syncthreads();
    if (threadIdx.x == 0) {
        float* lo = out + (size_t)S_LEN * DMODEL + (size_t)t * NEXP;
        float mx = lg[0];
#pragma unroll
        for (int e = 1; e < NEXP; e++) mx = fmaxf(mx, lg[e]);
        float p[NEXP];
#pragma unroll
        for (int e = 0; e < NEXP; e++) { p[e] = expf(lg[e] - mx); lo[e] = lg[e]; }
        int i1 = 0;
#pragma unroll
        for (int e = 1; e < NEXP; e++) if (lg[e] > lg[i1]) i1 = e;
        int i2 = -1;
#pragma unroll
        for (int e = 0; e < NEXP; e++) {
            if (e == i1) continue;
            if (i2 < 0 || lg[e] > lg[i2]) i2 = e;
        }
        float denom = p[i1] + p[i2];
        g_gate[t * 2]     = p[i1] / denom;
        g_gate[t * 2 + 1] = p[i2] / denom;
        int pos = atomicAdd(&g_cnt[i1], 1);
        g_list[i1][pos] = t * 2;
        pos = atomicAdd(&g_cnt[i2], 1);
        g_list[i2][pos] = t * 2 + 1;
    }
}

__global__ void final_k(float* __restrict__ out) {
    int i = blockIdx.x * 256 + threadIdx.x;   // float4 index
    int t = i / (DMODEL / 4);
    int d = i - t * (DMODEL / 4);
    const float4* h2 = (const float4*)g_hidden2;
    const float4* mp = (const float4*)g_moepart;
    float4 a = h2[i];
    float4 b = mp[(size_t)(2 * t) * (DMODEL / 4) + d];
    float4 c = mp[(size_t)(2 * t + 1) * (DMODEL / 4) + d];
    float4 w;
    w.x = a.x + b.x + c.x; w.y = a.y + b.y + c.y;
    w.z = a.z + b.z + c.z; w.w = a.w + b.w + c.w;
    ((float4*)out)[i] = w;
}

// ================= launch =================
extern "C" void kernel_launch(void* const* d_in, const int* in_sizes, int n_in,
                              void* d_out, int out_size) {
    const float* hs  = (const float*)d_in[0];
    const float* ln1 = (const float*)d_in[1];
    const float* ln2 = (const float*)d_in[2];
    const float* Wq  = (const float*)d_in[3];
    const float* Wk  = (const float*)d_in[4];
    const float* Wv  = (const float*)d_in[5];
    const float* Wo  = (const float*)d_in[6];
    const float* qns = (const float*)d_in[7];
    const float* kns = (const float*)d_in[8];
    const float* rW  = (const float*)d_in[9];
    const float* upW = (const float*)d_in[10];
    const float* upb = (const float*)d_in[11];
    const float* dnW = (const float*)d_in[12];
    const float* dnb = (const float*)d_in[13];
    float* out = (float*)d_out;

    void *wq_hi, *wq_lo, *wk_hi, *wk_lo, *wv_hi, *wv_lo, *wo_hi, *wo_lo;
    void *wup_hi, *wup_lo, *wdn_hi, *wdn_lo;
    cudaGetSymbolAddress(&wq_hi,  g_wq_hi);  cudaGetSymbolAddress(&wq_lo,  g_wq_lo);
    cudaGetSymbolAddress(&wk_hi,  g_wk_hi);  cudaGetSymbolAddress(&wk_lo,  g_wk_lo);
    cudaGetSymbolAddress(&wv_hi,  g_wv_hi);  cudaGetSymbolAddress(&wv_lo,  g_wv_lo);
    cudaGetSymbolAddress(&wo_hi,  g_wo_hi);  cudaGetSymbolAddress(&wo_lo,  g_wo_lo);
    cudaGetSymbolAddress(&wup_hi, g_wup_hi); cudaGetSymbolAddress(&wup_lo, g_wup_lo);
    cudaGetSymbolAddress(&wdn_hi, g_wdn_hi); cudaGetSymbolAddress(&wdn_lo, g_wdn_lo);

    cudaFuncSetAttribute(attn_mma_k, cudaFuncAttributeMaxDynamicSharedMemorySize, ATT_SMEM);
    cudaFuncSetAttribute(mma_gemm_k<0>, cudaFuncAttributeMaxDynamicSharedMemorySize, DSMEM);
    cudaFuncSetAttribute(mma_gemm_k<1>, cudaFuncAttributeMaxDynamicSharedMemorySize, DSMEM);
    cudaFuncSetAttribute(mma_gemm_k<2>, cudaFuncAttributeMaxDynamicSharedMemorySize, DSMEM);
    cudaFuncSetAttribute(mma_gemm_k<3>, cudaFuncAttributeMaxDynamicSharedMemorySize, DSMEM);

    // weight split (native layout, pure streaming)
    split_k<<<(DMODEL * ATTN_D) / 1024, 256>>>((const float4*)Wq, (uint2*)wq_hi, (uint2*)wq_lo);
    split_k<<<(DMODEL * 512) / 1024, 256>>>((const float4*)Wk, (uint2*)wk_hi, (uint2*)wk_lo);
    split_k<<<(DMODEL * 512) / 1024, 256>>>((const float4*)Wv, (uint2*)wv_hi, (uint2*)wv_lo);
    split_k<<<(ATTN_D * DMODEL) / 1024, 256>>>((const float4*)Wo, (uint2*)wo_hi, (uint2*)wo_lo);
    split_k<<<(NEXP * DMODEL * FDIM) / 1024, 256>>>((const float4*)upW, (uint2*)wup_hi, (uint2*)wup_lo);
    split_k<<<(NEXP * FDIM * DMODEL) / 1024, 256>>>((const float4*)dnW, (uint2*)wdn_hi, (uint2*)wdn_lo);

    // 1. rmsnorm1 -> bf16 hi/lo
    rmsnorm1_split_k<<<S_LEN, 256>>>(hs, ln1);
    // 2. fused QKV projection (V split to bf16 in epilogue)
    mma_gemm_k<0><<<dim3(QKV_N / 128, S_LEN / 128), 256, DSMEM>>>(nullptr, nullptr);
    // 3. per-head norm + rope -> split bf16 Q / K
    qk_rope_split_k<<<dim3(S_LEN, NHQ), 128>>>(0, qns);
    qk_rope_split_k<<<dim3(S_LEN, NHKV), 128>>>(1, kns);
    // 4. HMMA flash attention -> g_attn hi/lo
    attn_mma_k<<<dim3(S_LEN / 128, NHQ), 256, ATT_SMEM>>>();
    // 5. output projection + residual
    mma_gemm_k<1><<<dim3(DMODEL / 128, S_LEN / 128), 256, DSMEM>>>(hs, nullptr);
    // 6. rmsnorm2 -> f32 + bf16 hi/lo
    rmsnorm2_split_k<<<S_LEN, 256>>>(ln2);
    // 7. router
    init_k<<<1, 32>>>(out);
    router_k<<<S_LEN, 256>>>(rW, out);
    // 8. MoE (gathered rows)
    mma_gemm_k<2><<<dim3(FDIM / 128, 16, NEXP), 256, DSMEM>>>(nullptr, upb);
    mma_gemm_k<3><<<dim3(DMODEL / 128, 16, NEXP), 256, DSMEM>>>(nullptr, dnb);
    // 9. final residual + MoE sum
    final_k<<<(S_LEN * DMODEL / 4) / 256, 256>>>(out);
}

// round 11
// speedup vs baseline: 5.7568x; 1.0753x over previous
#include <cuda_runtime.h>
#include <cuda_fp16.h>
#include <cuda_pipeline.h>
#include <math.h>
#include <stdint.h>

#define S_LEN 2048
#define DMODEL 2048
#define QKV_N 5120
#define NHQ 32
#define NHKV 4
#define HDIM 128
#define NEXP 8
#define FDIM 768
#define EPSV 1e-6f
#define ATTN_D (NHQ * HDIM)   // 4096

typedef __half f16;

// ================= scratch (device globals; no allocations allowed) =================
__device__ __align__(256) f16   g_x_hi[S_LEN * DMODEL];
__device__ __align__(256) f16   g_x_lo[S_LEN * DMODEL];
__device__ __align__(256) f16   g_qh[S_LEN * NHQ * HDIM];
__device__ __align__(256) f16   g_ql[S_LEN * NHQ * HDIM];
__device__ __align__(256) f16   g_kh[NHKV * S_LEN * HDIM];
__device__ __align__(256) f16   g_kl[NHKV * S_LEN * HDIM];
__device__ __align__(256) f16   g_vh[NHKV * S_LEN * HDIM];
__device__ __align__(256) f16   g_vl[NHKV * S_LEN * HDIM];
__device__ __align__(256) f16   g_attn_hi[S_LEN * ATTN_D];
__device__ __align__(256) f16   g_attn_lo[S_LEN * ATTN_D];
__device__ __align__(256) float g_hidden2[S_LEN * DMODEL];
__device__ __align__(256) float g_xf[S_LEN * DMODEL];
__device__ __align__(256) f16   g_xf_hi[S_LEN * DMODEL];
__device__ __align__(256) f16   g_xf_lo[S_LEN * DMODEL];
__device__ __align__(256) f16   g_h_hi[S_LEN * 2 * FDIM];
__device__ __align__(256) f16   g_h_lo[S_LEN * 2 * FDIM];
__device__ __align__(256) float g_moepart[S_LEN * 2 * DMODEL];
__device__ float g_gate[S_LEN * 2];
__device__ int   g_cnt[NEXP];
__device__ int   g_list[NEXP][S_LEN];
// weights in NATIVE [K, N] layout; QKV/Wo split hi/lo (3-term), MoE single (2-term)
__device__ __align__(256) f16 g_wq_hi[DMODEL * ATTN_D];
__device__ __align__(256) f16 g_wq_lo[DMODEL * ATTN_D];
__device__ __align__(256) f16 g_wk_hi[DMODEL * 512];
__device__ __align__(256) f16 g_wk_lo[DMODEL * 512];
__device__ __align__(256) f16 g_wv_hi[DMODEL * 512];
__device__ __align__(256) f16 g_wv_lo[DMODEL * 512];
__device__ __align__(256) f16 g_wo_hi[ATTN_D * DMODEL];
__device__ __align__(256) f16 g_wo_lo[ATTN_D * DMODEL];
__device__ __align__(256) f16 g_wup[NEXP * DMODEL * FDIM];
__device__ __align__(256) f16 g_wdn[NEXP * FDIM * DMODEL];

// ================= PTX helpers =================
__device__ __forceinline__ uint32_t smem_u32(const void* p) {
    uint32_t a;
    asm("{ .reg .u64 t; cvta.to.shared.u64 t, %1; cvt.u32.u64 %0, t; }" : "=r"(a) : "l"(p));
    return a;
}
__device__ __forceinline__ void ldsm4(uint32_t a, uint32_t r[4]) {
    asm volatile("ldmatrix.sync.aligned.m8n8.x4.shared.b16 {%0,%1,%2,%3}, [%4];"
                 : "=r"(r[0]), "=r"(r[1]), "=r"(r[2]), "=r"(r[3]) : "r"(a));
}
__device__ __forceinline__ void ldsm2(uint32_t a, uint32_t r[2]) {
    asm volatile("ldmatrix.sync.aligned.m8n8.x2.shared.b16 {%0,%1}, [%2];"
                 : "=r"(r[0]), "=r"(r[1]) : "r"(a));
}
__device__ __forceinline__ void ldsm2t(uint32_t a, uint32_t r[2]) {
    asm volatile("ldmatrix.sync.aligned.m8n8.x2.trans.shared.b16 {%0,%1}, [%2];"
                 : "=r"(r[0]), "=r"(r[1]) : "r"(a));
}
__device__ __forceinline__ void mma16816(float c[4], const uint32_t a[4], const uint32_t b[2]) {
    asm volatile(
        "mma.sync.aligned.m16n8k16.row.col.f32.f16.f16.f32 "
        "{%0,%1,%2,%3}, {%4,%5,%6,%7}, {%8,%9}, {%0,%1,%2,%3};"
        : "+f"(c[0]), "+f"(c[1]), "+f"(c[2]), "+f"(c[3])
        : "r"(a[0]), "r"(a[1]), "r"(a[2]), "r"(a[3]), "r"(b[0]), "r"(b[1]));
}
__device__ __forceinline__ uint32_t lds_addr(uint32_t base, int row, int kbyte) {
    int seg = kbyte >> 4;
    return base + row * 128 + (((uint32_t)(seg ^ (row & 7))) << 4);
}
__device__ __forceinline__ int off256(int row, int seg) {
    return row * 256 + ((seg ^ (row & 7)) << 4);
}
__device__ __forceinline__ uint32_t pkhf(float x, float y) {
    __half2 t = __floats2half2_rn(x, y);
    return *reinterpret_cast<uint32_t*>(&t);
}
__device__ __forceinline__ float hhi(float x, float& r) {
    float h = __half2float(__float2half_rn(x));
    r = x - h;
    return h;
}

// ================= weight prep =================
__global__ void split_k(const float4* __restrict__ in, uint2* __restrict__ hi,
                        uint2* __restrict__ lo) {
    size_t i = (size_t)blockIdx.x * 256 + threadIdx.x;
    float4 v = in[i];
    float r0, r1, r2, r3;
    float h0 = hhi(v.x, r0), h1 = hhi(v.y, r1), h2 = hhi(v.z, r2), h3 = hhi(v.w, r3);
    hi[i] = make_uint2(pkhf(h0, h1), pkhf(h2, h3));
    lo[i] = make_uint2(pkhf(r0, r1), pkhf(r2, r3));
}
__global__ void convert_k(const float4* __restrict__ in, uint2* __restrict__ out) {
    size_t i = (size_t)blockIdx.x * 256 + threadIdx.x;
    float4 v = in[i];
    out[i] = make_uint2(pkhf(v.x, v.y), pkhf(v.z, v.w));
}

// ================= rmsnorm variants =================
__global__ void rmsnorm1_split_k(const float* __restrict__ in, const float* __restrict__ sc) {
    int row = blockIdx.x;
    const float* r = in + (size_t)row * DMODEL;
    float ss = 0.f;
    for (int i = threadIdx.x; i < DMODEL; i += 256) { float v = r[i]; ss += v * v; }
    for (int o = 16; o; o >>= 1) ss += __shfl_xor_sync(0xffffffffu, ss, o);
    __shared__ float red[8];
    if ((threadIdx.x & 31) == 0) red[threadIdx.x >> 5] = ss;
    __syncthreads();
    float tot = 0.f;
#pragma unroll
    for (int i = 0; i < 8; i++) tot += red[i];
    float inv = rsqrtf(tot / (float)DMODEL + EPSV);
    for (int i = threadIdx.x; i < DMODEL; i += 256) {
        float w = r[i] * inv * sc[i];
        float rem;
        float h = hhi(w, rem);
        size_t o = (size_t)row * DMODEL + i;
        g_x_hi[o] = __float2half_rn(h);
        g_x_lo[o] = __float2half_rn(rem);
    }
}

__global__ void rmsnorm2_split_k(const float* __restrict__ sc) {
    int row = blockIdx.x;
    const float* r = g_hidden2 + (size_t)row * DMODEL;
    float ss = 0.f;
    for (int i = threadIdx.x; i < DMODEL; i += 256) { float v = r[i]; ss += v * v; }
    for (int o = 16; o; o >>= 1) ss += __shfl_xor_sync(0xffffffffu, ss, o);
    __shared__ float red[8];
    if ((threadIdx.x & 31) == 0) red[threadIdx.x >> 5] = ss;
    __syncthreads();
    float tot = 0.f;
#pragma unroll
    for (int i = 0; i < 8; i++) tot += red[i];
    float inv = rsqrtf(tot / (float)DMODEL + EPSV);
    for (int i = threadIdx.x; i < DMODEL; i += 256) {
        float w = r[i] * inv * sc[i];
        size_t o = (size_t)row * DMODEL + i;
        g_xf[o] = w;
        float rem;
        float h = hhi(w, rem);
        g_xf_hi[o] = __float2half_rn(h);
        g_xf_lo[o] = __float2half_rn(rem);
    }
}

// ================= HMMA split-fp16 GEMM (B native [K,N] via ldmatrix.trans) =========
// MODE 0: QKV (3-term) — Q/K epilogue fuses qknorm+rope+split; V split direct
// MODE 1: Wo (3-term) + residual
// MODE 2: MoE up (2-term), epi bias+silu -> g_h hi/lo
// MODE 3: MoE dn (2-term), epi gate*(acc+bias) -> g_moepart
#define STAGE_BYTES 65536
#define DSMEM (3 * STAGE_BYTES + 1024)

template<int MODE>
__global__ __launch_bounds__(256, 1) void mma_gemm_k(const float* __restrict__ arg0,
                                                     const float* __restrict__ arg1) {
    constexpr int K   = (MODE == 1) ? ATTN_D : (MODE == 3) ? FDIM : DMODEL;
    constexpr int NCH = K / 64;
    constexpr bool THREE = (MODE < 2);

    extern __shared__ char dyn[];
    __shared__ int rows_s[128];

    int tid = threadIdx.x, wid = tid >> 5, lane = tid & 31;
    int e = blockIdx.z;
    int m0 = blockIdx.y * 128;
    int n0 = blockIdx.x * 128;

    int cnt = 0;
    if (MODE >= 2) {
        cnt = g_cnt[e];
        if (m0 >= cnt) return;
        if (tid < 128)
            rows_s[tid] = (m0 + tid < cnt) ? g_list[e][m0 + tid] : g_list[e][0];
        __syncthreads();
    }

    const f16 *Ahi, *Alo, *Bhi, *Blo = nullptr;
    int ldB, bn;
    if (MODE == 0) {
        Ahi = g_x_hi; Alo = g_x_lo;
        if (n0 < 4096)      { Bhi = g_wq_hi; Blo = g_wq_lo; ldB = 4096; bn = n0; }
        else if (n0 < 4608) { Bhi = g_wk_hi; Blo = g_wk_lo; ldB = 512;  bn = n0 - 4096; }
        else                { Bhi = g_wv_hi; Blo = g_wv_lo; ldB = 512;  bn = n0 - 4608; }
    } else if (MODE == 1) {
        Ahi = g_attn_hi; Alo = g_attn_lo; Bhi = g_wo_hi; Blo = g_wo_lo; ldB = DMODEL; bn = n0;
    } else if (MODE == 2) {
        Ahi = g_xf_hi; Alo = g_xf_lo;
        Bhi = g_wup + (size_t)e * DMODEL * FDIM;
        ldB = FDIM; bn = n0;
    } else {
        Ahi = g_h_hi; Alo = g_h_lo;
        Bhi = g_wdn + (size_t)e * FDIM * DMODEL;
        ldB = DMODEL; bn = n0;
    }

    uint32_t dyn_u = smem_u32(dyn);
    uint32_t tile0 = (dyn_u + 1023u) & ~1023u;
    char* tile0p = dyn + (tile0 - dyn_u);

    auto load_chunk = [&](int c, int s) {
        char* st = tile0p + s * STAGE_BYTES;
        for (int l = tid; l < 1024; l += 256) {
            int row = l >> 3, seg = l & 7;
            uint32_t off = (uint32_t)(row * 128 + seg * 16);
            uint32_t sw = off ^ ((off >> 3) & 0x70);
            size_t ar;
            if (MODE == 2)      ar = (size_t)(rows_s[row] >> 1) * K;
            else if (MODE == 3) ar = (size_t)rows_s[row] * K;
            else                ar = (size_t)(m0 + row) * K;
            __pipeline_memcpy_async(st + sw,         (const char*)(Ahi + ar + (size_t)c * 64) + seg * 16, 16);
            __pipeline_memcpy_async(st + 16384 + sw, (const char*)(Alo + ar + (size_t)c * 64) + seg * 16, 16);
        }
        for (int l = tid; l < 1024; l += 256) {
            int row = l >> 4, seg = l & 15;
            int off = off256(row, seg);
            size_t src = (size_t)(c * 64 + row) * ldB + bn + seg * 8;
            __pipeline_memcpy_async(st + 32768 + off, (const char*)(Bhi + src), 16);
            if (THREE)
                __pipeline_memcpy_async(st + 49152 + off, (const char*)(Blo + src), 16);
        }
    };

    int warp_m0 = (wid >> 2) * 64;
    int warp_n0 = (wid & 3) * 32;
    int bseg0 = warp_n0 >> 3;
    int g = lane >> 2, tig = lane & 3;

    float c[4][4][4];
#pragma unroll
    for (int mi = 0; mi < 4; mi++)
#pragma unroll
        for (int nj = 0; nj < 4; nj++)
#pragma unroll
            for (int q = 0; q < 4; q++) c[mi][nj][q] = 0.f;

    load_chunk(0, 0);
    __pipeline_commit();
    load_chunk(1, 1);
    __pipeline_commit();

    for (int i = 0; i < NCH; i++) {
        if (i + 2 < NCH) load_chunk(i + 2, (i + 2) % 3);
        __pipeline_commit();
        __pipeline_wait_prior(2);
        __syncthreads();

        uint32_t su  = tile0 + (uint32_t)(i % 3) * STAGE_BYTES;
        uint32_t aHiB = su, aLoB = su + 16384, bHiB = su + 32768;

#pragma unroll
        for (int kk = 0; kk < 4; kk++) {
            uint32_t Ah[4][4], Al[4][4], Bh[4][2], Bl[4][2];
            int a_row = lane & 15;
            int a_kb  = 32 * kk + ((lane >> 4) << 4);
#pragma unroll
            for (int mi = 0; mi < 4; mi++) {
                int row = warp_m0 + 16 * mi + a_row;
                ldsm4(lds_addr(aHiB, row, a_kb), Ah[mi]);
                ldsm4(lds_addr(aLoB, row, a_kb), Al[mi]);
            }
            int b_row = 16 * kk + (lane & 15);
#pragma unroll
            for (int nj = 0; nj < 4; nj++) {
                uint32_t baddr = bHiB + off256(b_row, bseg0 + nj);
                ldsm2t(baddr, Bh[nj]);
                if (THREE) ldsm2t(baddr + 16384, Bl[nj]);
            }
#pragma unroll
            for (int mi = 0; mi < 4; mi++)
#pragma unroll
                for (int nj = 0; nj < 4; nj++) {
                    mma16816(c[mi][nj], Ah[mi], Bh[nj]);
                    mma16816(c[mi][nj], Al[mi], Bh[nj]);
                    if (THREE) mma16816(c[mi][nj], Ah[mi], Bl[nj]);
                }
        }
        __syncthreads();
    }

    // ---------- MODE 0 Q/K: fused qknorm + rope + fp16 split ----------
    if (MODE == 0 && n0 < 4608) {
        float* S = (float*)tile0p;   // 128 x 132 fp32
#pragma unroll
        for (int mi = 0; mi < 4; mi++)
#pragma unroll
            for (int hh = 0; hh < 2; hh++) {
                int rl = warp_m0 + 16 * mi + 8 * hh + g;
#pragma unroll
                for (int nj = 0; nj < 4; nj++) {
                    int colL = warp_n0 + 8 * nj + 2 * tig;
                    S[rl * 132 + colL]     = c[mi][nj][2 * hh];
                    S[rl * 132 + colL + 1] = c[mi][nj][2 * hh + 1];
                }
            }
        __syncthreads();
        int isK = (n0 >= 4096);
        int head = (isK ? (n0 - 4096) : n0) >> 7;
        const float* sc = isK ? arg1 : arg0;
        f16* dsth = isK ? g_kh : g_qh;
        f16* dstl = isK ? g_kl : g_ql;
        for (int rr = 0; rr < 16; rr++) {
            int row = wid * 16 + rr;
            const float* Sr = S + row * 132;
            float v[4];
            float ss = 0.f;
#pragma unroll
            for (int k = 0; k < 4; k++) { v[k] = Sr[lane * 4 + k]; ss += v[k] * v[k]; }
#pragma unroll
            for (int o = 16; o; o >>= 1) ss += __shfl_xor_sync(0xffffffffu, ss, o);
            float inv = rsqrtf(ss * (1.0f / 128.0f) + EPSV);
            int sg = m0 + row;
            uint32_t hiW[2], loW[2];
#pragma unroll
            for (int kp = 0; kp < 2; kp++) {
                float outv[2], remv[2];
#pragma unroll
                for (int k2 = 0; k2 < 2; k2++) {
                    int d = lane * 4 + kp * 2 + k2;
                    float n = v[kp * 2 + k2] * inv * sc[d];
                    int j = d & 63;
                    float invf = expf(-0.21586735246819178f * (float)j);
                    float ang = (float)sg * invf;
                    float si, co;
                    sincosf(ang, &si, &co);
                    int od = (d < 64) ? d + 64 : d - 64;
                    float no = Sr[od] * inv * sc[od];
                    float rot = (d < 64) ? -no : no;
                    float val = n * co + rot * si;
                    if (!isK) val *= 0.08838834764831845f;   // fold 1/sqrt(128) into Q
                    outv[k2] = hhi(val, remv[k2]);
                }
                hiW[kp] = pkhf(outv[0], outv[1]);
                loW[kp] = pkhf(remv[0], remv[1]);
            }
            size_t o = isK ? (((size_t)head * S_LEN + sg) * HDIM + lane * 4)
                           : (((size_t)sg * NHQ + head) * HDIM + lane * 4);
            *(uint2*)(dsth + o) = make_uint2(hiW[0], hiW[1]);
            *(uint2*)(dstl + o) = make_uint2(loW[0], loW[1]);
        }
        return;
    }

    // ---------------- generic epilogue ----------------
#pragma unroll
    for (int mi = 0; mi < 4; mi++) {
#pragma unroll
        for (int hh = 0; hh < 2; hh++) {
            int rl = warp_m0 + 16 * mi + 8 * hh + g;
            int grow = m0 + rl;
            bool valid = true;
            int slot = 0;
            if (MODE >= 2) { valid = grow < cnt; slot = rows_s[rl]; }
#pragma unroll
            for (int nj = 0; nj < 4; nj++) {
                int col = n0 + warp_n0 + 8 * nj + 2 * tig;
                float v0 = c[mi][nj][2 * hh];
                float v1 = c[mi][nj][2 * hh + 1];
                if (MODE == 0) {
                    // V columns only (n0 >= 4608)
                    int cc = col - 4608;
                    int kvh = cc >> 7, d = cc & 127;
                    size_t o = ((size_t)kvh * S_LEN + grow) * HDIM + d;
                    float r0, r1;
                    float h0 = hhi(v0, r0), h1 = hhi(v1, r1);
                    *(uint32_t*)(g_vh + o) = pkhf(h0, h1);
                    *(uint32_t*)(g_vl + o) = pkhf(r0, r1);
                } else if (MODE == 1) {
                    size_t base = (size_t)grow * DMODEL + col;
                    g_hidden2[base]     = v0 + arg0[base];
                    g_hidden2[base + 1] = v1 + arg0[base + 1];
                } else if (MODE == 2) {
                    if (valid) {
                        const float* bia = arg1 + e * FDIM;
#pragma unroll
                        for (int d = 0; d < 2; d++) {
                            int f = col + d;
                            float v = (d ? v1 : v0) + bia[f];
                            float sact = v / (1.0f + expf(-v));
                            float rem;
                            float h = hhi(sact, rem);
                            size_t o = (size_t)slot * FDIM + f;
                            g_h_hi[o] = __float2half_rn(h);
                            g_h_lo[o] = __float2half_rn(rem);
                        }
                    }
                } else {
                    if (valid) {
                        const float* bia = arg1 + e * DMODEL;
                        float gt = g_gate[slot];
                        g_moepart[(size_t)slot * DMODEL + col]     = gt * (v0 + bia[col]);
                        g_moepart[(size_t)slot * DMODEL + col + 1] = gt * (v1 + bia[col + 1]);
                    }
                }
            }
        }
    }
}

// ================= HMMA flash attention (fp16, 3-term) =================
#define ATT_SMEM (65536 + 2 * 65536)
__global__ __launch_bounds__(256, 1) void attn_mma_k() {
    extern __shared__ char sm[];
    uint32_t sb = smem_u32(sm);
    int qi = gridDim.x - 1 - blockIdx.x;   // heaviest tiles first
    int h = blockIdx.y;
    int q0 = qi * 128, kvh = h >> 3;
    int nkv = 2 * (qi + 1);
    int tid = threadIdx.x, wid = tid >> 5, lane = tid & 31;
    int g = lane >> 2, tig = lane & 3;
    int wq0 = wid * 16;

    for (int l = tid; l < 2048; l += 256) {
        int row = l >> 4, seg = l & 15;
        int off = off256(row, seg);
        size_t src = ((size_t)(q0 + row) * NHQ + h) * HDIM + seg * 8;
        __pipeline_memcpy_async(sm + off,         g_qh + src, 16);
        __pipeline_memcpy_async(sm + 32768 + off, g_ql + src, 16);
    }

    auto fill_kv = [&](int t, int st) {
        char* base = sm + 65536 + st * 65536;
        int kv0 = t * 64;
        for (int l = tid; l < 1024; l += 256) {
            int row = l >> 4, seg = l & 15;
            int off = off256(row, seg);
            size_t src = ((size_t)kvh * S_LEN + kv0 + row) * HDIM + seg * 8;
            __pipeline_memcpy_async(base + off,         g_kh + src, 16);
            __pipeline_memcpy_async(base + 16384 + off, g_kl + src, 16);
            __pipeline_memcpy_async(base + 32768 + off, g_vh + src, 16);
            __pipeline_memcpy_async(base + 49152 + off, g_vl + src, 16);
        }
    };

    float o[16][4];
#pragma unroll
    for (int dj = 0; dj < 16; dj++)
#pragma unroll
        for (int q = 0; q < 4; q++) o[dj][q] = 0.f;
    float m0 = -3e38f, m1 = -3e38f, l0 = 0.f, l1 = 0.f;

    fill_kv(0, 0);
    __pipeline_commit();

    for (int t = 0; t < nkv; t++) {
        if (t + 1 < nkv) fill_kv(t + 1, (t + 1) & 1);
        __pipeline_commit();
        __pipeline_wait_prior(1);
        __syncthreads();

        uint32_t st  = sb + 65536 + (uint32_t)(t & 1) * 65536;
        int k0 = t * 64;

        float s[8][4];
#pragma unroll
        for (int nj = 0; nj < 8; nj++)
#pragma unroll
            for (int q = 0; q < 4; q++) s[nj][q] = 0.f;

#pragma unroll
        for (int kk = 0; kk < 8; kk++) {
            uint32_t aqh[4], aql[4];
            int a_row = wq0 + (lane & 15);
            int a_sb  = kk * 2 + ((lane >> 4) & 1);
            uint32_t aaddr = sb + off256(a_row, a_sb);
            ldsm4(aaddr, aqh);
            ldsm4(aaddr + 32768, aql);
#pragma unroll
            for (int nj = 0; nj < 8; nj++) {
                uint32_t bkh[2], bkl[2];
                int b_row = nj * 8 + (lane & 7);
                int b_sb  = kk * 2 + ((lane >> 3) & 1);
                uint32_t baddr = st + off256(b_row, b_sb);
                ldsm2(baddr, bkh);
                ldsm2(baddr + 16384, bkl);
                mma16816(s[nj], aqh, bkh);
                mma16816(s[nj], aql, bkh);
                mma16816(s[nj], aqh, bkl);
            }
        }

        if (k0 + 63 > q0 + wq0) {
            int r0 = q0 + wq0 + g, r1 = r0 + 8;
#pragma unroll
            for (int nj = 0; nj < 8; nj++) {
                int col = k0 + nj * 8 + 2 * tig;
                if (col > r0)     s[nj][0] = -1e9f;
                if (col + 1 > r0) s[nj][1] = -1e9f;
                if (col > r1)     s[nj][2] = -1e9f;
                if (col + 1 > r1) s[nj][3] = -1e9f;
            }
        }

        float mx0 = m0, mx1 = m1;
#pragma unroll
        for (int nj = 0; nj < 8; nj++) {
            mx0 = fmaxf(mx0, fmaxf(s[nj][0], s[nj][1]));
            mx1 = fmaxf(mx1, fmaxf(s[nj][2], s[nj][3]));
        }
        mx0 = fmaxf(mx0, __shfl_xor_sync(0xffffffffu, mx0, 1));
        mx0 = fmaxf(mx0, __shfl_xor_sync(0xffffffffu, mx0, 2));
        mx1 = fmaxf(mx1, __shfl_xor_sync(0xffffffffu, mx1, 1));
        mx1 = fmaxf(mx1, __shfl_xor_sync(0xffffffffu, mx1, 2));
        float a0 = __expf(m0 - mx0), a1 = __expf(m1 - mx1);
        m0 = mx0; m1 = mx1;
        l0 *= a0; l1 *= a1;
#pragma unroll
        for (int dj = 0; dj < 16; dj++) {
            o[dj][0] *= a0; o[dj][1] *= a0;
            o[dj][2] *= a1; o[dj][3] *= a1;
        }

        uint32_t phi[8][2], plo[8][2];
#pragma unroll
        for (int nj = 0; nj < 8; nj++) {
            float p00 = __expf(s[nj][0] - mx0), p01 = __expf(s[nj][1] - mx0);
            float p10 = __expf(s[nj][2] - mx1), p11 = __expf(s[nj][3] - mx1);
            l0 += p00 + p01; l1 += p10 + p11;
            float r00, r01, r10, r11;
            float h00 = hhi(p00, r00), h01 = hhi(p01, r01);
            float h10 = hhi(p10, r10), h11 = hhi(p11, r11);
            phi[nj][0] = pkhf(h00, h01); phi[nj][1] = pkhf(h10, h11);
            plo[nj][0] = pkhf(r00, r01); plo[nj][1] = pkhf(r10, r11);
        }

        uint32_t vh_b = st + 32768;
#pragma unroll
        for (int kc = 0; kc < 4; kc++) {
            uint32_t aph[4] = { phi[2 * kc][0], phi[2 * kc][1], phi[2 * kc + 1][0], phi[2 * kc + 1][1] };
            uint32_t apl[4] = { plo[2 * kc][0], plo[2 * kc][1], plo[2 * kc + 1][0], plo[2 * kc + 1][1] };
#pragma unroll
            for (int dj = 0; dj < 16; dj++) {
                uint32_t bvh[2], bvl[2];
                int v_row = kc * 16 + (lane & 15);
                uint32_t vaddr = vh_b + off256(v_row, dj);
                ldsm2t(vaddr, bvh);
                ldsm2t(vaddr + 16384, bvl);
                mma16816(o[dj], aph, bvh);
                mma16816(o[dj], apl, bvh);
                mma16816(o[dj], aph, bvl);
            }
        }
        __syncthreads();
    }

    l0 += __shfl_xor_sync(0xffffffffu, l0, 1);
    l0 += __shfl_xor_sync(0xffffffffu, l0, 2);
    l1 += __shfl_xor_sync(0xffffffffu, l1, 1);
    l1 += __shfl_xor_sync(0xffffffffu, l1, 2);
    float i0 = 1.0f / l0, i1 = 1.0f / l1;
    int r0 = q0 + wq0 + g, r1 = r0 + 8;
#pragma unroll
    for (int dj = 0; dj < 16; dj++) {
        int cc = dj * 8 + 2 * tig;
        size_t o0 = (size_t)r0 * ATTN_D + h * HDIM + cc;
        size_t o1 = (size_t)r1 * ATTN_D + h * HDIM + cc;
        float ra, rb;
        float v0 = o[dj][0] * i0, v1 = o[dj][1] * i0;
        float h0 = hhi(v0, ra), h1 = hhi(v1, rb);
        *(uint32_t*)(g_attn_hi + o0) = pkhf(h0, h1);
        *(uint32_t*)(g_attn_lo + o0) = pkhf(ra, rb);
        float w0 = o[dj][2] * i1, w1 = o[dj][3] * i1;
        h0 = hhi(w0, ra); h1 = hhi(w1, rb);
        *(uint32_t*)(g_attn_hi + o1) = pkhf(h0, h1);
        *(uint32_t*)(g_attn_lo + o1) = pkhf(ra, rb);
    }
}

// ================= init / router / final =================
__global__ void init_k(float* __restrict__ out) {
    if (threadIdx.x < NEXP) g_cnt[threadIdx.x] = 0;
    if (threadIdx.x == 0) out[(size_t)S_LEN * DMODEL + S_LEN * NEXP] = 1.0f;
}

__global__ void router_k(const float* __restrict__ rW, float* __restrict__ out) {
    int t = blockIdx.x;
    const float* xr = g_xf + (size_t)t * DMODEL;
    int w = threadIdx.x >> 5, lane = threadIdx.x & 31;
    float sum = 0.f;
    for (int dd = lane; dd < DMODEL; dd += 32) sum += xr[dd] * rW[dd * NEXP + w];
    for (int o = 16; o; o >>= 1) sum += __shfl_xor_sync(0xffffffffu, sum, o);
    __shared__ float lg[NEXP];
    if (lane == 0) lg[w] = sum;
    __syncthreads();
    if (threadIdx.x == 0) {
        float* lo = out + (size_t)S_LEN * DMODEL + (size_t)t * NEXP;
        float mx = lg[0];
#pragma unroll
        for (int e = 1; e < NEXP; e++) mx = fmaxf(mx, lg[e]);
        float p[NEXP];
#pragma unroll
        for (int e = 0; e < NEXP; e++) { p[e] = expf(lg[e] - mx); lo[e] = lg[e]; }
        int i1 = 0;
#pragma unroll
        for (int e = 1; e < NEXP; e++) if (lg[e] > lg[i1]) i1 = e;
        int i2 = -1;
#pragma unroll
        for (int e = 0; e < NEXP; e++) {
            if (e == i1) continue;
            if (i2 < 0 || lg[e] > lg[i2]) i2 = e;
        }
        float denom = p[i1] + p[i2];
        g_gate[t * 2]     = p[i1] / denom;
        g_gate[t * 2 + 1] = p[i2] / denom;
        int pos = atomicAdd(&g_cnt[i1], 1);
        g_list[i1][pos] = t * 2;
        pos = atomicAdd(&g_cnt[i2], 1);
        g_list[i2][pos] = t * 2 + 1;
    }
}

__global__ void final_k(float* __restrict__ out) {
    int i = blockIdx.x * 256 + threadIdx.x;   // float4 index
    int t = i / (DMODEL / 4);
    int d = i - t * (DMODEL / 4);
    const float4* h2 = (const float4*)g_hidden2;
    const float4* mp = (const float4*)g_moepart;
    float4 a = h2[i];
    float4 b = mp[(size_t)(2 * t) * (DMODEL / 4) + d];
    float4 c = mp[(size_t)(2 * t + 1) * (DMODEL / 4) + d];
    float4 w;
    w.x = a.x + b.x + c.x; w.y = a.y + b.y + c.y;
    w.z = a.z + b.z + c.z; w.w = a.w + b.w + c.w;
    ((float4*)out)[i] = w;
}

// ================= launch =================
extern "C" void kernel_launch(void* const* d_in, const int* in_sizes, int n_in,
                              void* d_out, int out_size) {
    const float* hs  = (const float*)d_in[0];
    const float* ln1 = (const float*)d_in[1];
    const float* ln2 = (const float*)d_in[2];
    const float* Wq  = (const float*)d_in[3];
    const float* Wk  = (const float*)d_in[4];
    const float* Wv  = (const float*)d_in[5];
    const float* Wo  = (const float*)d_in[6];
    const float* qns = (const float*)d_in[7];
    const float* kns = (const float*)d_in[8];
    const float* rW  = (const float*)d_in[9];
    const float* upW = (const float*)d_in[10];
    const float* upb = (const float*)d_in[11];
    const float* dnW = (const float*)d_in[12];
    const float* dnb = (const float*)d_in[13];
    float* out = (float*)d_out;

    void *wq_hi, *wq_lo, *wk_hi, *wk_lo, *wv_hi, *wv_lo, *wo_hi, *wo_lo, *wup, *wdn;
    cudaGetSymbolAddress(&wq_hi, g_wq_hi);  cudaGetSymbolAddress(&wq_lo, g_wq_lo);
    cudaGetSymbolAddress(&wk_hi, g_wk_hi);  cudaGetSymbolAddress(&wk_lo, g_wk_lo);
    cudaGetSymbolAddress(&wv_hi, g_wv_hi);  cudaGetSymbolAddress(&wv_lo, g_wv_lo);
    cudaGetSymbolAddress(&wo_hi, g_wo_hi);  cudaGetSymbolAddress(&wo_lo, g_wo_lo);
    cudaGetSymbolAddress(&wup, g_wup);      cudaGetSymbolAddress(&wdn, g_wdn);

    cudaFuncSetAttribute(attn_mma_k, cudaFuncAttributeMaxDynamicSharedMemorySize, ATT_SMEM);
    cudaFuncSetAttribute(mma_gemm_k<0>, cudaFuncAttributeMaxDynamicSharedMemorySize, DSMEM);
    cudaFuncSetAttribute(mma_gemm_k<1>, cudaFuncAttributeMaxDynamicSharedMemorySize, DSMEM);
    cudaFuncSetAttribute(mma_gemm_k<2>, cudaFuncAttributeMaxDynamicSharedMemorySize, DSMEM);
    cudaFuncSetAttribute(mma_gemm_k<3>, cudaFuncAttributeMaxDynamicSharedMemorySize, DSMEM);

    // weight prep: split for 3-term (QKV/Wo), plain convert for 2-term (MoE)
    split_k<<<(DMODEL * ATTN_D) / 1024, 256>>>((const float4*)Wq, (uint2*)wq_hi, (uint2*)wq_lo);
    split_k<<<(DMODEL * 512) / 1024, 256>>>((const float4*)Wk, (uint2*)wk_hi, (uint2*)wk_lo);
    split_k<<<(DMODEL * 512) / 1024, 256>>>((const float4*)Wv, (uint2*)wv_hi, (uint2*)wv_lo);
    split_k<<<(ATTN_D * DMODEL) / 1024, 256>>>((const float4*)Wo, (uint2*)wo_hi, (uint2*)wo_lo);
    convert_k<<<(NEXP * DMODEL * FDIM) / 1024, 256>>>((const float4*)upW, (uint2*)wup);
    convert_k<<<(NEXP * FDIM * DMODEL) / 1024, 256>>>((const float4*)dnW, (uint2*)wdn);

    // 1. rmsnorm1 -> fp16 hi/lo
    rmsnorm1_split_k<<<S_LEN, 256>>>(hs, ln1);
    // 2. fused QKV projection; Q/K epilogue does qknorm+rope+split, V split direct
    mma_gemm_k<0><<<dim3(QKV_N / 128, S_LEN / 128), 256, DSMEM>>>(qns, kns);
    // 3. HMMA flash attention -> g_attn hi/lo
    attn_mma_k<<<dim3(S_LEN / 128, NHQ), 256, ATT_SMEM>>>();
    // 4. output projection + residual
    mma_gemm_k<1><<<dim3(DMODEL / 128, S_LEN / 128), 256, DSMEM>>>(hs, nullptr);
    // 5. rmsnorm2 -> f32 + fp16 hi/lo
    rmsnorm2_split_k<<<S_LEN, 256>>>(ln2);
    // 6. router
    init_k<<<1, 32>>>(out);
    router_k<<<S_LEN, 256>>>(rW, out);
    // 7. MoE (gathered rows, 2-term)
    mma_gemm_k<2><<<dim3(FDIM / 128, 16, NEXP), 256, DSMEM>>>(nullptr, upb);
    mma_gemm_k<3><<<dim3(DMODEL / 128, 16, NEXP), 256, DSMEM>>>(nullptr, dnb);
    // 8. final residual + MoE sum
    final_k<<<(S_LEN * DMODEL / 4) / 256, 256>>>(out);
}

// round 12
// speedup vs baseline: 6.0761x; 1.0555x over previous
#include <cuda_runtime.h>
#include <cuda_fp16.h>
#include <cuda_pipeline.h>
#include <math.h>
#include <stdint.h>

#define S_LEN 2048
#define DMODEL 2048
#define QKV_N 5120
#define NHQ 32
#define NHKV 4
#define HDIM 128
#define NEXP 8
#define FDIM 768
#define EPSV 1e-6f
#define ATTN_D (NHQ * HDIM)   // 4096

typedef __half f16;

// ================= scratch (device globals; no allocations allowed) =================
__device__ __align__(256) f16   g_x_hi[S_LEN * DMODEL];
__device__ __align__(256) f16   g_x_lo[S_LEN * DMODEL];
__device__ __align__(256) f16   g_qh[S_LEN * NHQ * HDIM];
__device__ __align__(256) f16   g_ql[S_LEN * NHQ * HDIM];
__device__ __align__(256) f16   g_kh[NHKV * S_LEN * HDIM];
__device__ __align__(256) f16   g_kl[NHKV * S_LEN * HDIM];
__device__ __align__(256) f16   g_vh[NHKV * S_LEN * HDIM];
__device__ __align__(256) f16   g_vl[NHKV * S_LEN * HDIM];
__device__ __align__(256) f16   g_attn_hi[S_LEN * ATTN_D];
__device__ __align__(256) f16   g_attn_lo[S_LEN * ATTN_D];
__device__ __align__(256) float g_hidden2[S_LEN * DMODEL];
__device__ __align__(256) f16   g_xf_hi[S_LEN * DMODEL];
__device__ __align__(256) f16   g_h_hi[S_LEN * 2 * FDIM];
__device__ __align__(256) float g_moepart[S_LEN * 2 * DMODEL];
__device__ float g_gate[S_LEN * 2];
__device__ int   g_cnt[NEXP];
__device__ int   g_list[NEXP][S_LEN];
// weights in NATIVE [K, N] layout; QKV/Wo split hi/lo (3-term), MoE single (1-term)
__device__ __align__(256) f16 g_wq_hi[DMODEL * ATTN_D];
__device__ __align__(256) f16 g_wq_lo[DMODEL * ATTN_D];
__device__ __align__(256) f16 g_wk_hi[DMODEL * 512];
__device__ __align__(256) f16 g_wk_lo[DMODEL * 512];
__device__ __align__(256) f16 g_wv_hi[DMODEL * 512];
__device__ __align__(256) f16 g_wv_lo[DMODEL * 512];
__device__ __align__(256) f16 g_wo_hi[ATTN_D * DMODEL];
__device__ __align__(256) f16 g_wo_lo[ATTN_D * DMODEL];
__device__ __align__(256) f16 g_wup[NEXP * DMODEL * FDIM];
__device__ __align__(256) f16 g_wdn[NEXP * FDIM * DMODEL];

// ================= PTX helpers =================
__device__ __forceinline__ uint32_t smem_u32(const void* p) {
    uint32_t a;
    asm("{ .reg .u64 t; cvta.to.shared.u64 t, %1; cvt.u32.u64 %0, t; }" : "=r"(a) : "l"(p));
    return a;
}
__device__ __forceinline__ void ldsm4(uint32_t a, uint32_t r[4]) {
    asm volatile("ldmatrix.sync.aligned.m8n8.x4.shared.b16 {%0,%1,%2,%3}, [%4];"
                 : "=r"(r[0]), "=r"(r[1]), "=r"(r[2]), "=r"(r[3]) : "r"(a));
}
__device__ __forceinline__ void ldsm2(uint32_t a, uint32_t r[2]) {
    asm volatile("ldmatrix.sync.aligned.m8n8.x2.shared.b16 {%0,%1}, [%2];"
                 : "=r"(r[0]), "=r"(r[1]) : "r"(a));
}
__device__ __forceinline__ void ldsm2t(uint32_t a, uint32_t r[2]) {
    asm volatile("ldmatrix.sync.aligned.m8n8.x2.trans.shared.b16 {%0,%1}, [%2];"
                 : "=r"(r[0]), "=r"(r[1]) : "r"(a));
}
__device__ __forceinline__ void mma16816(float c[4], const uint32_t a[4], const uint32_t b[2]) {
    asm volatile(
        "mma.sync.aligned.m16n8k16.row.col.f32.f16.f16.f32 "
        "{%0,%1,%2,%3}, {%4,%5,%6,%7}, {%8,%9}, {%0,%1,%2,%3};"
        : "+f"(c[0]), "+f"(c[1]), "+f"(c[2]), "+f"(c[3])
        : "r"(a[0]), "r"(a[1]), "r"(a[2]), "r"(a[3]), "r"(b[0]), "r"(b[1]));
}
__device__ __forceinline__ uint32_t lds_addr(uint32_t base, int row, int kbyte) {
    int seg = kbyte >> 4;
    return base + row * 128 + (((uint32_t)(seg ^ (row & 7))) << 4);
}
__device__ __forceinline__ int off256(int row, int seg) {
    return row * 256 + ((seg ^ (row & 7)) << 4);
}
__device__ __forceinline__ uint32_t pkhf(float x, float y) {
    __half2 t = __floats2half2_rn(x, y);
    return *reinterpret_cast<uint32_t*>(&t);
}
__device__ __forceinline__ float hhi(float x, float& r) {
    float h = __half2float(__float2half_rn(x));
    r = x - h;
    return h;
}

// ================= weight prep =================
__global__ void split_k(const float4* __restrict__ in, uint2* __restrict__ hi,
                        uint2* __restrict__ lo) {
    size_t i = (size_t)blockIdx.x * 256 + threadIdx.x;
    float4 v = in[i];
    float r0, r1, r2, r3;
    float h0 = hhi(v.x, r0), h1 = hhi(v.y, r1), h2 = hhi(v.z, r2), h3 = hhi(v.w, r3);
    hi[i] = make_uint2(pkhf(h0, h1), pkhf(h2, h3));
    lo[i] = make_uint2(pkhf(r0, r1), pkhf(r2, r3));
}
__global__ void convert_k(const float4* __restrict__ in, uint2* __restrict__ out) {
    size_t i = (size_t)blockIdx.x * 256 + threadIdx.x;
    float4 v = in[i];
    out[i] = make_uint2(pkhf(v.x, v.y), pkhf(v.z, v.w));
}

// ================= rmsnorm1 =================
__global__ void rmsnorm1_split_k(const float* __restrict__ in, const float* __restrict__ sc) {
    int row = blockIdx.x;
    const float* r = in + (size_t)row * DMODEL;
    float ss = 0.f;
    for (int i = threadIdx.x; i < DMODEL; i += 256) { float v = r[i]; ss += v * v; }
    for (int o = 16; o; o >>= 1) ss += __shfl_xor_sync(0xffffffffu, ss, o);
    __shared__ float red[8];
    if ((threadIdx.x & 31) == 0) red[threadIdx.x >> 5] = ss;
    __syncthreads();
    float tot = 0.f;
#pragma unroll
    for (int i = 0; i < 8; i++) tot += red[i];
    float inv = rsqrtf(tot / (float)DMODEL + EPSV);
    for (int i = threadIdx.x; i < DMODEL; i += 256) {
        float w = r[i] * inv * sc[i];
        float rem;
        float h = hhi(w, rem);
        size_t o = (size_t)row * DMODEL + i;
        g_x_hi[o] = __float2half_rn(h);
        g_x_lo[o] = __float2half_rn(rem);
    }
}

// ================= fused rmsnorm2 + router (logits, top-2, expert lists) =================
__global__ void rmsnorm2_router_k(const float* __restrict__ sc, const float* __restrict__ rW,
                                  float* __restrict__ out) {
    __shared__ float xs[DMODEL];
    __shared__ float red[8];
    __shared__ float lg[NEXP];
    int row = blockIdx.x;
    int tid = threadIdx.x;
    const float4* r4 = (const float4*)(g_hidden2 + (size_t)row * DMODEL);
    const float4* s4 = (const float4*)sc;
    float4 v0 = r4[tid], v1 = r4[tid + 256];
    float ss = v0.x * v0.x + v0.y * v0.y + v0.z * v0.z + v0.w * v0.w
             + v1.x * v1.x + v1.y * v1.y + v1.z * v1.z + v1.w * v1.w;
    for (int o = 16; o; o >>= 1) ss += __shfl_xor_sync(0xffffffffu, ss, o);
    if ((tid & 31) == 0) red[tid >> 5] = ss;
    __syncthreads();
    float tot = 0.f;
#pragma unroll
    for (int i = 0; i < 8; i++) tot += red[i];
    float inv = rsqrtf(tot / (float)DMODEL + EPSV);
    float4 c0 = s4[tid], c1 = s4[tid + 256];
    float w0 = v0.x * inv * c0.x, w1 = v0.y * inv * c0.y;
    float w2 = v0.z * inv * c0.z, w3 = v0.w * inv * c0.w;
    float u0 = v1.x * inv * c1.x, u1 = v1.y * inv * c1.y;
    float u2 = v1.z * inv * c1.z, u3 = v1.w * inv * c1.w;
    xs[4 * tid] = w0; xs[4 * tid + 1] = w1; xs[4 * tid + 2] = w2; xs[4 * tid + 3] = w3;
    int t2 = tid + 256;
    xs[4 * t2] = u0; xs[4 * t2 + 1] = u1; xs[4 * t2 + 2] = u2; xs[4 * t2 + 3] = u3;
    size_t ob = (size_t)row * DMODEL;
    *(uint2*)(g_xf_hi + ob + 4 * tid) = make_uint2(pkhf(w0, w1), pkhf(w2, w3));
    *(uint2*)(g_xf_hi + ob + 4 * t2)  = make_uint2(pkhf(u0, u1), pkhf(u2, u3));
    __syncthreads();
    // logits: warp w -> expert w
    int w = tid >> 5, lane = tid & 31;
    float sum = 0.f;
    for (int dd = lane; dd < DMODEL; dd += 32) sum += xs[dd] * rW[dd * NEXP + w];
    for (int o = 16; o; o >>= 1) sum += __shfl_xor_sync(0xffffffffu, sum, o);
    if (lane == 0) lg[w] = sum;
    __syncthreads();
    if (tid == 0) {
        float* lo = out + (size_t)S_LEN * DMODEL + (size_t)row * NEXP;
        float mx = lg[0];
#pragma unroll
        for (int e = 1; e < NEXP; e++) mx = fmaxf(mx, lg[e]);
        float p[NEXP];
#pragma unroll
        for (int e = 0; e < NEXP; e++) { p[e] = expf(lg[e] - mx); lo[e] = lg[e]; }
        int i1 = 0;
#pragma unroll
        for (int e = 1; e < NEXP; e++) if (lg[e] > lg[i1]) i1 = e;
        int i2 = -1;
#pragma unroll
        for (int e = 0; e < NEXP; e++) {
            if (e == i1) continue;
            if (i2 < 0 || lg[e] > lg[i2]) i2 = e;
        }
        float denom = p[i1] + p[i2];
        g_gate[row * 2]     = p[i1] / denom;
        g_gate[row * 2 + 1] = p[i2] / denom;
        int pos = atomicAdd(&g_cnt[i1], 1);
        g_list[i1][pos] = row * 2;
        pos = atomicAdd(&g_cnt[i2], 1);
        g_list[i2][pos] = row * 2 + 1;
    }
}

// ================= HMMA GEMM (B native [K,N] via ldmatrix.trans) =========
// MODE 0: QKV (3-term) — Q/K epilogue fuses qknorm+rope+split; V split direct
// MODE 1: Wo (3-term) + residual
// MODE 2: MoE up (1-term), epi bias+silu -> g_h_hi
// MODE 3: MoE dn (1-term), epi gate*(acc+bias) -> g_moepart
#define STAGE_BYTES 65536
#define DSMEM (3 * STAGE_BYTES + 1024)

template<int MODE>
__global__ __launch_bounds__(256, 1) void mma_gemm_k(const float* __restrict__ arg0,
                                                     const float* __restrict__ arg1) {
    constexpr int K   = (MODE == 1) ? ATTN_D : (MODE == 3) ? FDIM : DMODEL;
    constexpr int NCH = K / 64;
    constexpr bool THREE = (MODE < 2);

    extern __shared__ char dyn[];
    __shared__ int rows_s[128];

    int tid = threadIdx.x, wid = tid >> 5, lane = tid & 31;
    int e = blockIdx.z;
    int m0 = blockIdx.y * 128;
    int n0 = blockIdx.x * 128;

    int cnt = 0;
    if (MODE >= 2) {
        cnt = g_cnt[e];
        if (m0 >= cnt) return;
        if (tid < 128)
            rows_s[tid] = (m0 + tid < cnt) ? g_list[e][m0 + tid] : g_list[e][0];
        __syncthreads();
    }

    const f16 *Ahi, *Alo = nullptr, *Bhi, *Blo = nullptr;
    int ldB, bn;
    if (MODE == 0) {
        Ahi = g_x_hi; Alo = g_x_lo;
        if (n0 < 4096)      { Bhi = g_wq_hi; Blo = g_wq_lo; ldB = 4096; bn = n0; }
        else if (n0 < 4608) { Bhi = g_wk_hi; Blo = g_wk_lo; ldB = 512;  bn = n0 - 4096; }
        else                { Bhi = g_wv_hi; Blo = g_wv_lo; ldB = 512;  bn = n0 - 4608; }
    } else if (MODE == 1) {
        Ahi = g_attn_hi; Alo = g_attn_lo; Bhi = g_wo_hi; Blo = g_wo_lo; ldB = DMODEL; bn = n0;
    } else if (MODE == 2) {
        Ahi = g_xf_hi;
        Bhi = g_wup + (size_t)e * DMODEL * FDIM;
        ldB = FDIM; bn = n0;
    } else {
        Ahi = g_h_hi;
        Bhi = g_wdn + (size_t)e * FDIM * DMODEL;
        ldB = DMODEL; bn = n0;
    }

    uint32_t dyn_u = smem_u32(dyn);
    uint32_t tile0 = (dyn_u + 1023u) & ~1023u;
    char* tile0p = dyn + (tile0 - dyn_u);

    auto load_chunk = [&](int c, int s) {
        char* st = tile0p + s * STAGE_BYTES;
        for (int l = tid; l < 1024; l += 256) {
            int row = l >> 3, seg = l & 7;
            uint32_t off = (uint32_t)(row * 128 + seg * 16);
            uint32_t sw = off ^ ((off >> 3) & 0x70);
            size_t ar;
            if (MODE == 2)      ar = (size_t)(rows_s[row] >> 1) * K;
            else if (MODE == 3) ar = (size_t)rows_s[row] * K;
            else                ar = (size_t)(m0 + row) * K;
            __pipeline_memcpy_async(st + sw, (const char*)(Ahi + ar + (size_t)c * 64) + seg * 16, 16);
            if (THREE)
                __pipeline_memcpy_async(st + 16384 + sw, (const char*)(Alo + ar + (size_t)c * 64) + seg * 16, 16);
        }
        for (int l = tid; l < 1024; l += 256) {
            int row = l >> 4, seg = l & 15;
            int off = off256(row, seg);
            size_t src = (size_t)(c * 64 + row) * ldB + bn + seg * 8;
            __pipeline_memcpy_async(st + 32768 + off, (const char*)(Bhi + src), 16);
            if (THREE)
                __pipeline_memcpy_async(st + 49152 + off, (const char*)(Blo + src), 16);
        }
    };

    int warp_m0 = (wid >> 2) * 64;
    int warp_n0 = (wid & 3) * 32;
    int bseg0 = warp_n0 >> 3;
    int g = lane >> 2, tig = lane & 3;

    float c[4][4][4];
#pragma unroll
    for (int mi = 0; mi < 4; mi++)
#pragma unroll
        for (int nj = 0; nj < 4; nj++)
#pragma unroll
            for (int q = 0; q < 4; q++) c[mi][nj][q] = 0.f;

    load_chunk(0, 0);
    __pipeline_commit();
    load_chunk(1, 1);
    __pipeline_commit();

    for (int i = 0; i < NCH; i++) {
        if (i + 2 < NCH) load_chunk(i + 2, (i + 2) % 3);
        __pipeline_commit();
        __pipeline_wait_prior(2);
        __syncthreads();

        uint32_t su  = tile0 + (uint32_t)(i % 3) * STAGE_BYTES;
        uint32_t aHiB = su, aLoB = su + 16384, bHiB = su + 32768;

#pragma unroll
        for (int kk = 0; kk < 4; kk++) {
            uint32_t Ah[4][4], Al[4][4], Bh[4][2], Bl[4][2];
            int a_row = lane & 15;
            int a_kb  = 32 * kk + ((lane >> 4) << 4);
#pragma unroll
            for (int mi = 0; mi < 4; mi++) {
                int row = warp_m0 + 16 * mi + a_row;
                ldsm4(lds_addr(aHiB, row, a_kb), Ah[mi]);
                if (THREE) ldsm4(lds_addr(aLoB, row, a_kb), Al[mi]);
            }
            int b_row = 16 * kk + (lane & 15);
#pragma unroll
            for (int nj = 0; nj < 4; nj++) {
                uint32_t baddr = bHiB + off256(b_row, bseg0 + nj);
                ldsm2t(baddr, Bh[nj]);
                if (THREE) ldsm2t(baddr + 16384, Bl[nj]);
            }
#pragma unroll
            for (int mi = 0; mi < 4; mi++)
#pragma unroll
                for (int nj = 0; nj < 4; nj++) {
                    mma16816(c[mi][nj], Ah[mi], Bh[nj]);
                    if (THREE) {
                        mma16816(c[mi][nj], Al[mi], Bh[nj]);
                        mma16816(c[mi][nj], Ah[mi], Bl[nj]);
                    }
                }
        }
        __syncthreads();
    }

    // ---------- MODE 0 Q/K: fused qknorm + rope + fp16 split ----------
    if (MODE == 0 && n0 < 4608) {
        float* S = (float*)tile0p;   // 128 x 132 fp32
#pragma unroll
        for (int mi = 0; mi < 4; mi++)
#pragma unroll
            for (int hh = 0; hh < 2; hh++) {
                int rl = warp_m0 + 16 * mi + 8 * hh + g;
#pragma unroll
                for (int nj = 0; nj < 4; nj++) {
                    int colL = warp_n0 + 8 * nj + 2 * tig;
                    S[rl * 132 + colL]     = c[mi][nj][2 * hh];
                    S[rl * 132 + colL + 1] = c[mi][nj][2 * hh + 1];
                }
            }
        __syncthreads();
        int isK = (n0 >= 4096);
        int head = (isK ? (n0 - 4096) : n0) >> 7;
        const float* sc = isK ? arg1 : arg0;
        f16* dsth = isK ? g_kh : g_qh;
        f16* dstl = isK ? g_kl : g_ql;
        for (int rr = 0; rr < 16; rr++) {
            int row = wid * 16 + rr;
            const float* Sr = S + row * 132;
            float v[4];
            float ss = 0.f;
#pragma unroll
            for (int k = 0; k < 4; k++) { v[k] = Sr[lane * 4 + k]; ss += v[k] * v[k]; }
#pragma unroll
            for (int o = 16; o; o >>= 1) ss += __shfl_xor_sync(0xffffffffu, ss, o);
            float inv = rsqrtf(ss * (1.0f / 128.0f) + EPSV);
            int sg = m0 + row;
            uint32_t hiW[2], loW[2];
#pragma unroll
            for (int kp = 0; kp < 2; kp++) {
                float outv[2], remv[2];
#pragma unroll
                for (int k2 = 0; k2 < 2; k2++) {
                    int d = lane * 4 + kp * 2 + k2;
                    float n = v[kp * 2 + k2] * inv * sc[d];
                    int j = d & 63;
                    float invf = expf(-0.21586735246819178f * (float)j);
                    float ang = (float)sg * invf;
                    float si, co;
                    sincosf(ang, &si, &co);
                    int od = (d < 64) ? d + 64 : d - 64;
                    float no = Sr[od] * inv * sc[od];
                    float rot = (d < 64) ? -no : no;
                    float val = n * co + rot * si;
                    if (!isK) val *= 0.08838834764831845f;   // fold 1/sqrt(128) into Q
                    outv[k2] = hhi(val, remv[k2]);
                }
                hiW[kp] = pkhf(outv[0], outv[1]);
                loW[kp] = pkhf(remv[0], remv[1]);
            }
            size_t o = isK ? (((size_t)head * S_LEN + sg) * HDIM + lane * 4)
                           : (((size_t)sg * NHQ + head) * HDIM + lane * 4);
            *(uint2*)(dsth + o) = make_uint2(hiW[0], hiW[1]);
            *(uint2*)(dstl + o) = make_uint2(loW[0], loW[1]);
        }
        return;
    }

    // ---------------- generic epilogue ----------------
#pragma unroll
    for (int mi = 0; mi < 4; mi++) {
#pragma unroll
        for (int hh = 0; hh < 2; hh++) {
            int rl = warp_m0 + 16 * mi + 8 * hh + g;
            int grow = m0 + rl;
            bool valid = true;
            int slot = 0;
            if (MODE >= 2) { valid = grow < cnt; slot = rows_s[rl]; }
#pragma unroll
            for (int nj = 0; nj < 4; nj++) {
                int col = n0 + warp_n0 + 8 * nj + 2 * tig;
                float v0 = c[mi][nj][2 * hh];
                float v1 = c[mi][nj][2 * hh + 1];
                if (MODE == 0) {
                    // V columns only (n0 >= 4608)
                    int cc = col - 4608;
                    int kvh = cc >> 7, d = cc & 127;
                    size_t o = ((size_t)kvh * S_LEN + grow) * HDIM + d;
                    float r0, r1;
                    float h0 = hhi(v0, r0), h1 = hhi(v1, r1);
                    *(uint32_t*)(g_vh + o) = pkhf(h0, h1);
                    *(uint32_t*)(g_vl + o) = pkhf(r0, r1);
                } else if (MODE == 1) {
                    size_t base = (size_t)grow * DMODEL + col;
                    g_hidden2[base]     = v0 + arg0[base];
                    g_hidden2[base + 1] = v1 + arg0[base + 1];
                } else if (MODE == 2) {
                    if (valid) {
                        const float* bia = arg1 + e * FDIM;
                        float va = v0 + bia[col], vb = v1 + bia[col + 1];
                        float sa = va / (1.0f + expf(-va));
                        float sb = vb / (1.0f + expf(-vb));
                        *(uint32_t*)(g_h_hi + (size_t)slot * FDIM + col) = pkhf(sa, sb);
                    }
                } else {
                    if (valid) {
                        const float* bia = arg1 + e * DMODEL;
                        float gt = g_gate[slot];
                        *(float2*)(g_moepart + (size_t)slot * DMODEL + col) =
                            make_float2(gt * (v0 + bia[col]), gt * (v1 + bia[col + 1]));
                    }
                }
            }
        }
    }
}

// ================= HMMA flash attention (fp16, 3-term) =================
#define ATT_SMEM (65536 + 2 * 65536)
__global__ __launch_bounds__(256, 1) void attn_mma_k() {
    extern __shared__ char sm[];
    uint32_t sb = smem_u32(sm);
    int qi = gridDim.x - 1 - blockIdx.x;   // heaviest tiles first
    int h = blockIdx.y;
    int q0 = qi * 128, kvh = h >> 3;
    int nkv = 2 * (qi + 1);
    int tid = threadIdx.x, wid = tid >> 5, lane = tid & 31;
    int g = lane >> 2, tig = lane & 3;
    int wq0 = wid * 16;

    for (int l = tid; l < 2048; l += 256) {
        int row = l >> 4, seg = l & 15;
        int off = off256(row, seg);
        size_t src = ((size_t)(q0 + row) * NHQ + h) * HDIM + seg * 8;
        __pipeline_memcpy_async(sm + off,         g_qh + src, 16);
        __pipeline_memcpy_async(sm + 32768 + off, g_ql + src, 16);
    }

    auto fill_kv = [&](int t, int st) {
        char* base = sm + 65536 + st * 65536;
        int kv0 = t * 64;
        for (int l = tid; l < 1024; l += 256) {
            int row = l >> 4, seg = l & 15;
            int off = off256(row, seg);
            size_t src = ((size_t)kvh * S_LEN + kv0 + row) * HDIM + seg * 8;
            __pipeline_memcpy_async(base + off,         g_kh + src, 16);
            __pipeline_memcpy_async(base + 16384 + off, g_kl + src, 16);
            __pipeline_memcpy_async(base + 32768 + off, g_vh + src, 16);
            __pipeline_memcpy_async(base + 49152 + off, g_vl + src, 16);
        }
    };

    float o[16][4];
#pragma unroll
    for (int dj = 0; dj < 16; dj++)
#pragma unroll
        for (int q = 0; q < 4; q++) o[dj][q] = 0.f;
    float m0 = -3e38f, m1 = -3e38f, l0 = 0.f, l1 = 0.f;

    fill_kv(0, 0);
    __pipeline_commit();

    for (int t = 0; t < nkv; t++) {
        if (t + 1 < nkv) fill_kv(t + 1, (t + 1) & 1);
        __pipeline_commit();
        __pipeline_wait_prior(1);
        __syncthreads();

        uint32_t st  = sb + 65536 + (uint32_t)(t & 1) * 65536;
        int k0 = t * 64;

        float s[8][4];
#pragma unroll
        for (int nj = 0; nj < 8; nj++)
#pragma unroll
            for (int q = 0; q < 4; q++) s[nj][q] = 0.f;

#pragma unroll
        for (int kk = 0; kk < 8; kk++) {
            uint32_t aqh[4], aql[4];
            int a_row = wq0 + (lane & 15);
            int a_sb  = kk * 2 + ((lane >> 4) & 1);
            uint32_t aaddr = sb + off256(a_row, a_sb);
            ldsm4(aaddr, aqh);
            ldsm4(aaddr + 32768, aql);
#pragma unroll
            for (int nj = 0; nj < 8; nj++) {
                uint32_t bkh[2], bkl[2];
                int b_row = nj * 8 + (lane & 7);
                int b_sb  = kk * 2 + ((lane >> 3) & 1);
                uint32_t baddr = st + off256(b_row, b_sb);
                ldsm2(baddr, bkh);
                ldsm2(baddr + 16384, bkl);
                mma16816(s[nj], aqh, bkh);
                mma16816(s[nj], aql, bkh);
                mma16816(s[nj], aqh, bkl);
            }
        }

        if (k0 + 63 > q0 + wq0) {
            int r0 = q0 + wq0 + g, r1 = r0 + 8;
#pragma unroll
            for (int nj = 0; nj < 8; nj++) {
                int col = k0 + nj * 8 + 2 * tig;
                if (col > r0)     s[nj][0] = -1e9f;
                if (col + 1 > r0) s[nj][1] = -1e9f;
                if (col > r1)     s[nj][2] = -1e9f;
                if (col + 1 > r1) s[nj][3] = -1e9f;
            }
        }

        float mx0 = m0, mx1 = m1;
#pragma unroll
        for (int nj = 0; nj < 8; nj++) {
            mx0 = fmaxf(mx0, fmaxf(s[nj][0], s[nj][1]));
            mx1 = fmaxf(mx1, fmaxf(s[nj][2], s[nj][3]));
        }
        mx0 = fmaxf(mx0, __shfl_xor_sync(0xffffffffu, mx0, 1));
        mx0 = fmaxf(mx0, __shfl_xor_sync(0xffffffffu, mx0, 2));
        mx1 = fmaxf(mx1, __shfl_xor_sync(0xffffffffu, mx1, 1));
        mx1 = fmaxf(mx1, __shfl_xor_sync(0xffffffffu, mx1, 2));
        float a0 = __expf(m0 - mx0), a1 = __expf(m1 - mx1);
        m0 = mx0; m1 = mx1;
        l0 *= a0; l1 *= a1;
#pragma unroll
        for (int dj = 0; dj < 16; dj++) {
            o[dj][0] *= a0; o[dj][1] *= a0;
            o[dj][2] *= a1; o[dj][3] *= a1;
        }

        uint32_t phi[8][2], plo[8][2];
#pragma unroll
        for (int nj = 0; nj < 8; nj++) {
            float p00 = __expf(s[nj][0] - mx0), p01 = __expf(s[nj][1] - mx0);
            float p10 = __expf(s[nj][2] - mx1), p11 = __expf(s[nj][3] - mx1);
            l0 += p00 + p01; l1 += p10 + p11;
            float r00, r01, r10, r11;
            float h00 = hhi(p00, r00), h01 = hhi(p01, r01);
            float h10 = hhi(p10, r10), h11 = hhi(p11, r11);
            phi[nj][0] = pkhf(h00, h01); phi[nj][1] = pkhf(h10, h11);
            plo[nj][0] = pkhf(r00, r01); plo[nj][1] = pkhf(r10, r11);
        }

        uint32_t vh_b = st + 32768;
#pragma unroll
        for (int kc = 0; kc < 4; kc++) {
            uint32_t aph[4] = { phi[2 * kc][0], phi[2 * kc][1], phi[2 * kc + 1][0], phi[2 * kc + 1][1] };
            uint32_t apl[4] = { plo[2 * kc][0], plo[2 * kc][1], plo[2 * kc + 1][0], plo[2 * kc + 1][1] };
#pragma unroll
            for (int dj = 0; dj < 16; dj++) {
                uint32_t bvh[2], bvl[2];
                int v_row = kc * 16 + (lane & 15);
                uint32_t vaddr = vh_b + off256(v_row, dj);
                ldsm2t(vaddr, bvh);
                ldsm2t(vaddr + 16384, bvl);
                mma16816(o[dj], aph, bvh);
                mma16816(o[dj], apl, bvh);
                mma16816(o[dj], aph, bvl);
            }
        }
        __syncthreads();
    }

    l0 += __shfl_xor_sync(0xffffffffu, l0, 1);
    l0 += __shfl_xor_sync(0xffffffffu, l0, 2);
    l1 += __shfl_xor_sync(0xffffffffu, l1, 1);
    l1 += __shfl_xor_sync(0xffffffffu, l1, 2);
    float i0 = 1.0f / l0, i1 = 1.0f / l1;
    int r0 = q0 + wq0 + g, r1 = r0 + 8;
#pragma unroll
    for (int dj = 0; dj < 16; dj++) {
        int cc = dj * 8 + 2 * tig;
        size_t o0 = (size_t)r0 * ATTN_D + h * HDIM + cc;
        size_t o1 = (size_t)r1 * ATTN_D + h * HDIM + cc;
        float ra, rb;
        float v0 = o[dj][0] * i0, v1 = o[dj][1] * i0;
        float h0 = hhi(v0, ra), h1 = hhi(v1, rb);
        *(uint32_t*)(g_attn_hi + o0) = pkhf(h0, h1);
        *(uint32_t*)(g_attn_lo + o0) = pkhf(ra, rb);
        float w0 = o[dj][2] * i1, w1 = o[dj][3] * i1;
        h0 = hhi(w0, ra); h1 = hhi(w1, rb);
        *(uint32_t*)(g_attn_hi + o1) = pkhf(h0, h1);
        *(uint32_t*)(g_attn_lo + o1) = pkhf(ra, rb);
    }
}

// ================= init / final =================
__global__ void init_k(float* __restrict__ out) {
    if (threadIdx.x < NEXP) g_cnt[threadIdx.x] = 0;
    if (threadIdx.x == 0) out[(size_t)S_LEN * DMODEL + S_LEN * NEXP] = 1.0f;
}

__global__ void final_k(float* __restrict__ out) {
    int i = blockIdx.x * 256 + threadIdx.x;   // float4 index
    int t = i / (DMODEL / 4);
    int d = i - t * (DMODEL / 4);
    const float4* h2 = (const float4*)g_hidden2;
    const float4* mp = (const float4*)g_moepart;
    float4 a = h2[i];
    float4 b = mp[(size_t)(2 * t) * (DMODEL / 4) + d];
    float4 c = mp[(size_t)(2 * t + 1) * (DMODEL / 4) + d];
    float4 w;
    w.x = a.x + b.x + c.x; w.y = a.y + b.y + c.y;
    w.z = a.z + b.z + c.z; w.w = a.w + b.w + c.w;
    ((float4*)out)[i] = w;
}

// ================= launch =================
extern "C" void kernel_launch(void* const* d_in, const int* in_sizes, int n_in,
                              void* d_out, int out_size) {
    const float* hs  = (const float*)d_in[0];
    const float* ln1 = (const float*)d_in[1];
    const float* ln2 = (const float*)d_in[2];
    const float* Wq  = (const float*)d_in[3];
    const float* Wk  = (const float*)d_in[4];
    const float* Wv  = (const float*)d_in[5];
    const float* Wo  = (const float*)d_in[6];
    const float* qns = (const float*)d_in[7];
    const float* kns = (const float*)d_in[8];
    const float* rW  = (const float*)d_in[9];
    const float* upW = (const float*)d_in[10];
    const float* upb = (const float*)d_in[11];
    const float* dnW = (const float*)d_in[12];
    const float* dnb = (const float*)d_in[13];
    float* out = (float*)d_out;

    void *wq_hi, *wq_lo, *wk_hi, *wk_lo, *wv_hi, *wv_lo, *wo_hi, *wo_lo, *wup, *wdn;
    cudaGetSymbolAddress(&wq_hi, g_wq_hi);  cudaGetSymbolAddress(&wq_lo, g_wq_lo);
    cudaGetSymbolAddress(&wk_hi, g_wk_hi);  cudaGetSymbolAddress(&wk_lo, g_wk_lo);
    cudaGetSymbolAddress(&wv_hi, g_wv_hi);  cudaGetSymbolAddress(&wv_lo, g_wv_lo);
    cudaGetSymbolAddress(&wo_hi, g_wo_hi);  cudaGetSymbolAddress(&wo_lo, g_wo_lo);
    cudaGetSymbolAddress(&wup, g_wup);      cudaGetSymbolAddress(&wdn, g_wdn);

    cudaFuncSetAttribute(attn_mma_k, cudaFuncAttributeMaxDynamicSharedMemorySize, ATT_SMEM);
    cudaFuncSetAttribute(mma_gemm_k<0>, cudaFuncAttributeMaxDynamicSharedMemorySize, DSMEM);
    cudaFuncSetAttribute(mma_gemm_k<1>, cudaFuncAttributeMaxDynamicSharedMemorySize, DSMEM);
    cudaFuncSetAttribute(mma_gemm_k<2>, cudaFuncAttributeMaxDynamicSharedMemorySize, DSMEM);
    cudaFuncSetAttribute(mma_gemm_k<3>, cudaFuncAttributeMaxDynamicSharedMemorySize, DSMEM);

    // weight prep: split for 3-term (QKV/Wo), plain convert for 1-term (MoE)
    split_k<<<(DMODEL * ATTN_D) / 1024, 256>>>((const float4*)Wq, (uint2*)wq_hi, (uint2*)wq_lo);
    split_k<<<(DMODEL * 512) / 1024, 256>>>((const float4*)Wk, (uint2*)wk_hi, (uint2*)wk_lo);
    split_k<<<(DMODEL * 512) / 1024, 256>>>((const float4*)Wv, (uint2*)wv_hi, (uint2*)wv_lo);
    split_k<<<(ATTN_D * DMODEL) / 1024, 256>>>((const float4*)Wo, (uint2*)wo_hi, (uint2*)wo_lo);
    convert_k<<<(NEXP * DMODEL * FDIM) / 1024, 256>>>((const float4*)upW, (uint2*)wup);
    convert_k<<<(NEXP * FDIM * DMODEL) / 1024, 256>>>((const float4*)dnW, (uint2*)wdn);

    // 1. rmsnorm1 -> fp16 hi/lo
    rmsnorm1_split_k<<<S_LEN, 256>>>(hs, ln1);
    // 2. fused QKV projection; Q/K epilogue does qknorm+rope+split, V split direct
    mma_gemm_k<0><<<dim3(QKV_N / 128, S_LEN / 128), 256, DSMEM>>>(qns, kns);
    // 3. HMMA flash attention -> g_attn hi/lo
    attn_mma_k<<<dim3(S_LEN / 128, NHQ), 256, ATT_SMEM>>>();
    // 4. output projection + residual
    mma_gemm_k<1><<<dim3(DMODEL / 128, S_LEN / 128), 256, DSMEM>>>(hs, nullptr);
    // 5. fused rmsnorm2 + router (init first: zero counts, write aux)
    init_k<<<1, 32>>>(out);
    rmsnorm2_router_k<<<S_LEN, 256>>>(ln2, rW, out);
    // 6. MoE (gathered rows, 1-term fp16)
    mma_gemm_k<2><<<dim3(FDIM / 128, 16, NEXP), 256, DSMEM>>>(nullptr, upb);
    mma_gemm_k<3><<<dim3(DMODEL / 128, 16, NEXP), 256, DSMEM>>>(nullptr, dnb);
    // 7. final residual + MoE sum
    final_k<<<(S_LEN * DMODEL / 4) / 256, 256>>>(out);
}

// round 13
// speedup vs baseline: 6.2209x; 1.0238x over previous
#include <cuda_runtime.h>
#include <cuda_fp16.h>
#include <cuda_pipeline.h>
#include <math.h>
#include <stdint.h>

#define S_LEN 2048
#define DMODEL 2048
#define QKV_N 5120
#define NHQ 32
#define NHKV 4
#define HDIM 128
#define NEXP 8
#define FDIM 768
#define EPSV 1e-6f
#define ATTN_D (NHQ * HDIM)   // 4096

typedef __half f16;

// ================= scratch (device globals; no allocations allowed) =================
__device__ __align__(256) f16   g_x_hi[S_LEN * DMODEL];
__device__ __align__(256) f16   g_x_lo[S_LEN * DMODEL];
__device__ __align__(256) f16   g_qh[S_LEN * NHQ * HDIM];
__device__ __align__(256) f16   g_ql[S_LEN * NHQ * HDIM];
__device__ __align__(256) f16   g_kh[NHKV * S_LEN * HDIM];
__device__ __align__(256) f16   g_kl[NHKV * S_LEN * HDIM];
__device__ __align__(256) f16   g_vh[NHKV * S_LEN * HDIM];
__device__ __align__(256) f16   g_vl[NHKV * S_LEN * HDIM];
__device__ __align__(256) f16   g_attn_hi[S_LEN * ATTN_D];
__device__ __align__(256) f16   g_attn_lo[S_LEN * ATTN_D];
__device__ __align__(256) float g_hidden2[S_LEN * DMODEL];
__device__ __align__(256) f16   g_xf_hi[S_LEN * DMODEL];
__device__ __align__(256) f16   g_h_hi[S_LEN * 2 * FDIM];
__device__ __align__(256) float g_moepart[S_LEN * 2 * DMODEL];
__device__ float g_gate[S_LEN * 2];
__device__ int   g_cnt[NEXP];
__device__ int   g_list[NEXP][S_LEN];
// weights in NATIVE [K, N] layout; QKV/Wo split hi/lo (3-term), MoE single (1-term)
__device__ __align__(256) f16 g_wq_hi[DMODEL * ATTN_D];
__device__ __align__(256) f16 g_wq_lo[DMODEL * ATTN_D];
__device__ __align__(256) f16 g_wk_hi[DMODEL * 512];
__device__ __align__(256) f16 g_wk_lo[DMODEL * 512];
__device__ __align__(256) f16 g_wv_hi[DMODEL * 512];
__device__ __align__(256) f16 g_wv_lo[DMODEL * 512];
__device__ __align__(256) f16 g_wo_hi[ATTN_D * DMODEL];
__device__ __align__(256) f16 g_wo_lo[ATTN_D * DMODEL];
__device__ __align__(256) f16 g_wup[NEXP * DMODEL * FDIM];
__device__ __align__(256) f16 g_wdn[NEXP * FDIM * DMODEL];

// ================= PTX helpers =================
__device__ __forceinline__ uint32_t smem_u32(const void* p) {
    uint32_t a;
    asm("{ .reg .u64 t; cvta.to.shared.u64 t, %1; cvt.u32.u64 %0, t; }" : "=r"(a) : "l"(p));
    return a;
}
__device__ __forceinline__ void ldsm4(uint32_t a, uint32_t r[4]) {
    asm volatile("ldmatrix.sync.aligned.m8n8.x4.shared.b16 {%0,%1,%2,%3}, [%4];"
                 : "=r"(r[0]), "=r"(r[1]), "=r"(r[2]), "=r"(r[3]) : "r"(a));
}
__device__ __forceinline__ void ldsm4t(uint32_t a, uint32_t r[4]) {
    asm volatile("ldmatrix.sync.aligned.m8n8.x4.trans.shared.b16 {%0,%1,%2,%3}, [%4];"
                 : "=r"(r[0]), "=r"(r[1]), "=r"(r[2]), "=r"(r[3]) : "r"(a));
}
__device__ __forceinline__ void mma16816(float c[4], const uint32_t a[4], const uint32_t b[2]) {
    asm volatile(
        "mma.sync.aligned.m16n8k16.row.col.f32.f16.f16.f32 "
        "{%0,%1,%2,%3}, {%4,%5,%6,%7}, {%8,%9}, {%0,%1,%2,%3};"
        : "+f"(c[0]), "+f"(c[1]), "+f"(c[2]), "+f"(c[3])
        : "r"(a[0]), "r"(a[1]), "r"(a[2]), "r"(a[3]), "r"(b[0]), "r"(b[1]));
}
__device__ __forceinline__ uint32_t lds_addr(uint32_t base, int row, int kbyte) {
    int seg = kbyte >> 4;
    return base + row * 128 + (((uint32_t)(seg ^ (row & 7))) << 4);
}
__device__ __forceinline__ int off256(int row, int seg) {
    return row * 256 + ((seg ^ (row & 7)) << 4);
}
__device__ __forceinline__ uint32_t pkhf(float x, float y) {
    __half2 t = __floats2half2_rn(x, y);
    return *reinterpret_cast<uint32_t*>(&t);
}
__device__ __forceinline__ float hhi(float x, float& r) {
    float h = __half2float(__float2half_rn(x));
    r = x - h;
    return h;
}

// ================= weight prep (2 float4 per thread for MLP) =================
__global__ void split_k(const float4* __restrict__ in, uint2* __restrict__ hi,
                        uint2* __restrict__ lo) {
    size_t base = (size_t)blockIdx.x * 512 + threadIdx.x;
#pragma unroll
    for (int u = 0; u < 2; u++) {
        size_t i = base + u * 256;
        float4 v = in[i];
        float r0, r1, r2, r3;
        float h0 = hhi(v.x, r0), h1 = hhi(v.y, r1), h2 = hhi(v.z, r2), h3 = hhi(v.w, r3);
        hi[i] = make_uint2(pkhf(h0, h1), pkhf(h2, h3));
        lo[i] = make_uint2(pkhf(r0, r1), pkhf(r2, r3));
    }
}
__global__ void convert_k(const float4* __restrict__ in, uint2* __restrict__ out) {
    size_t base = (size_t)blockIdx.x * 512 + threadIdx.x;
#pragma unroll
    for (int u = 0; u < 2; u++) {
        size_t i = base + u * 256;
        float4 v = in[i];
        out[i] = make_uint2(pkhf(v.x, v.y), pkhf(v.z, v.w));
    }
}

// ================= rmsnorm1 =================
__global__ void rmsnorm1_split_k(const float* __restrict__ in, const float* __restrict__ sc) {
    int row = blockIdx.x;
    const float* r = in + (size_t)row * DMODEL;
    float ss = 0.f;
    for (int i = threadIdx.x; i < DMODEL; i += 256) { float v = r[i]; ss += v * v; }
    for (int o = 16; o; o >>= 1) ss += __shfl_xor_sync(0xffffffffu, ss, o);
    __shared__ float red[8];
    if ((threadIdx.x & 31) == 0) red[threadIdx.x >> 5] = ss;
    __syncthreads();
    float tot = 0.f;
#pragma unroll
    for (int i = 0; i < 8; i++) tot += red[i];
    float inv = rsqrtf(tot / (float)DMODEL + EPSV);
    for (int i = threadIdx.x; i < DMODEL; i += 256) {
        float w = r[i] * inv * sc[i];
        float rem;
        float h = hhi(w, rem);
        size_t o = (size_t)row * DMODEL + i;
        g_x_hi[o] = __float2half_rn(h);
        g_x_lo[o] = __float2half_rn(rem);
    }
}

// ================= fused rmsnorm2 + router =================
__global__ void rmsnorm2_router_k(const float* __restrict__ sc, const float* __restrict__ rW,
                                  float* __restrict__ out) {
    __shared__ float xs[DMODEL];
    __shared__ float red[8];
    __shared__ float lg[NEXP];
    int row = blockIdx.x;
    int tid = threadIdx.x;
    const float4* r4 = (const float4*)(g_hidden2 + (size_t)row * DMODEL);
    const float4* s4 = (const float4*)sc;
    float4 v0 = r4[tid], v1 = r4[tid + 256];
    float ss = v0.x * v0.x + v0.y * v0.y + v0.z * v0.z + v0.w * v0.w
             + v1.x * v1.x + v1.y * v1.y + v1.z * v1.z + v1.w * v1.w;
    for (int o = 16; o; o >>= 1) ss += __shfl_xor_sync(0xffffffffu, ss, o);
    if ((tid & 31) == 0) red[tid >> 5] = ss;
    __syncthreads();
    float tot = 0.f;
#pragma unroll
    for (int i = 0; i < 8; i++) tot += red[i];
    float inv = rsqrtf(tot / (float)DMODEL + EPSV);
    float4 c0 = s4[tid], c1 = s4[tid + 256];
    float w0 = v0.x * inv * c0.x, w1 = v0.y * inv * c0.y;
    float w2 = v0.z * inv * c0.z, w3 = v0.w * inv * c0.w;
    float u0 = v1.x * inv * c1.x, u1 = v1.y * inv * c1.y;
    float u2 = v1.z * inv * c1.z, u3 = v1.w * inv * c1.w;
    xs[4 * tid] = w0; xs[4 * tid + 1] = w1; xs[4 * tid + 2] = w2; xs[4 * tid + 3] = w3;
    int t2 = tid + 256;
    xs[4 * t2] = u0; xs[4 * t2 + 1] = u1; xs[4 * t2 + 2] = u2; xs[4 * t2 + 3] = u3;
    size_t ob = (size_t)row * DMODEL;
    *(uint2*)(g_xf_hi + ob + 4 * tid) = make_uint2(pkhf(w0, w1), pkhf(w2, w3));
    *(uint2*)(g_xf_hi + ob + 4 * t2)  = make_uint2(pkhf(u0, u1), pkhf(u2, u3));
    __syncthreads();
    int w = tid >> 5, lane = tid & 31;
    float sum = 0.f;
    for (int dd = lane; dd < DMODEL; dd += 32) sum += xs[dd] * rW[dd * NEXP + w];
    for (int o = 16; o; o >>= 1) sum += __shfl_xor_sync(0xffffffffu, sum, o);
    if (lane == 0) lg[w] = sum;
    __syncthreads();
    if (tid == 0) {
        float* lo = out + (size_t)S_LEN * DMODEL + (size_t)row * NEXP;
        float mx = lg[0];
#pragma unroll
        for (int e = 1; e < NEXP; e++) mx = fmaxf(mx, lg[e]);
        float p[NEXP];
#pragma unroll
        for (int e = 0; e < NEXP; e++) { p[e] = expf(lg[e] - mx); lo[e] = lg[e]; }
        int i1 = 0;
#pragma unroll
        for (int e = 1; e < NEXP; e++) if (lg[e] > lg[i1]) i1 = e;
        int i2 = -1;
#pragma unroll
        for (int e = 0; e < NEXP; e++) {
            if (e == i1) continue;
            if (i2 < 0 || lg[e] > lg[i2]) i2 = e;
        }
        float denom = p[i1] + p[i2];
        g_gate[row * 2]     = p[i1] / denom;
        g_gate[row * 2 + 1] = p[i2] / denom;
        int pos = atomicAdd(&g_cnt[i1], 1);
        g_list[i1][pos] = row * 2;
        pos = atomicAdd(&g_cnt[i2], 1);
        g_list[i2][pos] = row * 2 + 1;
    }
}

// ================= HMMA GEMM (B native [K,N] via paired ldmatrix.x4.trans) =========
#define STAGE_BYTES 65536
#define DSMEM (3 * STAGE_BYTES + 1024)

template<int MODE>
__global__ __launch_bounds__(256, 1) void mma_gemm_k(const float* __restrict__ arg0,
                                                     const float* __restrict__ arg1) {
    constexpr int K   = (MODE == 1) ? ATTN_D : (MODE == 3) ? FDIM : DMODEL;
    constexpr int NCH = K / 64;
    constexpr bool THREE = (MODE < 2);

    extern __shared__ char dyn[];
    __shared__ int rows_s[128];

    int tid = threadIdx.x, wid = tid >> 5, lane = tid & 31;
    int e = blockIdx.z;
    int m0 = blockIdx.y * 128;
    int n0 = blockIdx.x * 128;

    int cnt = 0;
    if (MODE >= 2) {
        cnt = g_cnt[e];
        if (m0 >= cnt) return;
        if (tid < 128)
            rows_s[tid] = (m0 + tid < cnt) ? g_list[e][m0 + tid] : g_list[e][0];
        __syncthreads();
    }

    const f16 *Ahi, *Alo = nullptr, *Bhi, *Blo = nullptr;
    int ldB, bn;
    if (MODE == 0) {
        Ahi = g_x_hi; Alo = g_x_lo;
        if (n0 < 4096)      { Bhi = g_wq_hi; Blo = g_wq_lo; ldB = 4096; bn = n0; }
        else if (n0 < 4608) { Bhi = g_wk_hi; Blo = g_wk_lo; ldB = 512;  bn = n0 - 4096; }
        else                { Bhi = g_wv_hi; Blo = g_wv_lo; ldB = 512;  bn = n0 - 4608; }
    } else if (MODE == 1) {
        Ahi = g_attn_hi; Alo = g_attn_lo; Bhi = g_wo_hi; Blo = g_wo_lo; ldB = DMODEL; bn = n0;
    } else if (MODE == 2) {
        Ahi = g_xf_hi;
        Bhi = g_wup + (size_t)e * DMODEL * FDIM;
        ldB = FDIM; bn = n0;
    } else {
        Ahi = g_h_hi;
        Bhi = g_wdn + (size_t)e * FDIM * DMODEL;
        ldB = DMODEL; bn = n0;
    }

    uint32_t dyn_u = smem_u32(dyn);
    uint32_t tile0 = (dyn_u + 1023u) & ~1023u;
    char* tile0p = dyn + (tile0 - dyn_u);

    auto load_chunk = [&](int c, int s) {
        char* st = tile0p + s * STAGE_BYTES;
        for (int l = tid; l < 1024; l += 256) {
            int row = l >> 3, seg = l & 7;
            uint32_t off = (uint32_t)(row * 128 + seg * 16);
            uint32_t sw = off ^ ((off >> 3) & 0x70);
            size_t ar;
            if (MODE == 2)      ar = (size_t)(rows_s[row] >> 1) * K;
            else if (MODE == 3) ar = (size_t)rows_s[row] * K;
            else                ar = (size_t)(m0 + row) * K;
            __pipeline_memcpy_async(st + sw, (const char*)(Ahi + ar + (size_t)c * 64) + seg * 16, 16);
            if (THREE)
                __pipeline_memcpy_async(st + 16384 + sw, (const char*)(Alo + ar + (size_t)c * 64) + seg * 16, 16);
        }
        for (int l = tid; l < 1024; l += 256) {
            int row = l >> 4, seg = l & 15;
            int off = off256(row, seg);
            size_t src = (size_t)(c * 64 + row) * ldB + bn + seg * 8;
            __pipeline_memcpy_async(st + 32768 + off, (const char*)(Bhi + src), 16);
            if (THREE)
                __pipeline_memcpy_async(st + 49152 + off, (const char*)(Blo + src), 16);
        }
    };

    int warp_m0 = (wid >> 2) * 64;
    int warp_n0 = (wid & 3) * 32;
    int bseg0 = warp_n0 >> 3;
    int g = lane >> 2, tig = lane & 3;

    float c[4][4][4];
#pragma unroll
    for (int mi = 0; mi < 4; mi++)
#pragma unroll
        for (int nj = 0; nj < 4; nj++)
#pragma unroll
            for (int q = 0; q < 4; q++) c[mi][nj][q] = 0.f;

    load_chunk(0, 0);
    __pipeline_commit();
    load_chunk(1, 1);
    __pipeline_commit();

    for (int i = 0; i < NCH; i++) {
        __pipeline_wait_prior(1);
        __syncthreads();
        if (i + 2 < NCH) load_chunk(i + 2, (i + 2) % 3);
        __pipeline_commit();

        uint32_t su  = tile0 + (uint32_t)(i % 3) * STAGE_BYTES;
        uint32_t aHiB = su, aLoB = su + 16384, bHiB = su + 32768;

#pragma unroll
        for (int kk = 0; kk < 4; kk++) {
            uint32_t Ah[4][4], Al[4][4], Bh[4][2], Bl[4][2];
            int a_row = lane & 15;
            int a_kb  = 32 * kk + ((lane >> 4) << 4);
#pragma unroll
            for (int mi = 0; mi < 4; mi++) {
                int row = warp_m0 + 16 * mi + a_row;
                ldsm4(lds_addr(aHiB, row, a_kb), Ah[mi]);
                if (THREE) ldsm4(lds_addr(aLoB, row, a_kb), Al[mi]);
            }
            // B fragments: x4.trans pairs — lanes 16-31 fetch nj+1's segment
            int b_row = 16 * kk + (lane & 15);
#pragma unroll
            for (int njp = 0; njp < 2; njp++) {
                int nj = njp * 2;
                uint32_t r[4];
                uint32_t baddr = bHiB + off256(b_row, bseg0 + nj + (lane >> 4));
                ldsm4t(baddr, r);
                Bh[nj][0] = r[0]; Bh[nj][1] = r[1];
                Bh[nj + 1][0] = r[2]; Bh[nj + 1][1] = r[3];
                if (THREE) {
                    ldsm4t(baddr + 16384, r);
                    Bl[nj][0] = r[0]; Bl[nj][1] = r[1];
                    Bl[nj + 1][0] = r[2]; Bl[nj + 1][1] = r[3];
                }
            }
#pragma unroll
            for (int mi = 0; mi < 4; mi++)
#pragma unroll
                for (int nj = 0; nj < 4; nj++) {
                    mma16816(c[mi][nj], Ah[mi], Bh[nj]);
                    if (THREE) {
                        mma16816(c[mi][nj], Al[mi], Bh[nj]);
                        mma16816(c[mi][nj], Ah[mi], Bl[nj]);
                    }
                }
        }
    }

    // ---------- MODE 0 Q/K: fused qknorm + rope + fp16 split ----------
    if (MODE == 0 && n0 < 4608) {
        __syncthreads();   // all warps done computing before smem reuse
        float* S = (float*)tile0p;   // 128 x 132 fp32
#pragma unroll
        for (int mi = 0; mi < 4; mi++)
#pragma unroll
            for (int hh = 0; hh < 2; hh++) {
                int rl = warp_m0 + 16 * mi + 8 * hh + g;
#pragma unroll
                for (int nj = 0; nj < 4; nj++) {
                    int colL = warp_n0 + 8 * nj + 2 * tig;
                    S[rl * 132 + colL]     = c[mi][nj][2 * hh];
                    S[rl * 132 + colL + 1] = c[mi][nj][2 * hh + 1];
                }
            }
        __syncthreads();
        int isK = (n0 >= 4096);
        int head = (isK ? (n0 - 4096) : n0) >> 7;
        const float* sc = isK ? arg1 : arg0;
        f16* dsth = isK ? g_kh : g_qh;
        f16* dstl = isK ? g_kl : g_ql;
        for (int rr = 0; rr < 16; rr++) {
            int row = wid * 16 + rr;
            const float* Sr = S + row * 132;
            float v[4];
            float ss = 0.f;
#pragma unroll
            for (int k = 0; k < 4; k++) { v[k] = Sr[lane * 4 + k]; ss += v[k] * v[k]; }
#pragma unroll
            for (int o = 16; o; o >>= 1) ss += __shfl_xor_sync(0xffffffffu, ss, o);
            float inv = rsqrtf(ss * (1.0f / 128.0f) + EPSV);
            int sg = m0 + row;
            uint32_t hiW[2], loW[2];
#pragma unroll
            for (int kp = 0; kp < 2; kp++) {
                float outv[2], remv[2];
#pragma unroll
                for (int k2 = 0; k2 < 2; k2++) {
                    int d = lane * 4 + kp * 2 + k2;
                    float n = v[kp * 2 + k2] * inv * sc[d];
                    int j = d & 63;
                    float invf = expf(-0.21586735246819178f * (float)j);
                    float ang = (float)sg * invf;
                    float si, co;
                    sincosf(ang, &si, &co);
                    int od = (d < 64) ? d + 64 : d - 64;
                    float no = Sr[od] * inv * sc[od];
                    float rot = (d < 64) ? -no : no;
                    float val = n * co + rot * si;
                    if (!isK) val *= 0.08838834764831845f;   // fold 1/sqrt(128) into Q
                    outv[k2] = hhi(val, remv[k2]);
                }
                hiW[kp] = pkhf(outv[0], outv[1]);
                loW[kp] = pkhf(remv[0], remv[1]);
            }
            size_t o = isK ? (((size_t)head * S_LEN + sg) * HDIM + lane * 4)
                           : (((size_t)sg * NHQ + head) * HDIM + lane * 4);
            *(uint2*)(dsth + o) = make_uint2(hiW[0], hiW[1]);
            *(uint2*)(dstl + o) = make_uint2(loW[0], loW[1]);
        }
        return;
    }

    // ---------------- generic epilogue ----------------
#pragma unroll
    for (int mi = 0; mi < 4; mi++) {
#pragma unroll
        for (int hh = 0; hh < 2; hh++) {
            int rl = warp_m0 + 16 * mi + 8 * hh + g;
            int grow = m0 + rl;
            bool valid = true;
            int slot = 0;
            if (MODE >= 2) { valid = grow < cnt; slot = rows_s[rl]; }
#pragma unroll
            for (int nj = 0; nj < 4; nj++) {
                int col = n0 + warp_n0 + 8 * nj + 2 * tig;
                float v0 = c[mi][nj][2 * hh];
                float v1 = c[mi][nj][2 * hh + 1];
                if (MODE == 0) {
                    // V columns only (n0 >= 4608)
                    int cc = col - 4608;
                    int kvh = cc >> 7, d = cc & 127;
                    size_t o = ((size_t)kvh * S_LEN + grow) * HDIM + d;
                    float r0, r1;
                    float h0 = hhi(v0, r0), h1 = hhi(v1, r1);
                    *(uint32_t*)(g_vh + o) = pkhf(h0, h1);
                    *(uint32_t*)(g_vl + o) = pkhf(r0, r1);
                } else if (MODE == 1) {
                    size_t base = (size_t)grow * DMODEL + col;
                    g_hidden2[base]     = v0 + arg0[base];
                    g_hidden2[base + 1] = v1 + arg0[base + 1];
                } else if (MODE == 2) {
                    if (valid) {
                        const float* bia = arg1 + e * FDIM;
                        float va = v0 + bia[col], vb = v1 + bia[col + 1];
                        float sa = va / (1.0f + expf(-va));
                        float sb = vb / (1.0f + expf(-vb));
                        *(uint32_t*)(g_h_hi + (size_t)slot * FDIM + col) = pkhf(sa, sb);
                    }
                } else {
                    if (valid) {
                        const float* bia = arg1 + e * DMODEL;
                        float gt = g_gate[slot];
                        *(float2*)(g_moepart + (size_t)slot * DMODEL + col) =
                            make_float2(gt * (v0 + bia[col]), gt * (v1 + bia[col + 1]));
                    }
                }
            }
        }
    }
}

// ================= HMMA flash attention (fp16, 3-term, paired ldsm4) =================
#define ATT_SMEM (65536 + 2 * 65536)
__global__ __launch_bounds__(256, 1) void attn_mma_k() {
    extern __shared__ char sm[];
    uint32_t sb = smem_u32(sm);
    int qi = gridDim.x - 1 - blockIdx.x;   // heaviest tiles first
    int h = blockIdx.y;
    int q0 = qi * 128, kvh = h >> 3;
    int nkv = 2 * (qi + 1);
    int tid = threadIdx.x, wid = tid >> 5, lane = tid & 31;
    int g = lane >> 2, tig = lane & 3;
    int wq0 = wid * 16;

    for (int l = tid; l < 2048; l += 256) {
        int row = l >> 4, seg = l & 15;
        int off = off256(row, seg);
        size_t src = ((size_t)(q0 + row) * NHQ + h) * HDIM + seg * 8;
        __pipeline_memcpy_async(sm + off,         g_qh + src, 16);
        __pipeline_memcpy_async(sm + 32768 + off, g_ql + src, 16);
    }

    auto fill_kv = [&](int t, int st) {
        char* base = sm + 65536 + st * 65536;
        int kv0 = t * 64;
        for (int l = tid; l < 1024; l += 256) {
            int row = l >> 4, seg = l & 15;
            int off = off256(row, seg);
            size_t src = ((size_t)kvh * S_LEN + kv0 + row) * HDIM + seg * 8;
            __pipeline_memcpy_async(base + off,         g_kh + src, 16);
            __pipeline_memcpy_async(base + 16384 + off, g_kl + src, 16);
            __pipeline_memcpy_async(base + 32768 + off, g_vh + src, 16);
            __pipeline_memcpy_async(base + 49152 + off, g_vl + src, 16);
        }
    };

    float o[16][4];
#pragma unroll
    for (int dj = 0; dj < 16; dj++)
#pragma unroll
        for (int q = 0; q < 4; q++) o[dj][q] = 0.f;
    float m0 = -3e38f, m1 = -3e38f, l0 = 0.f, l1 = 0.f;

    fill_kv(0, 0);
    __pipeline_commit();

    for (int t = 0; t < nkv; t++) {
        if (t + 1 < nkv) fill_kv(t + 1, (t + 1) & 1);
        __pipeline_commit();
        __pipeline_wait_prior(1);
        __syncthreads();

        uint32_t st  = sb + 65536 + (uint32_t)(t & 1) * 65536;
        int k0 = t * 64;

        float s[8][4];
#pragma unroll
        for (int nj = 0; nj < 8; nj++)
#pragma unroll
            for (int q = 0; q < 4; q++) s[nj][q] = 0.f;

#pragma unroll
        for (int kk = 0; kk < 8; kk++) {
            uint32_t aqh[4], aql[4];
            int a_row = wq0 + (lane & 15);
            int a_sb  = kk * 2 + ((lane >> 4) & 1);
            uint32_t aaddr = sb + off256(a_row, a_sb);
            ldsm4(aaddr, aqh);
            ldsm4(aaddr + 32768, aql);
            // K fragments: x4 pairs — lanes 16-31 fetch nj+1's rows
            uint32_t Bh[8][2], Bl[8][2];
#pragma unroll
            for (int njp = 0; njp < 4; njp++) {
                int nj = njp * 2;
                int b_row = (nj + (lane >> 4)) * 8 + (lane & 7);
                int b_sb  = kk * 2 + ((lane >> 3) & 1);
                uint32_t baddr = st + off256(b_row, b_sb);
                uint32_t r[4];
                ldsm4(baddr, r);
                Bh[nj][0] = r[0]; Bh[nj][1] = r[1];
                Bh[nj + 1][0] = r[2]; Bh[nj + 1][1] = r[3];
                ldsm4(baddr + 16384, r);
                Bl[nj][0] = r[0]; Bl[nj][1] = r[1];
                Bl[nj + 1][0] = r[2]; Bl[nj + 1][1] = r[3];
            }
#pragma unroll
            for (int nj = 0; nj < 8; nj++) {
                mma16816(s[nj], aqh, Bh[nj]);
                mma16816(s[nj], aql, Bh[nj]);
                mma16816(s[nj], aqh, Bl[nj]);
            }
        }

        if (k0 + 63 > q0 + wq0) {
            int r0 = q0 + wq0 + g, r1 = r0 + 8;
#pragma unroll
            for (int nj = 0; nj < 8; nj++) {
                int col = k0 + nj * 8 + 2 * tig;
                if (col > r0)     s[nj][0] = -1e9f;
                if (col + 1 > r0) s[nj][1] = -1e9f;
                if (col > r1)     s[nj][2] = -1e9f;
                if (col + 1 > r1) s[nj][3] = -1e9f;
            }
        }

        float mx0 = m0, mx1 = m1;
#pragma unroll
        for (int nj = 0; nj < 8; nj++) {
            mx0 = fmaxf(mx0, fmaxf(s[nj][0], s[nj][1]));
            mx1 = fmaxf(mx1, fmaxf(s[nj][2], s[nj][3]));
        }
        mx0 = fmaxf(mx0, __shfl_xor_sync(0xffffffffu, mx0, 1));
        mx0 = fmaxf(mx0, __shfl_xor_sync(0xffffffffu, mx0, 2));
        mx1 = fmaxf(mx1, __shfl_xor_sync(0xffffffffu, mx1, 1));
        mx1 = fmaxf(mx1, __shfl_xor_sync(0xffffffffu, mx1, 2));
        float a0 = __expf(m0 - mx0), a1 = __expf(m1 - mx1);
        m0 = mx0; m1 = mx1;
        l0 *= a0; l1 *= a1;
#pragma unroll
        for (int dj = 0; dj < 16; dj++) {
            o[dj][0] *= a0; o[dj][1] *= a0;
            o[dj][2] *= a1; o[dj][3] *= a1;
        }

        uint32_t phi[8][2], plo[8][2];
#pragma unroll
        for (int nj = 0; nj < 8; nj++) {
            float p00 = __expf(s[nj][0] - mx0), p01 = __expf(s[nj][1] - mx0);
            float p10 = __expf(s[nj][2] - mx1), p11 = __expf(s[nj][3] - mx1);
            l0 += p00 + p01; l1 += p10 + p11;
            float r00, r01, r10, r11;
            float h00 = hhi(p00, r00), h01 = hhi(p01, r01);
            float h10 = hhi(p10, r10), h11 = hhi(p11, r11);
            phi[nj][0] = pkhf(h00, h01); phi[nj][1] = pkhf(h10, h11);
            plo[nj][0] = pkhf(r00, r01); plo[nj][1] = pkhf(r10, r11);
        }

        uint32_t vh_b = st + 32768;
#pragma unroll
        for (int kc = 0; kc < 4; kc++) {
            uint32_t aph[4] = { phi[2 * kc][0], phi[2 * kc][1], phi[2 * kc + 1][0], phi[2 * kc + 1][1] };
            uint32_t apl[4] = { plo[2 * kc][0], plo[2 * kc][1], plo[2 * kc + 1][0], plo[2 * kc + 1][1] };
            // V fragments: x4.trans pairs — lanes 16-31 fetch dj+1's segment
#pragma unroll
            for (int djp = 0; djp < 8; djp++) {
                int dj = djp * 2;
                int v_row = kc * 16 + (lane & 15);
                uint32_t vaddr = vh_b + off256(v_row, dj + (lane >> 4));
                uint32_t rh[4], rl[4];
                ldsm4t(vaddr, rh);
                ldsm4t(vaddr + 16384, rl);
                uint32_t b0[2] = { rh[0], rh[1] }, b1[2] = { rh[2], rh[3] };
                uint32_t c0[2] = { rl[0], rl[1] }, c1[2] = { rl[2], rl[3] };
                mma16816(o[dj], aph, b0);
                mma16816(o[dj], apl, b0);
                mma16816(o[dj], aph, c0);
                mma16816(o[dj + 1], aph, b1);
                mma16816(o[dj + 1], apl, b1);
                mma16816(o[dj + 1], aph, c1);
            }
        }
        __syncthreads();
    }

    l0 += __shfl_xor_sync(0xffffffffu, l0, 1);
    l0 += __shfl_xor_sync(0xffffffffu, l0, 2);
    l1 += __shfl_xor_sync(0xffffffffu, l1, 1);
    l1 += __shfl_xor_sync(0xffffffffu, l1, 2);
    float i0 = 1.0f / l0, i1 = 1.0f / l1;
    int r0 = q0 + wq0 + g, r1 = r0 + 8;
#pragma unroll
    for (int dj = 0; dj < 16; dj++) {
        int cc = dj * 8 + 2 * tig;
        size_t o0 = (size_t)r0 * ATTN_D + h * HDIM + cc;
        size_t o1 = (size_t)r1 * ATTN_D + h * HDIM + cc;
        float ra, rb;
        float v0 = o[dj][0] * i0, v1 = o[dj][1] * i0;
        float h0 = hhi(v0, ra), h1 = hhi(v1, rb);
        *(uint32_t*)(g_attn_hi + o0) = pkhf(h0, h1);
        *(uint32_t*)(g_attn_lo + o0) = pkhf(ra, rb);
        float w0 = o[dj][2] * i1, w1 = o[dj][3] * i1;
        h0 = hhi(w0, ra); h1 = hhi(w1, rb);
        *(uint32_t*)(g_attn_hi + o1) = pkhf(h0, h1);
        *(uint32_t*)(g_attn_lo + o1) = pkhf(ra, rb);
    }
}

// ================= init / final =================
__global__ void init_k(float* __restrict__ out) {
    if (threadIdx.x < NEXP) g_cnt[threadIdx.x] = 0;
    if (threadIdx.x == 0) out[(size_t)S_LEN * DMODEL + S_LEN * NEXP] = 1.0f;
}

__global__ void final_k(float* __restrict__ out) {
    int i = blockIdx.x * 256 + threadIdx.x;   // float4 index
    int t = i / (DMODEL / 4);
    int d = i - t * (DMODEL / 4);
    const float4* h2 = (const float4*)g_hidden2;
    const float4* mp = (const float4*)g_moepart;
    float4 a = h2[i];
    float4 b = mp[(size_t)(2 * t) * (DMODEL / 4) + d];
    float4 c = mp[(size_t)(2 * t + 1) * (DMODEL / 4) + d];
    float4 w;
    w.x = a.x + b.x + c.x; w.y = a.y + b.y + c.y;
    w.z = a.z + b.z + c.z; w.w = a.w + b.w + c.w;
    ((float4*)out)[i] = w;
}

// ================= launch =================
extern "C" void kernel_launch(void* const* d_in, const int* in_sizes, int n_in,
                              void* d_out, int out_size) {
    const float* hs  = (const float*)d_in[0];
    const float* ln1 = (const float*)d_in[1];
    const float* ln2 = (const float*)d_in[2];
    const float* Wq  = (const float*)d_in[3];
    const float* Wk  = (const float*)d_in[4];
    const float* Wv  = (const float*)d_in[5];
    const float* Wo  = (const float*)d_in[6];
    const float* qns = (const float*)d_in[7];
    const float* kns = (const float*)d_in[8];
    const float* rW  = (const float*)d_in[9];
    const float* upW = (const float*)d_in[10];
    const float* upb = (const float*)d_in[11];
    const float* dnW = (const float*)d_in[12];
    const float* dnb = (const float*)d_in[13];
    float* out = (float*)d_out;

    void *wq_hi, *wq_lo, *wk_hi, *wk_lo, *wv_hi, *wv_lo, *wo_hi, *wo_lo, *wup, *wdn;
    cudaGetSymbolAddress(&wq_hi, g_wq_hi);  cudaGetSymbolAddress(&wq_lo, g_wq_lo);
    cudaGetSymbolAddress(&wk_hi, g_wk_hi);  cudaGetSymbolAddress(&wk_lo, g_wk_lo);
    cudaGetSymbolAddress(&wv_hi, g_wv_hi);  cudaGetSymbolAddress(&wv_lo, g_wv_lo);
    cudaGetSymbolAddress(&wo_hi, g_wo_hi);  cudaGetSymbolAddress(&wo_lo, g_wo_lo);
    cudaGetSymbolAddress(&wup, g_wup);      cudaGetSymbolAddress(&wdn, g_wdn);

    cudaFuncSetAttribute(attn_mma_k, cudaFuncAttributeMaxDynamicSharedMemorySize, ATT_SMEM);
    cudaFuncSetAttribute(mma_gemm_k<0>, cudaFuncAttributeMaxDynamicSharedMemorySize, DSMEM);
    cudaFuncSetAttribute(mma_gemm_k<1>, cudaFuncAttributeMaxDynamicSharedMemorySize, DSMEM);
    cudaFuncSetAttribute(mma_gemm_k<2>, cudaFuncAttributeMaxDynamicSharedMemorySize, DSMEM);
    cudaFuncSetAttribute(mma_gemm_k<3>, cudaFuncAttributeMaxDynamicSharedMemorySize, DSMEM);

    // weight prep (2 float4 per thread)
    split_k<<<(DMODEL * ATTN_D) / 2048, 256>>>((const float4*)Wq, (uint2*)wq_hi, (uint2*)wq_lo);
    split_k<<<(DMODEL * 512) / 2048, 256>>>((const float4*)Wk, (uint2*)wk_hi, (uint2*)wk_lo);
    split_k<<<(DMODEL * 512) / 2048, 256>>>((const float4*)Wv, (uint2*)wv_hi, (uint2*)wv_lo);
    split_k<<<(ATTN_D * DMODEL) / 2048, 256>>>((const float4*)Wo, (uint2*)wo_hi, (uint2*)wo_lo);
    convert_k<<<(NEXP * DMODEL * FDIM) / 2048, 256>>>((const float4*)upW, (uint2*)wup);
    convert_k<<<(NEXP * FDIM * DMODEL) / 2048, 256>>>((const float4*)dnW, (uint2*)wdn);

    // 1. rmsnorm1 -> fp16 hi/lo
    rmsnorm1_split_k<<<S_LEN, 256>>>(hs, ln1);
    // 2. fused QKV projection; Q/K epilogue does qknorm+rope+split, V split direct
    mma_gemm_k<0><<<dim3(QKV_N / 128, S_LEN / 128), 256, DSMEM>>>(qns, kns);
    // 3. HMMA flash attention -> g_attn hi/lo
    attn_mma_k<<<dim3(S_LEN / 128, NHQ), 256, ATT_SMEM>>>();
    // 4. output projection + residual
    mma_gemm_k<1><<<dim3(DMODEL / 128, S_LEN / 128), 256, DSMEM>>>(hs, nullptr);
    // 5. fused rmsnorm2 + router (init first: zero counts, write aux)
    init_k<<<1, 32>>>(out);
    rmsnorm2_router_k<<<S_LEN, 256>>>(ln2, rW, out);
    // 6. MoE (gathered rows, 1-term fp16)
    mma_gemm_k<2><<<dim3(FDIM / 128, 16, NEXP), 256, DSMEM>>>(nullptr, upb);
    mma_gemm_k<3><<<dim3(DMODEL / 128, 16, NEXP), 256, DSMEM>>>(nullptr, dnb);
    // 7. final residual + MoE sum
    final_k<<<(S_LEN * DMODEL / 4) / 256, 256>>>(out);
}

// round 14
// speedup vs baseline: 6.2421x; 1.0034x over previous
#include <cuda_runtime.h>
#include <cuda_fp16.h>
#include <cuda_pipeline.h>
#include <math.h>
#include <stdint.h>

#define S_LEN 2048
#define DMODEL 2048
#define QKV_N 5120
#define NHQ 32
#define NHKV 4
#define HDIM 128
#define NEXP 8
#define FDIM 768
#define EPSV 1e-6f
#define ATTN_D (NHQ * HDIM)   // 4096

typedef __half f16;

// ================= scratch (device globals; no allocations allowed) =================
__device__ __align__(256) f16   g_x_hi[S_LEN * DMODEL];
__device__ __align__(256) f16   g_x_lo[S_LEN * DMODEL];
__device__ __align__(256) f16   g_qh[S_LEN * NHQ * HDIM];
__device__ __align__(256) f16   g_ql[S_LEN * NHQ * HDIM];
__device__ __align__(256) f16   g_kh[NHKV * S_LEN * HDIM];
__device__ __align__(256) f16   g_kl[NHKV * S_LEN * HDIM];
__device__ __align__(256) f16   g_vh[NHKV * S_LEN * HDIM];
__device__ __align__(256) f16   g_vl[NHKV * S_LEN * HDIM];
__device__ __align__(256) f16   g_attn_hi[S_LEN * ATTN_D];
__device__ __align__(256) f16   g_attn_lo[S_LEN * ATTN_D];
__device__ __align__(256) float g_hidden2[S_LEN * DMODEL];
__device__ __align__(256) f16   g_xf_hi[S_LEN * DMODEL];
__device__ __align__(256) f16   g_h_hi[S_LEN * 2 * FDIM];
__device__ __align__(256) float g_moepart[S_LEN * 2 * DMODEL];
__device__ float g_gate[S_LEN * 2];
__device__ int   g_cnt[NEXP];
__device__ int   g_list[NEXP][S_LEN];
// weights in NATIVE [K, N] layout; QKV/Wo split hi/lo (3-term), MoE single (1-term)
__device__ __align__(256) f16 g_wq_hi[DMODEL * ATTN_D];
__device__ __align__(256) f16 g_wq_lo[DMODEL * ATTN_D];
__device__ __align__(256) f16 g_wk_hi[DMODEL * 512];
__device__ __align__(256) f16 g_wk_lo[DMODEL * 512];
__device__ __align__(256) f16 g_wv_hi[DMODEL * 512];
__device__ __align__(256) f16 g_wv_lo[DMODEL * 512];
__device__ __align__(256) f16 g_wo_hi[ATTN_D * DMODEL];
__device__ __align__(256) f16 g_wo_lo[ATTN_D * DMODEL];
__device__ __align__(256) f16 g_wup[NEXP * DMODEL * FDIM];
__device__ __align__(256) f16 g_wdn[NEXP * FDIM * DMODEL];

// ================= PTX helpers =================
__device__ __forceinline__ uint32_t smem_u32(const void* p) {
    uint32_t a;
    asm("{ .reg .u64 t; cvta.to.shared.u64 t, %1; cvt.u32.u64 %0, t; }" : "=r"(a) : "l"(p));
    return a;
}
__device__ __forceinline__ void ldsm4(uint32_t a, uint32_t r[4]) {
    asm volatile("ldmatrix.sync.aligned.m8n8.x4.shared.b16 {%0,%1,%2,%3}, [%4];"
                 : "=r"(r[0]), "=r"(r[1]), "=r"(r[2]), "=r"(r[3]) : "r"(a));
}
__device__ __forceinline__ void ldsm4t(uint32_t a, uint32_t r[4]) {
    asm volatile("ldmatrix.sync.aligned.m8n8.x4.trans.shared.b16 {%0,%1,%2,%3}, [%4];"
                 : "=r"(r[0]), "=r"(r[1]), "=r"(r[2]), "=r"(r[3]) : "r"(a));
}
__device__ __forceinline__ void mma16816(float c[4], const uint32_t a[4], const uint32_t b[2]) {
    asm volatile(
        "mma.sync.aligned.m16n8k16.row.col.f32.f16.f16.f32 "
        "{%0,%1,%2,%3}, {%4,%5,%6,%7}, {%8,%9}, {%0,%1,%2,%3};"
        : "+f"(c[0]), "+f"(c[1]), "+f"(c[2]), "+f"(c[3])
        : "r"(a[0]), "r"(a[1]), "r"(a[2]), "r"(a[3]), "r"(b[0]), "r"(b[1]));
}
__device__ __forceinline__ uint32_t lds_addr(uint32_t base, int row, int kbyte) {
    int seg = kbyte >> 4;
    return base + row * 128 + (((uint32_t)(seg ^ (row & 7))) << 4);
}
__device__ __forceinline__ int off256(int row, int seg) {
    return row * 256 + ((seg ^ (row & 7)) << 4);
}
__device__ __forceinline__ uint32_t pkhf(float x, float y) {
    __half2 t = __floats2half2_rn(x, y);
    return *reinterpret_cast<uint32_t*>(&t);
}
__device__ __forceinline__ float hhi(float x, float& r) {
    float h = __half2float(__float2half_rn(x));
    r = x - h;
    return h;
}

// ================= weight prep (2 float4 per thread) =================
__global__ void split_k(const float4* __restrict__ in, uint2* __restrict__ hi,
                        uint2* __restrict__ lo) {
    size_t base = (size_t)blockIdx.x * 512 + threadIdx.x;
#pragma unroll
    for (int u = 0; u < 2; u++) {
        size_t i = base + u * 256;
        float4 v = in[i];
        float r0, r1, r2, r3;
        float h0 = hhi(v.x, r0), h1 = hhi(v.y, r1), h2 = hhi(v.z, r2), h3 = hhi(v.w, r3);
        hi[i] = make_uint2(pkhf(h0, h1), pkhf(h2, h3));
        lo[i] = make_uint2(pkhf(r0, r1), pkhf(r2, r3));
    }
}
__global__ void convert_k(const float4* __restrict__ in, uint2* __restrict__ out) {
    size_t base = (size_t)blockIdx.x * 512 + threadIdx.x;
#pragma unroll
    for (int u = 0; u < 2; u++) {
        size_t i = base + u * 256;
        float4 v = in[i];
        out[i] = make_uint2(pkhf(v.x, v.y), pkhf(v.z, v.w));
    }
}

// ================= rmsnorm1 =================
__global__ void rmsnorm1_split_k(const float* __restrict__ in, const float* __restrict__ sc) {
    int row = blockIdx.x;
    const float* r = in + (size_t)row * DMODEL;
    float ss = 0.f;
    for (int i = threadIdx.x; i < DMODEL; i += 256) { float v = r[i]; ss += v * v; }
    for (int o = 16; o; o >>= 1) ss += __shfl_xor_sync(0xffffffffu, ss, o);
    __shared__ float red[8];
    if ((threadIdx.x & 31) == 0) red[threadIdx.x >> 5] = ss;
    __syncthreads();
    float tot = 0.f;
#pragma unroll
    for (int i = 0; i < 8; i++) tot += red[i];
    float inv = rsqrtf(tot / (float)DMODEL + EPSV);
    for (int i = threadIdx.x; i < DMODEL; i += 256) {
        float w = r[i] * inv * sc[i];
        float rem;
        float h = hhi(w, rem);
        size_t o = (size_t)row * DMODEL + i;
        g_x_hi[o] = __float2half_rn(h);
        g_x_lo[o] = __float2half_rn(rem);
    }
}

// ================= fused rmsnorm2 + router =================
__global__ void rmsnorm2_router_k(const float* __restrict__ sc, const float* __restrict__ rW,
                                  float* __restrict__ out) {
    __shared__ float xs[DMODEL];
    __shared__ float red[8];
    __shared__ float lg[NEXP];
    int row = blockIdx.x;
    int tid = threadIdx.x;
    const float4* r4 = (const float4*)(g_hidden2 + (size_t)row * DMODEL);
    const float4* s4 = (const float4*)sc;
    float4 v0 = r4[tid], v1 = r4[tid + 256];
    float ss = v0.x * v0.x + v0.y * v0.y + v0.z * v0.z + v0.w * v0.w
             + v1.x * v1.x + v1.y * v1.y + v1.z * v1.z + v1.w * v1.w;
    for (int o = 16; o; o >>= 1) ss += __shfl_xor_sync(0xffffffffu, ss, o);
    if ((tid & 31) == 0) red[tid >> 5] = ss;
    __syncthreads();
    float tot = 0.f;
#pragma unroll
    for (int i = 0; i < 8; i++) tot += red[i];
    float inv = rsqrtf(tot / (float)DMODEL + EPSV);
    float4 c0 = s4[tid], c1 = s4[tid + 256];
    float w0 = v0.x * inv * c0.x, w1 = v0.y * inv * c0.y;
    float w2 = v0.z * inv * c0.z, w3 = v0.w * inv * c0.w;
    float u0 = v1.x * inv * c1.x, u1 = v1.y * inv * c1.y;
    float u2 = v1.z * inv * c1.z, u3 = v1.w * inv * c1.w;
    xs[4 * tid] = w0; xs[4 * tid + 1] = w1; xs[4 * tid + 2] = w2; xs[4 * tid + 3] = w3;
    int t2 = tid + 256;
    xs[4 * t2] = u0; xs[4 * t2 + 1] = u1; xs[4 * t2 + 2] = u2; xs[4 * t2 + 3] = u3;
    size_t ob = (size_t)row * DMODEL;
    *(uint2*)(g_xf_hi + ob + 4 * tid) = make_uint2(pkhf(w0, w1), pkhf(w2, w3));
    *(uint2*)(g_xf_hi + ob + 4 * t2)  = make_uint2(pkhf(u0, u1), pkhf(u2, u3));
    __syncthreads();
    int w = tid >> 5, lane = tid & 31;
    float sum = 0.f;
    for (int dd = lane; dd < DMODEL; dd += 32) sum += xs[dd] * rW[dd * NEXP + w];
    for (int o = 16; o; o >>= 1) sum += __shfl_xor_sync(0xffffffffu, sum, o);
    if (lane == 0) lg[w] = sum;
    __syncthreads();
    if (tid == 0) {
        float* lo = out + (size_t)S_LEN * DMODEL + (size_t)row * NEXP;
        float mx = lg[0];
#pragma unroll
        for (int e = 1; e < NEXP; e++) mx = fmaxf(mx, lg[e]);
        float p[NEXP];
#pragma unroll
        for (int e = 0; e < NEXP; e++) { p[e] = expf(lg[e] - mx); lo[e] = lg[e]; }
        int i1 = 0;
#pragma unroll
        for (int e = 1; e < NEXP; e++) if (lg[e] > lg[i1]) i1 = e;
        int i2 = -1;
#pragma unroll
        for (int e = 0; e < NEXP; e++) {
            if (e == i1) continue;
            if (i2 < 0 || lg[e] > lg[i2]) i2 = e;
        }
        float denom = p[i1] + p[i2];
        g_gate[row * 2]     = p[i1] / denom;
        g_gate[row * 2 + 1] = p[i2] / denom;
        int pos = atomicAdd(&g_cnt[i1], 1);
        g_list[i1][pos] = row * 2;
        pos = atomicAdd(&g_cnt[i2], 1);
        g_list[i2][pos] = row * 2 + 1;
    }
}

// ================= HMMA GEMM (B native [K,N] via paired ldmatrix.x4.trans) =========
#define STAGE_BYTES 65536
#define DSMEM (3 * STAGE_BYTES + 1024)

template<int MODE>
__global__ __launch_bounds__(256, 1) void mma_gemm_k(const float* __restrict__ arg0,
                                                     const float* __restrict__ arg1) {
    constexpr int K   = (MODE == 1) ? ATTN_D : (MODE == 3) ? FDIM : DMODEL;
    constexpr int NCH = K / 64;
    constexpr bool THREE = (MODE < 2);

    extern __shared__ char dyn[];
    __shared__ int rows_s[128];

    int tid = threadIdx.x, wid = tid >> 5, lane = tid & 31;
    int e = blockIdx.z;
    int m0 = blockIdx.y * 128;
    int n0 = blockIdx.x * 128;

    int cnt = 0;
    if (MODE >= 2) {
        cnt = g_cnt[e];
        if (m0 >= cnt) return;
        if (tid < 128)
            rows_s[tid] = (m0 + tid < cnt) ? g_list[e][m0 + tid] : g_list[e][0];
        __syncthreads();
    }

    const f16 *Ahi, *Alo = nullptr, *Bhi, *Blo = nullptr;
    int ldB, bn;
    if (MODE == 0) {
        Ahi = g_x_hi; Alo = g_x_lo;
        if (n0 < 4096)      { Bhi = g_wq_hi; Blo = g_wq_lo; ldB = 4096; bn = n0; }
        else if (n0 < 4608) { Bhi = g_wk_hi; Blo = g_wk_lo; ldB = 512;  bn = n0 - 4096; }
        else                { Bhi = g_wv_hi; Blo = g_wv_lo; ldB = 512;  bn = n0 - 4608; }
    } else if (MODE == 1) {
        Ahi = g_attn_hi; Alo = g_attn_lo; Bhi = g_wo_hi; Blo = g_wo_lo; ldB = DMODEL; bn = n0;
    } else if (MODE == 2) {
        Ahi = g_xf_hi;
        Bhi = g_wup + (size_t)e * DMODEL * FDIM;
        ldB = FDIM; bn = n0;
    } else {
        Ahi = g_h_hi;
        Bhi = g_wdn + (size_t)e * FDIM * DMODEL;
        ldB = DMODEL; bn = n0;
    }

    uint32_t dyn_u = smem_u32(dyn);
    uint32_t tile0 = (dyn_u + 1023u) & ~1023u;
    char* tile0p = dyn + (tile0 - dyn_u);

    auto load_chunk = [&](int c, int s) {
        char* st = tile0p + s * STAGE_BYTES;
        for (int l = tid; l < 1024; l += 256) {
            int row = l >> 3, seg = l & 7;
            uint32_t off = (uint32_t)(row * 128 + seg * 16);
            uint32_t sw = off ^ ((off >> 3) & 0x70);
            size_t ar;
            if (MODE == 2)      ar = (size_t)(rows_s[row] >> 1) * K;
            else if (MODE == 3) ar = (size_t)rows_s[row] * K;
            else                ar = (size_t)(m0 + row) * K;
            __pipeline_memcpy_async(st + sw, (const char*)(Ahi + ar + (size_t)c * 64) + seg * 16, 16);
            if (THREE)
                __pipeline_memcpy_async(st + 16384 + sw, (const char*)(Alo + ar + (size_t)c * 64) + seg * 16, 16);
        }
        for (int l = tid; l < 1024; l += 256) {
            int row = l >> 4, seg = l & 15;
            int off = off256(row, seg);
            size_t src = (size_t)(c * 64 + row) * ldB + bn + seg * 8;
            __pipeline_memcpy_async(st + 32768 + off, (const char*)(Bhi + src), 16);
            if (THREE)
                __pipeline_memcpy_async(st + 49152 + off, (const char*)(Blo + src), 16);
        }
    };

    int warp_m0 = (wid >> 2) * 64;
    int warp_n0 = (wid & 3) * 32;
    int bseg0 = warp_n0 >> 3;
    int g = lane >> 2, tig = lane & 3;

    float c[4][4][4];
#pragma unroll
    for (int mi = 0; mi < 4; mi++)
#pragma unroll
        for (int nj = 0; nj < 4; nj++)
#pragma unroll
            for (int q = 0; q < 4; q++) c[mi][nj][q] = 0.f;

    load_chunk(0, 0);
    __pipeline_commit();
    load_chunk(1, 1);
    __pipeline_commit();

    for (int i = 0; i < NCH; i++) {
        __pipeline_wait_prior(1);
        __syncthreads();
        if (i + 2 < NCH) load_chunk(i + 2, (i + 2) % 3);
        __pipeline_commit();

        uint32_t su  = tile0 + (uint32_t)(i % 3) * STAGE_BYTES;
        uint32_t aHiB = su, aLoB = su + 16384, bHiB = su + 32768;

#pragma unroll
        for (int kk = 0; kk < 4; kk++) {
            uint32_t Ah[4][4], Al[4][4], Bh[4][2], Bl[4][2];
            int a_row = lane & 15;
            int a_kb  = 32 * kk + ((lane >> 4) << 4);
#pragma unroll
            for (int mi = 0; mi < 4; mi++) {
                int row = warp_m0 + 16 * mi + a_row;
                ldsm4(lds_addr(aHiB, row, a_kb), Ah[mi]);
                if (THREE) ldsm4(lds_addr(aLoB, row, a_kb), Al[mi]);
            }
            // B fragments: x4.trans pairs — lanes 16-31 fetch nj+1's segment
            int b_row = 16 * kk + (lane & 15);
#pragma unroll
            for (int njp = 0; njp < 2; njp++) {
                int nj = njp * 2;
                uint32_t r[4];
                uint32_t baddr = bHiB + off256(b_row, bseg0 + nj + (lane >> 4));
                ldsm4t(baddr, r);
                Bh[nj][0] = r[0]; Bh[nj][1] = r[1];
                Bh[nj + 1][0] = r[2]; Bh[nj + 1][1] = r[3];
                if (THREE) {
                    ldsm4t(baddr + 16384, r);
                    Bl[nj][0] = r[0]; Bl[nj][1] = r[1];
                    Bl[nj + 1][0] = r[2]; Bl[nj + 1][1] = r[3];
                }
            }
#pragma unroll
            for (int mi = 0; mi < 4; mi++)
#pragma unroll
                for (int nj = 0; nj < 4; nj++) {
                    mma16816(c[mi][nj], Ah[mi], Bh[nj]);
                    if (THREE) {
                        mma16816(c[mi][nj], Al[mi], Bh[nj]);
                        mma16816(c[mi][nj], Ah[mi], Bl[nj]);
                    }
                }
        }
    }

    // ---------- MODE 0 Q/K: fused qknorm + rope + fp16 split ----------
    if (MODE == 0 && n0 < 4608) {
        __syncthreads();   // all warps done computing before smem reuse
        float* S = (float*)tile0p;   // 128 x 132 fp32
#pragma unroll
        for (int mi = 0; mi < 4; mi++)
#pragma unroll
            for (int hh = 0; hh < 2; hh++) {
                int rl = warp_m0 + 16 * mi + 8 * hh + g;
#pragma unroll
                for (int nj = 0; nj < 4; nj++) {
                    int colL = warp_n0 + 8 * nj + 2 * tig;
                    S[rl * 132 + colL]     = c[mi][nj][2 * hh];
                    S[rl * 132 + colL + 1] = c[mi][nj][2 * hh + 1];
                }
            }
        __syncthreads();
        int isK = (n0 >= 4096);
        int head = (isK ? (n0 - 4096) : n0) >> 7;
        const float* sc = isK ? arg1 : arg0;
        f16* dsth = isK ? g_kh : g_qh;
        f16* dstl = isK ? g_kl : g_ql;
        for (int rr = 0; rr < 16; rr++) {
            int row = wid * 16 + rr;
            const float* Sr = S + row * 132;
            float v[4];
            float ss = 0.f;
#pragma unroll
            for (int k = 0; k < 4; k++) { v[k] = Sr[lane * 4 + k]; ss += v[k] * v[k]; }
#pragma unroll
            for (int o = 16; o; o >>= 1) ss += __shfl_xor_sync(0xffffffffu, ss, o);
            float inv = rsqrtf(ss * (1.0f / 128.0f) + EPSV);
            int sg = m0 + row;
            uint32_t hiW[2], loW[2];
#pragma unroll
            for (int kp = 0; kp < 2; kp++) {
                float outv[2], remv[2];
#pragma unroll
                for (int k2 = 0; k2 < 2; k2++) {
                    int d = lane * 4 + kp * 2 + k2;
                    float n = v[kp * 2 + k2] * inv * sc[d];
                    int j = d & 63;
                    float invf = expf(-0.21586735246819178f * (float)j);
                    float ang = (float)sg * invf;
                    float si, co;
                    sincosf(ang, &si, &co);
                    int od = (d < 64) ? d + 64 : d - 64;
                    float no = Sr[od] * inv * sc[od];
                    float rot = (d < 64) ? -no : no;
                    float val = n * co + rot * si;
                    if (!isK) val *= 0.08838834764831845f;   // fold 1/sqrt(128) into Q
                    outv[k2] = hhi(val, remv[k2]);
                }
                hiW[kp] = pkhf(outv[0], outv[1]);
                loW[kp] = pkhf(remv[0], remv[1]);
            }
            size_t o = isK ? (((size_t)head * S_LEN + sg) * HDIM + lane * 4)
                           : (((size_t)sg * NHQ + head) * HDIM + lane * 4);
            *(uint2*)(dsth + o) = make_uint2(hiW[0], hiW[1]);
            *(uint2*)(dstl + o) = make_uint2(loW[0], loW[1]);
        }
        return;
    }

    // ---------------- generic epilogue ----------------
#pragma unroll
    for (int mi = 0; mi < 4; mi++) {
#pragma unroll
        for (int hh = 0; hh < 2; hh++) {
            int rl = warp_m0 + 16 * mi + 8 * hh + g;
            int grow = m0 + rl;
            bool valid = true;
            int slot = 0;
            if (MODE >= 2) { valid = grow < cnt; slot = rows_s[rl]; }
#pragma unroll
            for (int nj = 0; nj < 4; nj++) {
                int col = n0 + warp_n0 + 8 * nj + 2 * tig;
                float v0 = c[mi][nj][2 * hh];
                float v1 = c[mi][nj][2 * hh + 1];
                if (MODE == 0) {
                    // V columns only (n0 >= 4608)
                    int cc = col - 4608;
                    int kvh = cc >> 7, d = cc & 127;
                    size_t o = ((size_t)kvh * S_LEN + grow) * HDIM + d;
                    float r0, r1;
                    float h0 = hhi(v0, r0), h1 = hhi(v1, r1);
                    *(uint32_t*)(g_vh + o) = pkhf(h0, h1);
                    *(uint32_t*)(g_vl + o) = pkhf(r0, r1);
                } else if (MODE == 1) {
                    size_t base = (size_t)grow * DMODEL + col;
                    g_hidden2[base]     = v0 + arg0[base];
                    g_hidden2[base + 1] = v1 + arg0[base + 1];
                } else if (MODE == 2) {
                    if (valid) {
                        const float* bia = arg1 + e * FDIM;
                        float va = v0 + bia[col], vb = v1 + bia[col + 1];
                        float sa = va / (1.0f + expf(-va));
                        float sb = vb / (1.0f + expf(-vb));
                        *(uint32_t*)(g_h_hi + (size_t)slot * FDIM + col) = pkhf(sa, sb);
                    }
                } else {
                    if (valid) {
                        const float* bia = arg1 + e * DMODEL;
                        float gt = g_gate[slot];
                        *(float2*)(g_moepart + (size_t)slot * DMODEL + col) =
                            make_float2(gt * (v0 + bia[col]), gt * (v1 + bia[col + 1]));
                    }
                }
            }
        }
    }
}

// ================= HMMA flash attention (fp16, 3-term, paired ldsm4) =================
#define ATT_SMEM (65536 + 2 * 65536)
__global__ __launch_bounds__(256, 1) void attn_mma_k() {
    extern __shared__ char sm[];
    uint32_t sb = smem_u32(sm);
    int qi = gridDim.x - 1 - blockIdx.x;   // heaviest tiles first
    int h = blockIdx.y;
    int q0 = qi * 128, kvh = h >> 3;
    int nkv = 2 * (qi + 1);
    int tid = threadIdx.x, wid = tid >> 5, lane = tid & 31;
    int g = lane >> 2, tig = lane & 3;
    int wq0 = wid * 16;

    for (int l = tid; l < 2048; l += 256) {
        int row = l >> 4, seg = l & 15;
        int off = off256(row, seg);
        size_t src = ((size_t)(q0 + row) * NHQ + h) * HDIM + seg * 8;
        __pipeline_memcpy_async(sm + off,         g_qh + src, 16);
        __pipeline_memcpy_async(sm + 32768 + off, g_ql + src, 16);
    }

    auto fill_kv = [&](int t, int st) {
        char* base = sm + 65536 + st * 65536;
        int kv0 = t * 64;
        for (int l = tid; l < 1024; l += 256) {
            int row = l >> 4, seg = l & 15;
            int off = off256(row, seg);
            size_t src = ((size_t)kvh * S_LEN + kv0 + row) * HDIM + seg * 8;
            __pipeline_memcpy_async(base + off,         g_kh + src, 16);
            __pipeline_memcpy_async(base + 16384 + off, g_kl + src, 16);
            __pipeline_memcpy_async(base + 32768 + off, g_vh + src, 16);
            __pipeline_memcpy_async(base + 49152 + off, g_vl + src, 16);
        }
    };

    float o[16][4];
#pragma unroll
    for (int dj = 0; dj < 16; dj++)
#pragma unroll
        for (int q = 0; q < 4; q++) o[dj][q] = 0.f;
    float m0 = -3e38f, m1 = -3e38f, l0 = 0.f, l1 = 0.f;

    fill_kv(0, 0);
    __pipeline_commit();

    for (int t = 0; t < nkv; t++) {
        if (t + 1 < nkv) fill_kv(t + 1, (t + 1) & 1);
        __pipeline_commit();
        __pipeline_wait_prior(1);
        __syncthreads();

        uint32_t st  = sb + 65536 + (uint32_t)(t & 1) * 65536;
        int k0 = t * 64;

        float s[8][4];
#pragma unroll
        for (int nj = 0; nj < 8; nj++)
#pragma unroll
            for (int q = 0; q < 4; q++) s[nj][q] = 0.f;

#pragma unroll
        for (int kk = 0; kk < 8; kk++) {
            uint32_t aqh[4], aql[4];
            int a_row = wq0 + (lane & 15);
            int a_sb  = kk * 2 + ((lane >> 4) & 1);
            uint32_t aaddr = sb + off256(a_row, a_sb);
            ldsm4(aaddr, aqh);
            ldsm4(aaddr + 32768, aql);
            // K fragments: x4 pairs — lanes 16-31 fetch nj+1's rows
            uint32_t Bh[8][2], Bl[8][2];
#pragma unroll
            for (int njp = 0; njp < 4; njp++) {
                int nj = njp * 2;
                int b_row = (nj + (lane >> 4)) * 8 + (lane & 7);
                int b_sb  = kk * 2 + ((lane >> 3) & 1);
                uint32_t baddr = st + off256(b_row, b_sb);
                uint32_t r[4];
                ldsm4(baddr, r);
                Bh[nj][0] = r[0]; Bh[nj][1] = r[1];
                Bh[nj + 1][0] = r[2]; Bh[nj + 1][1] = r[3];
                ldsm4(baddr + 16384, r);
                Bl[nj][0] = r[0]; Bl[nj][1] = r[1];
                Bl[nj + 1][0] = r[2]; Bl[nj + 1][1] = r[3];
            }
#pragma unroll
            for (int nj = 0; nj < 8; nj++) {
                mma16816(s[nj], aqh, Bh[nj]);
                mma16816(s[nj], aql, Bh[nj]);
                mma16816(s[nj], aqh, Bl[nj]);
            }
        }

        if (k0 + 63 > q0 + wq0) {
            int r0 = q0 + wq0 + g, r1 = r0 + 8;
#pragma unroll
            for (int nj = 0; nj < 8; nj++) {
                int col = k0 + nj * 8 + 2 * tig;
                if (col > r0)     s[nj][0] = -1e9f;
                if (col + 1 > r0) s[nj][1] = -1e9f;
                if (col > r1)     s[nj][2] = -1e9f;
                if (col + 1 > r1) s[nj][3] = -1e9f;
            }
        }

        float mx0 = m0, mx1 = m1;
#pragma unroll
        for (int nj = 0; nj < 8; nj++) {
            mx0 = fmaxf(mx0, fmaxf(s[nj][0], s[nj][1]));
            mx1 = fmaxf(mx1, fmaxf(s[nj][2], s[nj][3]));
        }
        mx0 = fmaxf(mx0, __shfl_xor_sync(0xffffffffu, mx0, 1));
        mx0 = fmaxf(mx0, __shfl_xor_sync(0xffffffffu, mx0, 2));
        mx1 = fmaxf(mx1, __shfl_xor_sync(0xffffffffu, mx1, 1));
        mx1 = fmaxf(mx1, __shfl_xor_sync(0xffffffffu, mx1, 2));
        float a0 = __expf(m0 - mx0), a1 = __expf(m1 - mx1);
        m0 = mx0; m1 = mx1;
        l0 *= a0; l1 *= a1;
#pragma unroll
        for (int dj = 0; dj < 16; dj++) {
            o[dj][0] *= a0; o[dj][1] *= a0;
            o[dj][2] *= a1; o[dj][3] *= a1;
        }

        uint32_t phi[8][2], plo[8][2];
#pragma unroll
        for (int nj = 0; nj < 8; nj++) {
            float p00 = __expf(s[nj][0] - mx0), p01 = __expf(s[nj][1] - mx0);
            float p10 = __expf(s[nj][2] - mx1), p11 = __expf(s[nj][3] - mx1);
            l0 += p00 + p01; l1 += p10 + p11;
            float r00, r01, r10, r11;
            float h00 = hhi(p00, r00), h01 = hhi(p01, r01);
            float h10 = hhi(p10, r10), h11 = hhi(p11, r11);
            phi[nj][0] = pkhf(h00, h01); phi[nj][1] = pkhf(h10, h11);
            plo[nj][0] = pkhf(r00, r01); plo[nj][1] = pkhf(r10, r11);
        }

        uint32_t vh_b = st + 32768;
#pragma unroll
        for (int kc = 0; kc < 4; kc++) {
            uint32_t aph[4] = { phi[2 * kc][0], phi[2 * kc][1], phi[2 * kc + 1][0], phi[2 * kc + 1][1] };
            uint32_t apl[4] = { plo[2 * kc][0], plo[2 * kc][1], plo[2 * kc + 1][0], plo[2 * kc + 1][1] };
            // V fragments: x4.trans pairs — lanes 16-31 fetch dj+1's segment
#pragma unroll
            for (int djp = 0; djp < 8; djp++) {
                int dj = djp * 2;
                int v_row = kc * 16 + (lane & 15);
                uint32_t vaddr = vh_b + off256(v_row, dj + (lane >> 4));
                uint32_t rh[4], rl[4];
                ldsm4t(vaddr, rh);
                ldsm4t(vaddr + 16384, rl);
                uint32_t b0[2] = { rh[0], rh[1] }, b1[2] = { rh[2], rh[3] };
                uint32_t c0[2] = { rl[0], rl[1] }, c1[2] = { rl[2], rl[3] };
                mma16816(o[dj], aph, b0);
                mma16816(o[dj], apl, b0);
                mma16816(o[dj], aph, c0);
                mma16816(o[dj + 1], aph, b1);
                mma16816(o[dj + 1], apl, b1);
                mma16816(o[dj + 1], aph, c1);
            }
        }
        __syncthreads();
    }

    l0 += __shfl_xor_sync(0xffffffffu, l0, 1);
    l0 += __shfl_xor_sync(0xffffffffu, l0, 2);
    l1 += __shfl_xor_sync(0xffffffffu, l1, 1);
    l1 += __shfl_xor_sync(0xffffffffu, l1, 2);
    float i0 = 1.0f / l0, i1 = 1.0f / l1;
    int r0 = q0 + wq0 + g, r1 = r0 + 8;
#pragma unroll
    for (int dj = 0; dj < 16; dj++) {
        int cc = dj * 8 + 2 * tig;
        size_t o0 = (size_t)r0 * ATTN_D + h * HDIM + cc;
        size_t o1 = (size_t)r1 * ATTN_D + h * HDIM + cc;
        float ra, rb;
        float v0 = o[dj][0] * i0, v1 = o[dj][1] * i0;
        float h0 = hhi(v0, ra), h1 = hhi(v1, rb);
        *(uint32_t*)(g_attn_hi + o0) = pkhf(h0, h1);
        *(uint32_t*)(g_attn_lo + o0) = pkhf(ra, rb);
        float w0 = o[dj][2] * i1, w1 = o[dj][3] * i1;
        h0 = hhi(w0, ra); h1 = hhi(w1, rb);
        *(uint32_t*)(g_attn_hi + o1) = pkhf(h0, h1);
        *(uint32_t*)(g_attn_lo + o1) = pkhf(ra, rb);
    }
}

// ================= init / final =================
__global__ void init_k(float* __restrict__ out) {
    if (threadIdx.x < NEXP) g_cnt[threadIdx.x] = 0;
    if (threadIdx.x == 0) out[(size_t)S_LEN * DMODEL + S_LEN * NEXP] = 1.0f;
}

__global__ void final_k(float* __restrict__ out) {
    int i = blockIdx.x * 256 + threadIdx.x;   // float4 index
    int t = i / (DMODEL / 4);
    int d = i - t * (DMODEL / 4);
    const float4* h2 = (const float4*)g_hidden2;
    const float4* mp = (const float4*)g_moepart;
    float4 a = h2[i];
    float4 b = mp[(size_t)(2 * t) * (DMODEL / 4) + d];
    float4 c = mp[(size_t)(2 * t + 1) * (DMODEL / 4) + d];
    float4 w;
    w.x = a.x + b.x + c.x; w.y = a.y + b.y + c.y;
    w.z = a.z + b.z + c.z; w.w = a.w + b.w + c.w;
    ((float4*)out)[i] = w;
}

// ================= launch =================
extern "C" void kernel_launch(void* const* d_in, const int* in_sizes, int n_in,
                              void* d_out, int out_size) {
    const float* hs  = (const float*)d_in[0];
    const float* ln1 = (const float*)d_in[1];
    const float* ln2 = (const float*)d_in[2];
    const float* Wq  = (const float*)d_in[3];
    const float* Wk  = (const float*)d_in[4];
    const float* Wv  = (const float*)d_in[5];
    const float* Wo  = (const float*)d_in[6];
    const float* qns = (const float*)d_in[7];
    const float* kns = (const float*)d_in[8];
    const float* rW  = (const float*)d_in[9];
    const float* upW = (const float*)d_in[10];
    const float* upb = (const float*)d_in[11];
    const float* dnW = (const float*)d_in[12];
    const float* dnb = (const float*)d_in[13];
    float* out = (float*)d_out;

    void *wq_hi, *wq_lo, *wk_hi, *wk_lo, *wv_hi, *wv_lo, *wo_hi, *wo_lo, *wup, *wdn;
    cudaGetSymbolAddress(&wq_hi, g_wq_hi);  cudaGetSymbolAddress(&wq_lo, g_wq_lo);
    cudaGetSymbolAddress(&wk_hi, g_wk_hi);  cudaGetSymbolAddress(&wk_lo, g_wk_lo);
    cudaGetSymbolAddress(&wv_hi, g_wv_hi);  cudaGetSymbolAddress(&wv_lo, g_wv_lo);
    cudaGetSymbolAddress(&wo_hi, g_wo_hi);  cudaGetSymbolAddress(&wo_lo, g_wo_lo);
    cudaGetSymbolAddress(&wup, g_wup);      cudaGetSymbolAddress(&wdn, g_wdn);

    cudaFuncSetAttribute(attn_mma_k, cudaFuncAttributeMaxDynamicSharedMemorySize, ATT_SMEM);
    cudaFuncSetAttribute(mma_gemm_k<0>, cudaFuncAttributeMaxDynamicSharedMemorySize, DSMEM);
    cudaFuncSetAttribute(mma_gemm_k<1>, cudaFuncAttributeMaxDynamicSharedMemorySize, DSMEM);
    cudaFuncSetAttribute(mma_gemm_k<2>, cudaFuncAttributeMaxDynamicSharedMemorySize, DSMEM);
    cudaFuncSetAttribute(mma_gemm_k<3>, cudaFuncAttributeMaxDynamicSharedMemorySize, DSMEM);

    // side stream for deferred weight prep (created once; host objects only)
    static cudaStream_t s2 = nullptr;
    static cudaEvent_t evFork = nullptr, evJoin = nullptr;
    if (!s2) {
        cudaStreamCreate(&s2);
        cudaEventCreateWithFlags(&evFork, cudaEventDisableTiming);
        cudaEventCreateWithFlags(&evJoin, cudaEventDisableTiming);
    }

    // ---- fork: Wo split + MoE converts on s2 (not needed until after attention) ----
    cudaEventRecord(evFork, 0);
    cudaStreamWaitEvent(s2, evFork, 0);
    split_k<<<(ATTN_D * DMODEL) / 2048, 256, 0, s2>>>((const float4*)Wo, (uint2*)wo_hi, (uint2*)wo_lo);
    convert_k<<<(NEXP * DMODEL * FDIM) / 2048, 256, 0, s2>>>((const float4*)upW, (uint2*)wup);
    convert_k<<<(NEXP * FDIM * DMODEL) / 2048, 256, 0, s2>>>((const float4*)dnW, (uint2*)wdn);
    cudaEventRecord(evJoin, s2);

    // ---- main chain on stream 0 ----
    split_k<<<(DMODEL * ATTN_D) / 2048, 256>>>((const float4*)Wq, (uint2*)wq_hi, (uint2*)wq_lo);
    split_k<<<(DMODEL * 512) / 2048, 256>>>((const float4*)Wk, (uint2*)wk_hi, (uint2*)wk_lo);
    split_k<<<(DMODEL * 512) / 2048, 256>>>((const float4*)Wv, (uint2*)wv_hi, (uint2*)wv_lo);

    // 1. rmsnorm1 -> fp16 hi/lo
    rmsnorm1_split_k<<<S_LEN, 256>>>(hs, ln1);
    // 2. fused QKV projection; Q/K epilogue does qknorm+rope+split, V split direct
    mma_gemm_k<0><<<dim3(QKV_N / 128, S_LEN / 128), 256, DSMEM>>>(qns, kns);
    // 3. HMMA flash attention -> g_attn hi/lo
    attn_mma_k<<<dim3(S_LEN / 128, NHQ), 256, ATT_SMEM>>>();
    // ---- join: Wo weights (and MoE weights) ready ----
    cudaStreamWaitEvent(0, evJoin, 0);
    // 4. output projection + residual
    mma_gemm_k<1><<<dim3(DMODEL / 128, S_LEN / 128), 256, DSMEM>>>(hs, nullptr);
    // 5. fused rmsnorm2 + router (init first: zero counts, write aux)
    init_k<<<1, 32>>>(out);
    rmsnorm2_router_k<<<S_LEN, 256>>>(ln2, rW, out);
    // 6. MoE (gathered rows, 1-term fp16)
    mma_gemm_k<2><<<dim3(FDIM / 128, 16, NEXP), 256, DSMEM>>>(nullptr, upb);
    mma_gemm_k<3><<<dim3(DMODEL / 128, 16, NEXP), 256, DSMEM>>>(nullptr, dnb);
    // 7. final residual + MoE sum
    final_k<<<(S_LEN * DMODEL / 4) / 256, 256>>>(out);
}

// round 16
// speedup vs baseline: 6.2743x; 1.0052x over previous
#include <cuda_runtime.h>
#include <cuda_fp16.h>
#include <cuda_pipeline.h>
#include <math.h>
#include <stdint.h>

#define S_LEN 2048
#define DMODEL 2048
#define QKV_N 5120
#define NHQ 32
#define NHKV 4
#define HDIM 128
#define NEXP 8
#define FDIM 768
#define EPSV 1e-6f
#define ATTN_D (NHQ * HDIM)   // 4096

typedef __half f16;

// ================= scratch (device globals; no allocations allowed) =================
__device__ __align__(256) f16   g_x_hi[S_LEN * DMODEL];
__device__ __align__(256) f16   g_x_lo[S_LEN * DMODEL];
__device__ __align__(256) f16   g_qh[S_LEN * NHQ * HDIM];
__device__ __align__(256) f16   g_ql[S_LEN * NHQ * HDIM];
__device__ __align__(256) f16   g_kh[NHKV * S_LEN * HDIM];
__device__ __align__(256) f16   g_kl[NHKV * S_LEN * HDIM];
__device__ __align__(256) f16   g_vh[NHKV * S_LEN * HDIM];
__device__ __align__(256) f16   g_vl[NHKV * S_LEN * HDIM];
__device__ __align__(256) f16   g_attn_hi[S_LEN * ATTN_D];
__device__ __align__(256) f16   g_attn_lo[S_LEN * ATTN_D];
__device__ __align__(256) float g_hidden2[S_LEN * DMODEL];
__device__ __align__(256) f16   g_xf_hi[S_LEN * DMODEL];
__device__ __align__(256) f16   g_h_hi[S_LEN * 2 * FDIM];
__device__ __align__(256) float g_moepart[S_LEN * 2 * DMODEL];
__device__ float g_gate[S_LEN * 2];
__device__ int   g_cnt[NEXP];
__device__ int   g_list[NEXP][S_LEN];
// weights in NATIVE [K, N] layout; QKV/Wo split hi/lo (3-term), MoE single (1-term)
__device__ __align__(256) f16 g_wq_hi[DMODEL * ATTN_D];
__device__ __align__(256) f16 g_wq_lo[DMODEL * ATTN_D];
__device__ __align__(256) f16 g_wk_hi[DMODEL * 512];
__device__ __align__(256) f16 g_wk_lo[DMODEL * 512];
__device__ __align__(256) f16 g_wv_hi[DMODEL * 512];
__device__ __align__(256) f16 g_wv_lo[DMODEL * 512];
__device__ __align__(256) f16 g_wo_hi[ATTN_D * DMODEL];
__device__ __align__(256) f16 g_wo_lo[ATTN_D * DMODEL];
__device__ __align__(256) f16 g_wup[NEXP * DMODEL * FDIM];
__device__ __align__(256) f16 g_wdn[NEXP * FDIM * DMODEL];

// ================= PTX helpers =================
__device__ __forceinline__ uint32_t smem_u32(const void* p) {
    uint32_t a;
    asm("{ .reg .u64 t; cvta.to.shared.u64 t, %1; cvt.u32.u64 %0, t; }" : "=r"(a) : "l"(p));
    return a;
}
__device__ __forceinline__ void ldsm4(uint32_t a, uint32_t r[4]) {
    asm volatile("ldmatrix.sync.aligned.m8n8.x4.shared.b16 {%0,%1,%2,%3}, [%4];"
                 : "=r"(r[0]), "=r"(r[1]), "=r"(r[2]), "=r"(r[3]) : "r"(a));
}
__device__ __forceinline__ void ldsm4t(uint32_t a, uint32_t r[4]) {
    asm volatile("ldmatrix.sync.aligned.m8n8.x4.trans.shared.b16 {%0,%1,%2,%3}, [%4];"
                 : "=r"(r[0]), "=r"(r[1]), "=r"(r[2]), "=r"(r[3]) : "r"(a));
}
__device__ __forceinline__ void mma16816(float c[4], const uint32_t a[4], const uint32_t b[2]) {
    asm volatile(
        "mma.sync.aligned.m16n8k16.row.col.f32.f16.f16.f32 "
        "{%0,%1,%2,%3}, {%4,%5,%6,%7}, {%8,%9}, {%0,%1,%2,%3};"
        : "+f"(c[0]), "+f"(c[1]), "+f"(c[2]), "+f"(c[3])
        : "r"(a[0]), "r"(a[1]), "r"(a[2]), "r"(a[3]), "r"(b[0]), "r"(b[1]));
}
__device__ __forceinline__ uint32_t lds_addr(uint32_t base, int row, int kbyte) {
    int seg = kbyte >> 4;
    return base + row * 128 + (((uint32_t)(seg ^ (row & 7))) << 4);
}
__device__ __forceinline__ int off256(int row, int seg) {
    return row * 256 + ((seg ^ (row & 7)) << 4);
}
__device__ __forceinline__ uint32_t pkhf(float x, float y) {
    __half2 t = __floats2half2_rn(x, y);
    return *reinterpret_cast<uint32_t*>(&t);
}
__device__ __forceinline__ float hhi(float x, float& r) {
    float h = __half2float(__float2half_rn(x));
    r = x - h;
    return h;
}

// ================= weight prep (2 float4 per thread) =================
__global__ void split_k(const float4* __restrict__ in, uint2* __restrict__ hi,
                        uint2* __restrict__ lo) {
    size_t base = (size_t)blockIdx.x * 512 + threadIdx.x;
#pragma unroll
    for (int u = 0; u < 2; u++) {
        size_t i = base + u * 256;
        float4 v = in[i];
        float r0, r1, r2, r3;
        float h0 = hhi(v.x, r0), h1 = hhi(v.y, r1), h2 = hhi(v.z, r2), h3 = hhi(v.w, r3);
        hi[i] = make_uint2(pkhf(h0, h1), pkhf(h2, h3));
        lo[i] = make_uint2(pkhf(r0, r1), pkhf(r2, r3));
    }
}
__global__ void convert_k(const float4* __restrict__ in, uint2* __restrict__ out) {
    size_t base = (size_t)blockIdx.x * 512 + threadIdx.x;
#pragma unroll
    for (int u = 0; u < 2; u++) {
        size_t i = base + u * 256;
        float4 v = in[i];
        out[i] = make_uint2(pkhf(v.x, v.y), pkhf(v.z, v.w));
    }
}

// ================= rmsnorm1 =================
__global__ void rmsnorm1_split_k(const float* __restrict__ in, const float* __restrict__ sc) {
    int row = blockIdx.x;
    const float* r = in + (size_t)row * DMODEL;
    float ss = 0.f;
    for (int i = threadIdx.x; i < DMODEL; i += 256) { float v = r[i]; ss += v * v; }
    for (int o = 16; o; o >>= 1) ss += __shfl_xor_sync(0xffffffffu, ss, o);
    __shared__ float red[8];
    if ((threadIdx.x & 31) == 0) red[threadIdx.x >> 5] = ss;
    __syncthreads();
    float tot = 0.f;
#pragma unroll
    for (int i = 0; i < 8; i++) tot += red[i];
    float inv = rsqrtf(tot / (float)DMODEL + EPSV);
    for (int i = threadIdx.x; i < DMODEL; i += 256) {
        float w = r[i] * inv * sc[i];
        float rem;
        float h = hhi(w, rem);
        size_t o = (size_t)row * DMODEL + i;
        g_x_hi[o] = __float2half_rn(h);
        g_x_lo[o] = __float2half_rn(rem);
    }
}

// ================= fused rmsnorm2 + router =================
__global__ void rmsnorm2_router_k(const float* __restrict__ sc, const float* __restrict__ rW,
                                  float* __restrict__ out) {
    __shared__ float xs[DMODEL];
    __shared__ float red[8];
    __shared__ float lg[NEXP];
    int row = blockIdx.x;
    int tid = threadIdx.x;
    const float4* r4 = (const float4*)(g_hidden2 + (size_t)row * DMODEL);
    const float4* s4 = (const float4*)sc;
    float4 v0 = r4[tid], v1 = r4[tid + 256];
    float ss = v0.x * v0.x + v0.y * v0.y + v0.z * v0.z + v0.w * v0.w
             + v1.x * v1.x + v1.y * v1.y + v1.z * v1.z + v1.w * v1.w;
    for (int o = 16; o; o >>= 1) ss += __shfl_xor_sync(0xffffffffu, ss, o);
    if ((tid & 31) == 0) red[tid >> 5] = ss;
    __syncthreads();
    float tot = 0.f;
#pragma unroll
    for (int i = 0; i < 8; i++) tot += red[i];
    float inv = rsqrtf(tot / (float)DMODEL + EPSV);
    float4 c0 = s4[tid], c1 = s4[tid + 256];
    float w0 = v0.x * inv * c0.x, w1 = v0.y * inv * c0.y;
    float w2 = v0.z * inv * c0.z, w3 = v0.w * inv * c0.w;
    float u0 = v1.x * inv * c1.x, u1 = v1.y * inv * c1.y;
    float u2 = v1.z * inv * c1.z, u3 = v1.w * inv * c1.w;
    xs[4 * tid] = w0; xs[4 * tid + 1] = w1; xs[4 * tid + 2] = w2; xs[4 * tid + 3] = w3;
    int t2 = tid + 256;
    xs[4 * t2] = u0; xs[4 * t2 + 1] = u1; xs[4 * t2 + 2] = u2; xs[4 * t2 + 3] = u3;
    size_t ob = (size_t)row * DMODEL;
    *(uint2*)(g_xf_hi + ob + 4 * tid) = make_uint2(pkhf(w0, w1), pkhf(w2, w3));
    *(uint2*)(g_xf_hi + ob + 4 * t2)  = make_uint2(pkhf(u0, u1), pkhf(u2, u3));
    __syncthreads();
    int w = tid >> 5, lane = tid & 31;
    float sum = 0.f;
    for (int dd = lane; dd < DMODEL; dd += 32) sum += xs[dd] * rW[dd * NEXP + w];
    for (int o = 16; o; o >>= 1) sum += __shfl_xor_sync(0xffffffffu, sum, o);
    if (lane == 0) lg[w] = sum;
    __syncthreads();
    if (tid == 0) {
        float* lo = out + (size_t)S_LEN * DMODEL + (size_t)row * NEXP;
        float mx = lg[0];
#pragma unroll
        for (int e = 1; e < NEXP; e++) mx = fmaxf(mx, lg[e]);
        float p[NEXP];
#pragma unroll
        for (int e = 0; e < NEXP; e++) { p[e] = expf(lg[e] - mx); lo[e] = lg[e]; }
        int i1 = 0;
#pragma unroll
        for (int e = 1; e < NEXP; e++) if (lg[e] > lg[i1]) i1 = e;
        int i2 = -1;
#pragma unroll
        for (int e = 0; e < NEXP; e++) {
            if (e == i1) continue;
            if (i2 < 0 || lg[e] > lg[i2]) i2 = e;
        }
        float denom = p[i1] + p[i2];
        g_gate[row * 2]     = p[i1] / denom;
        g_gate[row * 2 + 1] = p[i2] / denom;
        int pos = atomicAdd(&g_cnt[i1], 1);
        g_list[i1][pos] = row * 2;
        pos = atomicAdd(&g_cnt[i2], 1);
        g_list[i2][pos] = row * 2 + 1;
    }
}

// ================= HMMA GEMM (B native [K,N] via paired ldmatrix.x4.trans) =========
#define STAGE_BYTES 65536
#define DSMEM (3 * STAGE_BYTES + 1024)

template<int MODE>
__global__ __launch_bounds__(256, 1) void mma_gemm_k(const float* __restrict__ arg0,
                                                     const float* __restrict__ arg1) {
    constexpr int K   = (MODE == 1) ? ATTN_D : (MODE == 3) ? FDIM : DMODEL;
    constexpr int NCH = K / 64;
    constexpr bool THREE = (MODE < 2);

    extern __shared__ char dyn[];
    __shared__ int rows_s[128];

    int tid = threadIdx.x, wid = tid >> 5, lane = tid & 31;
    int e = blockIdx.z;
    int m0 = blockIdx.y * 128;
    int n0 = blockIdx.x * 128;

    int cnt = 0;
    if (MODE >= 2) {
        cnt = g_cnt[e];
        if (m0 >= cnt) return;
        if (tid < 128)
            rows_s[tid] = (m0 + tid < cnt) ? g_list[e][m0 + tid] : g_list[e][0];
        __syncthreads();
    }

    const f16 *Ahi, *Alo = nullptr, *Bhi, *Blo = nullptr;
    int ldB, bn;
    if (MODE == 0) {
        Ahi = g_x_hi; Alo = g_x_lo;
        if (n0 < 4096)      { Bhi = g_wq_hi; Blo = g_wq_lo; ldB = 4096; bn = n0; }
        else if (n0 < 4608) { Bhi = g_wk_hi; Blo = g_wk_lo; ldB = 512;  bn = n0 - 4096; }
        else                { Bhi = g_wv_hi; Blo = g_wv_lo; ldB = 512;  bn = n0 - 4608; }
    } else if (MODE == 1) {
        Ahi = g_attn_hi; Alo = g_attn_lo; Bhi = g_wo_hi; Blo = g_wo_lo; ldB = DMODEL; bn = n0;
    } else if (MODE == 2) {
        Ahi = g_xf_hi;
        Bhi = g_wup + (size_t)e * DMODEL * FDIM;
        ldB = FDIM; bn = n0;
    } else {
        Ahi = g_h_hi;
        Bhi = g_wdn + (size_t)e * FDIM * DMODEL;
        ldB = DMODEL; bn = n0;
    }

    uint32_t dyn_u = smem_u32(dyn);
    uint32_t tile0 = (dyn_u + 1023u) & ~1023u;
    char* tile0p = dyn + (tile0 - dyn_u);

    auto load_chunk = [&](int c, int s) {
        char* st = tile0p + s * STAGE_BYTES;
        for (int l = tid; l < 1024; l += 256) {
            int row = l >> 3, seg = l & 7;
            uint32_t off = (uint32_t)(row * 128 + seg * 16);
            uint32_t sw = off ^ ((off >> 3) & 0x70);
            size_t ar;
            if (MODE == 2)      ar = (size_t)(rows_s[row] >> 1) * K;
            else if (MODE == 3) ar = (size_t)rows_s[row] * K;
            else                ar = (size_t)(m0 + row) * K;
            __pipeline_memcpy_async(st + sw, (const char*)(Ahi + ar + (size_t)c * 64) + seg * 16, 16);
            if (THREE)
                __pipeline_memcpy_async(st + 16384 + sw, (const char*)(Alo + ar + (size_t)c * 64) + seg * 16, 16);
        }
        for (int l = tid; l < 1024; l += 256) {
            int row = l >> 4, seg = l & 15;
            int off = off256(row, seg);
            size_t src = (size_t)(c * 64 + row) * ldB + bn + seg * 8;
            __pipeline_memcpy_async(st + 32768 + off, (const char*)(Bhi + src), 16);
            if (THREE)
                __pipeline_memcpy_async(st + 49152 + off, (const char*)(Blo + src), 16);
        }
    };

    int warp_m0 = (wid >> 2) * 64;
    int warp_n0 = (wid & 3) * 32;
    int bseg0 = warp_n0 >> 3;
    int g = lane >> 2, tig = lane & 3;

    float c[4][4][4];
#pragma unroll
    for (int mi = 0; mi < 4; mi++)
#pragma unroll
        for (int nj = 0; nj < 4; nj++)
#pragma unroll
            for (int q = 0; q < 4; q++) c[mi][nj][q] = 0.f;

    load_chunk(0, 0);
    __pipeline_commit();
    load_chunk(1, 1);
    __pipeline_commit();

    for (int i = 0; i < NCH; i++) {
        __pipeline_wait_prior(1);
        __syncthreads();
        if (i + 2 < NCH) load_chunk(i + 2, (i + 2) % 3);
        __pipeline_commit();

        uint32_t su  = tile0 + (uint32_t)(i % 3) * STAGE_BYTES;
        uint32_t aHiB = su, aLoB = su + 16384, bHiB = su + 32768;

#pragma unroll
        for (int kk = 0; kk < 4; kk++) {
            uint32_t Ah[4][4], Al[4][4], Bh[4][2], Bl[4][2];
            int a_row = lane & 15;
            int a_kb  = 32 * kk + ((lane >> 4) << 4);
#pragma unroll
            for (int mi = 0; mi < 4; mi++) {
                int row = warp_m0 + 16 * mi + a_row;
                ldsm4(lds_addr(aHiB, row, a_kb), Ah[mi]);
                if (THREE) ldsm4(lds_addr(aLoB, row, a_kb), Al[mi]);
            }
            // B fragments: x4.trans pairs — lanes 16-31 fetch nj+1's segment
            int b_row = 16 * kk + (lane & 15);
#pragma unroll
            for (int njp = 0; njp < 2; njp++) {
                int nj = njp * 2;
                uint32_t r[4];
                uint32_t baddr = bHiB + off256(b_row, bseg0 + nj + (lane >> 4));
                ldsm4t(baddr, r);
                Bh[nj][0] = r[0]; Bh[nj][1] = r[1];
                Bh[nj + 1][0] = r[2]; Bh[nj + 1][1] = r[3];
                if (THREE) {
                    ldsm4t(baddr + 16384, r);
                    Bl[nj][0] = r[0]; Bl[nj][1] = r[1];
                    Bl[nj + 1][0] = r[2]; Bl[nj + 1][1] = r[3];
                }
            }
#pragma unroll
            for (int mi = 0; mi < 4; mi++)
#pragma unroll
                for (int nj = 0; nj < 4; nj++) {
                    mma16816(c[mi][nj], Ah[mi], Bh[nj]);
                    if (THREE) {
                        mma16816(c[mi][nj], Al[mi], Bh[nj]);
                        mma16816(c[mi][nj], Ah[mi], Bl[nj]);
                    }
                }
        }
    }

    // ---------- MODE 0 Q/K: fused qknorm + rope + fp16 split ----------
    if (MODE == 0 && n0 < 4608) {
        __syncthreads();   // all warps done computing before smem reuse
        float* S = (float*)tile0p;   // 128 x 132 fp32
#pragma unroll
        for (int mi = 0; mi < 4; mi++)
#pragma unroll
            for (int hh = 0; hh < 2; hh++) {
                int rl = warp_m0 + 16 * mi + 8 * hh + g;
#pragma unroll
                for (int nj = 0; nj < 4; nj++) {
                    int colL = warp_n0 + 8 * nj + 2 * tig;
                    S[rl * 132 + colL]     = c[mi][nj][2 * hh];
                    S[rl * 132 + colL + 1] = c[mi][nj][2 * hh + 1];
                }
            }
        __syncthreads();
        int isK = (n0 >= 4096);
        int head = (isK ? (n0 - 4096) : n0) >> 7;
        const float* sc = isK ? arg1 : arg0;
        f16* dsth = isK ? g_kh : g_qh;
        f16* dstl = isK ? g_kl : g_ql;
        // hoisted per-thread constants (d-dependent only)
        float invf[4], scd[4], scod[4];
        int odx[4];
#pragma unroll
        for (int k = 0; k < 4; k++) {
            int d = lane * 4 + k;
            int j = d & 63;
            invf[k] = expf(-0.21586735246819178f * (float)j);
            scd[k] = sc[d];
            odx[k] = (d < 64) ? d + 64 : d - 64;
            scod[k] = sc[odx[k]];
        }
        float qscale = isK ? 1.0f : 0.08838834764831845f;
        for (int rr = 0; rr < 16; rr++) {
            int row = wid * 16 + rr;
            const float* Sr = S + row * 132;
            float v[4];
            float ss = 0.f;
#pragma unroll
            for (int k = 0; k < 4; k++) { v[k] = Sr[lane * 4 + k]; ss += v[k] * v[k]; }
#pragma unroll
            for (int o = 16; o; o >>= 1) ss += __shfl_xor_sync(0xffffffffu, ss, o);
            float inv = rsqrtf(ss * (1.0f / 128.0f) + EPSV);
            int sg = m0 + row;
            uint32_t hiW[2], loW[2];
#pragma unroll
            for (int kp = 0; kp < 2; kp++) {
                float outv[2], remv[2];
#pragma unroll
                for (int k2 = 0; k2 < 2; k2++) {
                    int k = kp * 2 + k2;
                    int d = lane * 4 + k;
                    float n = v[k] * inv * scd[k];
                    float ang = (float)sg * invf[k];
                    float si, co;
                    sincosf(ang, &si, &co);
                    float no = Sr[odx[k]] * inv * scod[k];
                    float rot = (d < 64) ? -no : no;
                    float val = (n * co + rot * si) * qscale;
                    outv[k2] = hhi(val, remv[k2]);
                }
                hiW[kp] = pkhf(outv[0], outv[1]);
                loW[kp] = pkhf(remv[0], remv[1]);
            }
            size_t o = isK ? (((size_t)head * S_LEN + sg) * HDIM + lane * 4)
                           : (((size_t)sg * NHQ + head) * HDIM + lane * 4);
            *(uint2*)(dsth + o) = make_uint2(hiW[0], hiW[1]);
            *(uint2*)(dstl + o) = make_uint2(loW[0], loW[1]);
        }
        return;
    }

    // ---------------- generic epilogue ----------------
#pragma unroll
    for (int mi = 0; mi < 4; mi++) {
#pragma unroll
        for (int hh = 0; hh < 2; hh++) {
            int rl = warp_m0 + 16 * mi + 8 * hh + g;
            int grow = m0 + rl;
            bool valid = true;
            int slot = 0;
            if (MODE >= 2) { valid = grow < cnt; slot = rows_s[rl]; }
#pragma unroll
            for (int nj = 0; nj < 4; nj++) {
                int col = n0 + warp_n0 + 8 * nj + 2 * tig;
                float v0 = c[mi][nj][2 * hh];
                float v1 = c[mi][nj][2 * hh + 1];
                if (MODE == 0) {
                    // V columns only (n0 >= 4608)
                    int cc = col - 4608;
                    int kvh = cc >> 7, d = cc & 127;
                    size_t o = ((size_t)kvh * S_LEN + grow) * HDIM + d;
                    float r0, r1;
                    float h0 = hhi(v0, r0), h1 = hhi(v1, r1);
                    *(uint32_t*)(g_vh + o) = pkhf(h0, h1);
                    *(uint32_t*)(g_vl + o) = pkhf(r0, r1);
                } else if (MODE == 1) {
                    size_t base = (size_t)grow * DMODEL + col;
                    g_hidden2[base]     = v0 + arg0[base];
                    g_hidden2[base + 1] = v1 + arg0[base + 1];
                } else if (MODE == 2) {
                    if (valid) {
                        const float* bia = arg1 + e * FDIM;
                        float va = v0 + bia[col], vb = v1 + bia[col + 1];
                        float sa = va / (1.0f + expf(-va));
                        float sb = vb / (1.0f + expf(-vb));
                        *(uint32_t*)(g_h_hi + (size_t)slot * FDIM + col) = pkhf(sa, sb);
                    }
                } else {
                    if (valid) {
                        const float* bia = arg1 + e * DMODEL;
                        float gt = g_gate[slot];
                        *(float2*)(g_moepart + (size_t)slot * DMODEL + col) =
                            make_float2(gt * (v0 + bia[col]), gt * (v1 + bia[col + 1]));
                    }
                }
            }
        }
    }
}

// ================= HMMA flash attention (fp16, 3-term, single-sync loop) =================
#define ATT_SMEM (65536 + 2 * 65536)
__global__ __launch_bounds__(256, 1) void attn_mma_k() {
    extern __shared__ char sm[];
    uint32_t sb = smem_u32(sm);
    int qi = gridDim.x - 1 - blockIdx.x;   // heaviest tiles first
    int h = blockIdx.y;
    int q0 = qi * 128, kvh = h >> 3;
    int nkv = 2 * (qi + 1);
    int tid = threadIdx.x, wid = tid >> 5, lane = tid & 31;
    int g = lane >> 2, tig = lane & 3;
    int wq0 = wid * 16;

    for (int l = tid; l < 2048; l += 256) {
        int row = l >> 4, seg = l & 15;
        int off = off256(row, seg);
        size_t src = ((size_t)(q0 + row) * NHQ + h) * HDIM + seg * 8;
        __pipeline_memcpy_async(sm + off,         g_qh + src, 16);
        __pipeline_memcpy_async(sm + 32768 + off, g_ql + src, 16);
    }

    auto fill_kv = [&](int t, int st) {
        char* base = sm + 65536 + st * 65536;
        int kv0 = t * 64;
        for (int l = tid; l < 1024; l += 256) {
            int row = l >> 4, seg = l & 15;
            int off = off256(row, seg);
            size_t src = ((size_t)kvh * S_LEN + kv0 + row) * HDIM + seg * 8;
            __pipeline_memcpy_async(base + off,         g_kh + src, 16);
            __pipeline_memcpy_async(base + 16384 + off, g_kl + src, 16);
            __pipeline_memcpy_async(base + 32768 + off, g_vh + src, 16);
            __pipeline_memcpy_async(base + 49152 + off, g_vl + src, 16);
        }
    };

    float o[16][4];
#pragma unroll
    for (int dj = 0; dj < 16; dj++)
#pragma unroll
        for (int q = 0; q < 4; q++) o[dj][q] = 0.f;
    float m0 = -3e38f, m1 = -3e38f, l0 = 0.f, l1 = 0.f;

    fill_kv(0, 0);
    __pipeline_commit();

    for (int t = 0; t < nkv; t++) {
        __pipeline_wait_prior(0);      // fill t (and Q on t=0) complete
        __syncthreads();               // all warps past compute t-1
        if (t + 1 < nkv) { fill_kv(t + 1, (t + 1) & 1); __pipeline_commit(); }

        uint32_t st  = sb + 65536 + (uint32_t)(t & 1) * 65536;
        int k0 = t * 64;

        float s[8][4];
#pragma unroll
        for (int nj = 0; nj < 8; nj++)
#pragma unroll
            for (int q = 0; q < 4; q++) s[nj][q] = 0.f;

#pragma unroll
        for (int kk = 0; kk < 8; kk++) {
            uint32_t aqh[4], aql[4];
            int a_row = wq0 + (lane & 15);
            int a_sb  = kk * 2 + ((lane >> 4) & 1);
            uint32_t aaddr = sb + off256(a_row, a_sb);
            ldsm4(aaddr, aqh);
            ldsm4(aaddr + 32768, aql);
            // K fragments: x4 pairs — lanes 16-31 fetch nj+1's rows
            uint32_t Bh[8][2], Bl[8][2];
#pragma unroll
            for (int njp = 0; njp < 4; njp++) {
                int nj = njp * 2;
                int b_row = (nj + (lane >> 4)) * 8 + (lane & 7);
                int b_sb  = kk * 2 + ((lane >> 3) & 1);
                uint32_t baddr = st + off256(b_row, b_sb);
                uint32_t r[4];
                ldsm4(baddr, r);
                Bh[nj][0] = r[0]; Bh[nj][1] = r[1];
                Bh[nj + 1][0] = r[2]; Bh[nj + 1][1] = r[3];
                ldsm4(baddr + 16384, r);
                Bl[nj][0] = r[0]; Bl[nj][1] = r[1];
                Bl[nj + 1][0] = r[2]; Bl[nj + 1][1] = r[3];
            }
#pragma unroll
            for (int nj = 0; nj < 8; nj++) {
                mma16816(s[nj], aqh, Bh[nj]);
                mma16816(s[nj], aql, Bh[nj]);
                mma16816(s[nj], aqh, Bl[nj]);
            }
        }

        if (k0 + 63 > q0 + wq0) {
            int r0 = q0 + wq0 + g, r1 = r0 + 8;
#pragma unroll
            for (int nj = 0; nj < 8; nj++) {
                int col = k0 + nj * 8 + 2 * tig;
                if (col > r0)     s[nj][0] = -1e9f;
                if (col + 1 > r0) s[nj][1] = -1e9f;
                if (col > r1)     s[nj][2] = -1e9f;
                if (col + 1 > r1) s[nj][3] = -1e9f;
            }
        }

        float mx0 = m0, mx1 = m1;
#pragma unroll
        for (int nj = 0; nj < 8; nj++) {
            mx0 = fmaxf(mx0, fmaxf(s[nj][0], s[nj][1]));
            mx1 = fmaxf(mx1, fmaxf(s[nj][2], s[nj][3]));
        }
        mx0 = fmaxf(mx0, __shfl_xor_sync(0xffffffffu, mx0, 1));
        mx0 = fmaxf(mx0, __shfl_xor_sync(0xffffffffu, mx0, 2));
        mx1 = fmaxf(mx1, __shfl_xor_sync(0xffffffffu, mx1, 1));
        mx1 = fmaxf(mx1, __shfl_xor_sync(0xffffffffu, mx1, 2));
        float a0 = __expf(m0 - mx0), a1 = __expf(m1 - mx1);
        m0 = mx0; m1 = mx1;
        l0 *= a0; l1 *= a1;
#pragma unroll
        for (int dj = 0; dj < 16; dj++) {
            o[dj][0] *= a0; o[dj][1] *= a0;
            o[dj][2] *= a1; o[dj][3] *= a1;
        }

        uint32_t phi[8][2], plo[8][2];
#pragma unroll
        for (int nj = 0; nj < 8; nj++) {
            float p00 = __expf(s[nj][0] - mx0), p01 = __expf(s[nj][1] - mx0);
            float p10 = __expf(s[nj][2] - mx1), p11 = __expf(s[nj][3] - mx1);
            l0 += p00 + p01; l1 += p10 + p11;
            float r00, r01, r10, r11;
            float h00 = hhi(p00, r00), h01 = hhi(p01, r01);
            float h10 = hhi(p10, r10), h11 = hhi(p11, r11);
            phi[nj][0] = pkhf(h00, h01); phi[nj][1] = pkhf(h10, h11);
            plo[nj][0] = pkhf(r00, r01); plo[nj][1] = pkhf(r10, r11);
        }

        uint32_t vh_b = st + 32768;
#pragma unroll
        for (int kc = 0; kc < 4; kc++) {
            uint32_t aph[4] = { phi[2 * kc][0], phi[2 * kc][1], phi[2 * kc + 1][0], phi[2 * kc + 1][1] };
            uint32_t apl[4] = { plo[2 * kc][0], plo[2 * kc][1], plo[2 * kc + 1][0], plo[2 * kc + 1][1] };
            // V fragments: x4.trans pairs — lanes 16-31 fetch dj+1's segment
#pragma unroll
            for (int djp = 0; djp < 8; djp++) {
                int dj = djp * 2;
                int v_row = kc * 16 + (lane & 15);
                uint32_t vaddr = vh_b + off256(v_row, dj + (lane >> 4));
                uint32_t rh[4], rl[4];
                ldsm4t(vaddr, rh);
                ldsm4t(vaddr + 16384, rl);
                uint32_t b0[2] = { rh[0], rh[1] }, b1[2] = { rh[2], rh[3] };
                uint32_t c0[2] = { rl[0], rl[1] }, c1[2] = { rl[2], rl[3] };
                mma16816(o[dj], aph, b0);
                mma16816(o[dj], apl, b0);
                mma16816(o[dj], aph, c0);
                mma16816(o[dj + 1], aph, b1);
                mma16816(o[dj + 1], apl, b1);
                mma16816(o[dj + 1], aph, c1);
            }
        }
    }

    l0 += __shfl_xor_sync(0xffffffffu, l0, 1);
    l0 += __shfl_xor_sync(0xffffffffu, l0, 2);
    l1 += __shfl_xor_sync(0xffffffffu, l1, 1);
    l1 += __shfl_xor_sync(0xffffffffu, l1, 2);
    float i0 = 1.0f / l0, i1 = 1.0f / l1;
    int r0 = q0 + wq0 + g, r1 = r0 + 8;
#pragma unroll
    for (int dj = 0; dj < 16; dj++) {
        int cc = dj * 8 + 2 * tig;
        size_t o0 = (size_t)r0 * ATTN_D + h * HDIM + cc;
        size_t o1 = (size_t)r1 * ATTN_D + h * HDIM + cc;
        float ra, rb;
        float v0 = o[dj][0] * i0, v1 = o[dj][1] * i0;
        float h0 = hhi(v0, ra), h1 = hhi(v1, rb);
        *(uint32_t*)(g_attn_hi + o0) = pkhf(h0, h1);
        *(uint32_t*)(g_attn_lo + o0) = pkhf(ra, rb);
        float w0 = o[dj][2] * i1, w1 = o[dj][3] * i1;
        h0 = hhi(w0, ra); h1 = hhi(w1, rb);
        *(uint32_t*)(g_attn_hi + o1) = pkhf(h0, h1);
        *(uint32_t*)(g_attn_lo + o1) = pkhf(ra, rb);
    }
}

// ================= init / final =================
__global__ void init_k(float* __restrict__ out) {
    if (threadIdx.x < NEXP) g_cnt[threadIdx.x] = 0;
    if (threadIdx.x == 0) out[(size_t)S_LEN * DMODEL + S_LEN * NEXP] = 1.0f;
}

__global__ void final_k(float* __restrict__ out) {
    int i = blockIdx.x * 256 + threadIdx.x;   // float4 index
    int t = i / (DMODEL / 4);
    int d = i - t * (DMODEL / 4);
    const float4* h2 = (const float4*)g_hidden2;
    const float4* mp = (const float4*)g_moepart;
    float4 a = h2[i];
    float4 b = mp[(size_t)(2 * t) * (DMODEL / 4) + d];
    float4 c = mp[(size_t)(2 * t + 1) * (DMODEL / 4) + d];
    float4 w;
    w.x = a.x + b.x + c.x; w.y = a.y + b.y + c.y;
    w.z = a.z + b.z + c.z; w.w = a.w + b.w + c.w;
    ((float4*)out)[i] = w;
}

// ================= launch =================
extern "C" void kernel_launch(void* const* d_in, const int* in_sizes, int n_in,
                              void* d_out, int out_size) {
    const float* hs  = (const float*)d_in[0];
    const float* ln1 = (const float*)d_in[1];
    const float* ln2 = (const float*)d_in[2];
    const float* Wq  = (const float*)d_in[3];
    const float* Wk  = (const float*)d_in[4];
    const float* Wv  = (const float*)d_in[5];
    const float* Wo  = (const float*)d_in[6];
    const float* qns = (const float*)d_in[7];
    const float* kns = (const float*)d_in[8];
    const float* rW  = (const float*)d_in[9];
    const float* upW = (const float*)d_in[10];
    const float* upb = (const float*)d_in[11];
    const float* dnW = (const float*)d_in[12];
    const float* dnb = (const float*)d_in[13];
    float* out = (float*)d_out;

    void *wq_hi, *wq_lo, *wk_hi, *wk_lo, *wv_hi, *wv_lo, *wo_hi, *wo_lo, *wup, *wdn;
    cudaGetSymbolAddress(&wq_hi, g_wq_hi);  cudaGetSymbolAddress(&wq_lo, g_wq_lo);
    cudaGetSymbolAddress(&wk_hi, g_wk_hi);  cudaGetSymbolAddress(&wk_lo, g_wk_lo);
    cudaGetSymbolAddress(&wv_hi, g_wv_hi);  cudaGetSymbolAddress(&wv_lo, g_wv_lo);
    cudaGetSymbolAddress(&wo_hi, g_wo_hi);  cudaGetSymbolAddress(&wo_lo, g_wo_lo);
    cudaGetSymbolAddress(&wup, g_wup);      cudaGetSymbolAddress(&wdn, g_wdn);

    cudaFuncSetAttribute(attn_mma_k, cudaFuncAttributeMaxDynamicSharedMemorySize, ATT_SMEM);
    cudaFuncSetAttribute(mma_gemm_k<0>, cudaFuncAttributeMaxDynamicSharedMemorySize, DSMEM);
    cudaFuncSetAttribute(mma_gemm_k<1>, cudaFuncAttributeMaxDynamicSharedMemorySize, DSMEM);
    cudaFuncSetAttribute(mma_gemm_k<2>, cudaFuncAttributeMaxDynamicSharedMemorySize, DSMEM);
    cudaFuncSetAttribute(mma_gemm_k<3>, cudaFuncAttributeMaxDynamicSharedMemorySize, DSMEM);

    // side stream (created once; host objects only)
    static cudaStream_t s2 = nullptr;
    static cudaEvent_t evFork = nullptr, evJoin = nullptr;
    if (!s2) {
        cudaStreamCreate(&s2);
        cudaEventCreateWithFlags(&evFork, cudaEventDisableTiming);
        cudaEventCreateWithFlags(&evJoin, cudaEventDisableTiming);
    }

    // fork point at capture start (s2 kernels SUBMITTED later so attn is launch #6 for ncu)
    cudaEventRecord(evFork, 0);

    // ---- main chain on stream 0 (launches 1..6) ----
    split_k<<<(DMODEL * ATTN_D) / 2048, 256>>>((const float4*)Wq, (uint2*)wq_hi, (uint2*)wq_lo);
    split_k<<<(DMODEL * 512) / 2048, 256>>>((const float4*)Wk, (uint2*)wk_hi, (uint2*)wk_lo);
    split_k<<<(DMODEL * 512) / 2048, 256>>>((const float4*)Wv, (uint2*)wv_hi, (uint2*)wv_lo);
    rmsnorm1_split_k<<<S_LEN, 256>>>(hs, ln1);
    mma_gemm_k<0><<<dim3(QKV_N / 128, S_LEN / 128), 256, DSMEM>>>(qns, kns);
    attn_mma_k<<<dim3(S_LEN / 128, NHQ), 256, ATT_SMEM>>>();   // launch #6 -> ncu target

    // ---- deferred weight prep on s2 (independent; joined before Wo GEMM) ----
    cudaStreamWaitEvent(s2, evFork, 0);
    split_k<<<(ATTN_D * DMODEL) / 2048, 256, 0, s2>>>((const float4*)Wo, (uint2*)wo_hi, (uint2*)wo_lo);
    convert_k<<<(NEXP * DMODEL * FDIM) / 2048, 256, 0, s2>>>((const float4*)upW, (uint2*)wup);
    convert_k<<<(NEXP * FDIM * DMODEL) / 2048, 256, 0, s2>>>((const float4*)dnW, (uint2*)wdn);
    cudaEventRecord(evJoin, s2);
    cudaStreamWaitEvent(0, evJoin, 0);

    // 4. output projection + residual
    mma_gemm_k<1><<<dim3(DMODEL / 128, S_LEN / 128), 256, DSMEM>>>(hs, nullptr);
    // 5. fused rmsnorm2 + router (init first: zero counts, write aux)
    init_k<<<1, 32>>>(out);
    rmsnorm2_router_k<<<S_LEN, 256>>>(ln2, rW, out);
    // 6. MoE (gathered rows, 1-term fp16)
    mma_gemm_k<2><<<dim3(FDIM / 128, 16, NEXP), 256, DSMEM>>>(nullptr, upb);
    mma_gemm_k<3><<<dim3(DMODEL / 128, 16, NEXP), 256, DSMEM>>>(nullptr, dnb);
    // 7. final residual + MoE sum
    final_k<<<(S_LEN * DMODEL / 4) / 256, 256>>>(out);
}

// round 17
// speedup vs baseline: 6.3430x; 1.0110x over previous
#include <cuda_runtime.h>
#include <cuda_fp16.h>
#include <cuda_pipeline.h>
#include <math.h>
#include <stdint.h>

#define S_LEN 2048
#define DMODEL 2048
#define QKV_N 5120
#define NHQ 32
#define NHKV 4
#define HDIM 128
#define NEXP 8
#define FDIM 768
#define EPSV 1e-6f
#define ATTN_D (NHQ * HDIM)   // 4096

typedef __half f16;

// ================= scratch (device globals; no allocations allowed) =================
__device__ __align__(256) f16   g_x_hi[S_LEN * DMODEL];
__device__ __align__(256) f16   g_x_lo[S_LEN * DMODEL];
__device__ __align__(256) f16   g_qh[S_LEN * NHQ * HDIM];
__device__ __align__(256) f16   g_ql[S_LEN * NHQ * HDIM];
__device__ __align__(256) f16   g_kh[NHKV * S_LEN * HDIM];
__device__ __align__(256) f16   g_kl[NHKV * S_LEN * HDIM];
__device__ __align__(256) f16   g_vh[NHKV * S_LEN * HDIM];
__device__ __align__(256) f16   g_vl[NHKV * S_LEN * HDIM];
__device__ __align__(256) f16   g_attn_hi[S_LEN * ATTN_D];
__device__ __align__(256) f16   g_attn_lo[S_LEN * ATTN_D];
__device__ __align__(256) float g_hidden2[S_LEN * DMODEL];
__device__ __align__(256) f16   g_xf_hi[S_LEN * DMODEL];
__device__ __align__(256) f16   g_h_hi[S_LEN * 2 * FDIM];
__device__ __align__(256) float g_moepart[S_LEN * 2 * DMODEL];
__device__ float g_gate[S_LEN * 2];
__device__ int   g_cnt[NEXP];
__device__ int   g_list[NEXP][S_LEN];
// weights in NATIVE [K, N] layout; QKV/Wo split hi/lo (3-term), MoE single (1-term)
__device__ __align__(256) f16 g_wq_hi[DMODEL * ATTN_D];
__device__ __align__(256) f16 g_wq_lo[DMODEL * ATTN_D];
__device__ __align__(256) f16 g_wk_hi[DMODEL * 512];
__device__ __align__(256) f16 g_wk_lo[DMODEL * 512];
__device__ __align__(256) f16 g_wv_hi[DMODEL * 512];
__device__ __align__(256) f16 g_wv_lo[DMODEL * 512];
__device__ __align__(256) f16 g_wo_hi[ATTN_D * DMODEL];
__device__ __align__(256) f16 g_wo_lo[ATTN_D * DMODEL];
__device__ __align__(256) f16 g_wup[NEXP * DMODEL * FDIM];
__device__ __align__(256) f16 g_wdn[NEXP * FDIM * DMODEL];

// ================= PTX helpers =================
__device__ __forceinline__ uint32_t smem_u32(const void* p) {
    uint32_t a;
    asm("{ .reg .u64 t; cvta.to.shared.u64 t, %1; cvt.u32.u64 %0, t; }" : "=r"(a) : "l"(p));
    return a;
}
__device__ __forceinline__ void ldsm4(uint32_t a, uint32_t r[4]) {
    asm volatile("ldmatrix.sync.aligned.m8n8.x4.shared.b16 {%0,%1,%2,%3}, [%4];"
                 : "=r"(r[0]), "=r"(r[1]), "=r"(r[2]), "=r"(r[3]) : "r"(a));
}
__device__ __forceinline__ void ldsm4t(uint32_t a, uint32_t r[4]) {
    asm volatile("ldmatrix.sync.aligned.m8n8.x4.trans.shared.b16 {%0,%1,%2,%3}, [%4];"
                 : "=r"(r[0]), "=r"(r[1]), "=r"(r[2]), "=r"(r[3]) : "r"(a));
}
__device__ __forceinline__ void mma16816(float c[4], const uint32_t a[4], const uint32_t b[2]) {
    asm volatile(
        "mma.sync.aligned.m16n8k16.row.col.f32.f16.f16.f32 "
        "{%0,%1,%2,%3}, {%4,%5,%6,%7}, {%8,%9}, {%0,%1,%2,%3};"
        : "+f"(c[0]), "+f"(c[1]), "+f"(c[2]), "+f"(c[3])
        : "r"(a[0]), "r"(a[1]), "r"(a[2]), "r"(a[3]), "r"(b[0]), "r"(b[1]));
}
__device__ __forceinline__ uint32_t lds_addr(uint32_t base, int row, int kbyte) {
    int seg = kbyte >> 4;
    return base + row * 128 + (((uint32_t)(seg ^ (row & 7))) << 4);
}
__device__ __forceinline__ int off256(int row, int seg) {
    return row * 256 + ((seg ^ (row & 7)) << 4);
}
__device__ __forceinline__ uint32_t pkhf(float x, float y) {
    __half2 t = __floats2half2_rn(x, y);
    return *reinterpret_cast<uint32_t*>(&t);
}
__device__ __forceinline__ float hhi(float x, float& r) {
    float h = __half2float(__float2half_rn(x));
    r = x - h;
    return h;
}

// ================= weight prep (4 float4 per thread) =================
__global__ void split_k(const float4* __restrict__ in, uint2* __restrict__ hi,
                        uint2* __restrict__ lo) {
    size_t base = (size_t)blockIdx.x * 1024 + threadIdx.x;
#pragma unroll
    for (int u = 0; u < 4; u++) {
        size_t i = base + u * 256;
        float4 v = in[i];
        float r0, r1, r2, r3;
        float h0 = hhi(v.x, r0), h1 = hhi(v.y, r1), h2 = hhi(v.z, r2), h3 = hhi(v.w, r3);
        hi[i] = make_uint2(pkhf(h0, h1), pkhf(h2, h3));
        lo[i] = make_uint2(pkhf(r0, r1), pkhf(r2, r3));
    }
}
__global__ void convert_k(const float4* __restrict__ in, uint2* __restrict__ out) {
    size_t base = (size_t)blockIdx.x * 1024 + threadIdx.x;
#pragma unroll
    for (int u = 0; u < 4; u++) {
        size_t i = base + u * 256;
        float4 v = in[i];
        out[i] = make_uint2(pkhf(v.x, v.y), pkhf(v.z, v.w));
    }
}

// ================= rmsnorm1 (float4 vectorized) =================
__global__ void rmsnorm1_split_k(const float* __restrict__ in, const float* __restrict__ sc) {
    __shared__ float red[8];
    int row = blockIdx.x;
    int tid = threadIdx.x;
    const float4* r4 = (const float4*)(in + (size_t)row * DMODEL);
    const float4* s4 = (const float4*)sc;
    float4 v0 = r4[tid], v1 = r4[tid + 256];
    float ss = v0.x * v0.x + v0.y * v0.y + v0.z * v0.z + v0.w * v0.w
             + v1.x * v1.x + v1.y * v1.y + v1.z * v1.z + v1.w * v1.w;
    for (int o = 16; o; o >>= 1) ss += __shfl_xor_sync(0xffffffffu, ss, o);
    if ((tid & 31) == 0) red[tid >> 5] = ss;
    __syncthreads();
    float tot = 0.f;
#pragma unroll
    for (int i = 0; i < 8; i++) tot += red[i];
    float inv = rsqrtf(tot / (float)DMODEL + EPSV);
    float4 c0 = s4[tid], c1 = s4[tid + 256];
    size_t ob = (size_t)row * DMODEL;
    float ra, rb, rc, rd;
    float w0 = hhi(v0.x * inv * c0.x, ra), w1 = hhi(v0.y * inv * c0.y, rb);
    float w2 = hhi(v0.z * inv * c0.z, rc), w3 = hhi(v0.w * inv * c0.w, rd);
    *(uint2*)(g_x_hi + ob + 4 * tid) = make_uint2(pkhf(w0, w1), pkhf(w2, w3));
    *(uint2*)(g_x_lo + ob + 4 * tid) = make_uint2(pkhf(ra, rb), pkhf(rc, rd));
    float u0 = hhi(v1.x * inv * c1.x, ra), u1 = hhi(v1.y * inv * c1.y, rb);
    float u2 = hhi(v1.z * inv * c1.z, rc), u3 = hhi(v1.w * inv * c1.w, rd);
    *(uint2*)(g_x_hi + ob + 4 * tid + 1024) = make_uint2(pkhf(u0, u1), pkhf(u2, u3));
    *(uint2*)(g_x_lo + ob + 4 * tid + 1024) = make_uint2(pkhf(ra, rb), pkhf(rc, rd));
}

// ================= fused rmsnorm2 + router =================
__global__ void rmsnorm2_router_k(const float* __restrict__ sc, const float* __restrict__ rW,
                                  float* __restrict__ out) {
    __shared__ float xs[DMODEL];
    __shared__ float red[8];
    __shared__ float lg[NEXP];
    int row = blockIdx.x;
    int tid = threadIdx.x;
    const float4* r4 = (const float4*)(g_hidden2 + (size_t)row * DMODEL);
    const float4* s4 = (const float4*)sc;
    float4 v0 = r4[tid], v1 = r4[tid + 256];
    float ss = v0.x * v0.x + v0.y * v0.y + v0.z * v0.z + v0.w * v0.w
             + v1.x * v1.x + v1.y * v1.y + v1.z * v1.z + v1.w * v1.w;
    for (int o = 16; o; o >>= 1) ss += __shfl_xor_sync(0xffffffffu, ss, o);
    if ((tid & 31) == 0) red[tid >> 5] = ss;
    __syncthreads();
    float tot = 0.f;
#pragma unroll
    for (int i = 0; i < 8; i++) tot += red[i];
    float inv = rsqrtf(tot / (float)DMODEL + EPSV);
    float4 c0 = s4[tid], c1 = s4[tid + 256];
    float w0 = v0.x * inv * c0.x, w1 = v0.y * inv * c0.y;
    float w2 = v0.z * inv * c0.z, w3 = v0.w * inv * c0.w;
    float u0 = v1.x * inv * c1.x, u1 = v1.y * inv * c1.y;
    float u2 = v1.z * inv * c1.z, u3 = v1.w * inv * c1.w;
    xs[4 * tid] = w0; xs[4 * tid + 1] = w1; xs[4 * tid + 2] = w2; xs[4 * tid + 3] = w3;
    int t2 = tid + 256;
    xs[4 * t2] = u0; xs[4 * t2 + 1] = u1; xs[4 * t2 + 2] = u2; xs[4 * t2 + 3] = u3;
    size_t ob = (size_t)row * DMODEL;
    *(uint2*)(g_xf_hi + ob + 4 * tid) = make_uint2(pkhf(w0, w1), pkhf(w2, w3));
    *(uint2*)(g_xf_hi + ob + 4 * t2)  = make_uint2(pkhf(u0, u1), pkhf(u2, u3));
    __syncthreads();
    int w = tid >> 5, lane = tid & 31;
    float sum = 0.f;
    for (int dd = lane; dd < DMODEL; dd += 32) sum += xs[dd] * rW[dd * NEXP + w];
    for (int o = 16; o; o >>= 1) sum += __shfl_xor_sync(0xffffffffu, sum, o);
    if (lane == 0) lg[w] = sum;
    __syncthreads();
    if (tid == 0) {
        float* lo = out + (size_t)S_LEN * DMODEL + (size_t)row * NEXP;
        float mx = lg[0];
#pragma unroll
        for (int e = 1; e < NEXP; e++) mx = fmaxf(mx, lg[e]);
        float p[NEXP];
#pragma unroll
        for (int e = 0; e < NEXP; e++) { p[e] = expf(lg[e] - mx); lo[e] = lg[e]; }
        int i1 = 0;
#pragma unroll
        for (int e = 1; e < NEXP; e++) if (lg[e] > lg[i1]) i1 = e;
        int i2 = -1;
#pragma unroll
        for (int e = 0; e < NEXP; e++) {
            if (e == i1) continue;
            if (i2 < 0 || lg[e] > lg[i2]) i2 = e;
        }
        float denom = p[i1] + p[i2];
        g_gate[row * 2]     = p[i1] / denom;
        g_gate[row * 2 + 1] = p[i2] / denom;
        int pos = atomicAdd(&g_cnt[i1], 1);
        g_list[i1][pos] = row * 2;
        pos = atomicAdd(&g_cnt[i2], 1);
        g_list[i2][pos] = row * 2 + 1;
    }
}

// ================= HMMA GEMM (B native [K,N] via paired ldmatrix.x4.trans) =========
#define STAGE_BYTES 65536
#define DSMEM (3 * STAGE_BYTES + 1024)

template<int MODE>
__global__ __launch_bounds__(256, 1) void mma_gemm_k(const float* __restrict__ arg0,
                                                     const float* __restrict__ arg1) {
    constexpr int K   = (MODE == 1) ? ATTN_D : (MODE == 3) ? FDIM : DMODEL;
    constexpr int NCH = K / 64;
    constexpr bool THREE = (MODE < 2);

    extern __shared__ char dyn[];
    __shared__ int rows_s[128];

    int tid = threadIdx.x, wid = tid >> 5, lane = tid & 31;
    int e = blockIdx.z;
    int m0 = blockIdx.y * 128;
    int n0 = blockIdx.x * 128;

    int cnt = 0;
    if (MODE >= 2) {
        cnt = g_cnt[e];
        if (m0 >= cnt) return;
        if (tid < 128)
            rows_s[tid] = (m0 + tid < cnt) ? g_list[e][m0 + tid] : g_list[e][0];
        __syncthreads();
    }

    const f16 *Ahi, *Alo = nullptr, *Bhi, *Blo = nullptr;
    int ldB, bn;
    if (MODE == 0) {
        Ahi = g_x_hi; Alo = g_x_lo;
        if (n0 < 4096)      { Bhi = g_wq_hi; Blo = g_wq_lo; ldB = 4096; bn = n0; }
        else if (n0 < 4608) { Bhi = g_wk_hi; Blo = g_wk_lo; ldB = 512;  bn = n0 - 4096; }
        else                { Bhi = g_wv_hi; Blo = g_wv_lo; ldB = 512;  bn = n0 - 4608; }
    } else if (MODE == 1) {
        Ahi = g_attn_hi; Alo = g_attn_lo; Bhi = g_wo_hi; Blo = g_wo_lo; ldB = DMODEL; bn = n0;
    } else if (MODE == 2) {
        Ahi = g_xf_hi;
        Bhi = g_wup + (size_t)e * DMODEL * FDIM;
        ldB = FDIM; bn = n0;
    } else {
        Ahi = g_h_hi;
        Bhi = g_wdn + (size_t)e * FDIM * DMODEL;
        ldB = DMODEL; bn = n0;
    }

    uint32_t dyn_u = smem_u32(dyn);
    uint32_t tile0 = (dyn_u + 1023u) & ~1023u;
    char* tile0p = dyn + (tile0 - dyn_u);

    auto load_chunk = [&](int c, int s) {
        char* st = tile0p + s * STAGE_BYTES;
        for (int l = tid; l < 1024; l += 256) {
            int row = l >> 3, seg = l & 7;
            uint32_t off = (uint32_t)(row * 128 + seg * 16);
            uint32_t sw = off ^ ((off >> 3) & 0x70);
            size_t ar;
            if (MODE == 2)      ar = (size_t)(rows_s[row] >> 1) * K;
            else if (MODE == 3) ar = (size_t)rows_s[row] * K;
            else                ar = (size_t)(m0 + row) * K;
            __pipeline_memcpy_async(st + sw, (const char*)(Ahi + ar + (size_t)c * 64) + seg * 16, 16);
            if (THREE)
                __pipeline_memcpy_async(st + 16384 + sw, (const char*)(Alo + ar + (size_t)c * 64) + seg * 16, 16);
        }
        for (int l = tid; l < 1024; l += 256) {
            int row = l >> 4, seg = l & 15;
            int off = off256(row, seg);
            size_t src = (size_t)(c * 64 + row) * ldB + bn + seg * 8;
            __pipeline_memcpy_async(st + 32768 + off, (const char*)(Bhi + src), 16);
            if (THREE)
                __pipeline_memcpy_async(st + 49152 + off, (const char*)(Blo + src), 16);
        }
    };

    int warp_m0 = (wid >> 2) * 64;
    int warp_n0 = (wid & 3) * 32;
    int bseg0 = warp_n0 >> 3;
    int g = lane >> 2, tig = lane & 3;

    float c[4][4][4];
#pragma unroll
    for (int mi = 0; mi < 4; mi++)
#pragma unroll
        for (int nj = 0; nj < 4; nj++)
#pragma unroll
            for (int q = 0; q < 4; q++) c[mi][nj][q] = 0.f;

    load_chunk(0, 0);
    __pipeline_commit();
    load_chunk(1, 1);
    __pipeline_commit();

    for (int i = 0; i < NCH; i++) {
        __pipeline_wait_prior(1);
        __syncthreads();
        if (i + 2 < NCH) load_chunk(i + 2, (i + 2) % 3);
        __pipeline_commit();

        uint32_t su  = tile0 + (uint32_t)(i % 3) * STAGE_BYTES;
        uint32_t aHiB = su, aLoB = su + 16384, bHiB = su + 32768;

#pragma unroll
        for (int kk = 0; kk < 4; kk++) {
            uint32_t Ah[4][4], Al[4][4], Bh[4][2], Bl[4][2];
            int a_row = lane & 15;
            int a_kb  = 32 * kk + ((lane >> 4) << 4);
#pragma unroll
            for (int mi = 0; mi < 4; mi++) {
                int row = warp_m0 + 16 * mi + a_row;
                ldsm4(lds_addr(aHiB, row, a_kb), Ah[mi]);
                if (THREE) ldsm4(lds_addr(aLoB, row, a_kb), Al[mi]);
            }
            // B fragments: x4.trans pairs — lanes 16-31 fetch nj+1's segment
            int b_row = 16 * kk + (lane & 15);
#pragma unroll
            for (int njp = 0; njp < 2; njp++) {
                int nj = njp * 2;
                uint32_t r[4];
                uint32_t baddr = bHiB + off256(b_row, bseg0 + nj + (lane >> 4));
                ldsm4t(baddr, r);
                Bh[nj][0] = r[0]; Bh[nj][1] = r[1];
                Bh[nj + 1][0] = r[2]; Bh[nj + 1][1] = r[3];
                if (THREE) {
                    ldsm4t(baddr + 16384, r);
                    Bl[nj][0] = r[0]; Bl[nj][1] = r[1];
                    Bl[nj + 1][0] = r[2]; Bl[nj + 1][1] = r[3];
                }
            }
#pragma unroll
            for (int mi = 0; mi < 4; mi++)
#pragma unroll
                for (int nj = 0; nj < 4; nj++) {
                    mma16816(c[mi][nj], Ah[mi], Bh[nj]);
                    if (THREE) {
                        mma16816(c[mi][nj], Al[mi], Bh[nj]);
                        mma16816(c[mi][nj], Ah[mi], Bl[nj]);
                    }
                }
        }
    }

    // ---------- MODE 0 Q/K: fused qknorm + rope + fp16 split ----------
    if (MODE == 0 && n0 < 4608) {
        __syncthreads();   // all warps done computing before smem reuse
        float* S = (float*)tile0p;   // 128 x 132 fp32
#pragma unroll
        for (int mi = 0; mi < 4; mi++)
#pragma unroll
            for (int hh = 0; hh < 2; hh++) {
                int rl = warp_m0 + 16 * mi + 8 * hh + g;
#pragma unroll
                for (int nj = 0; nj < 4; nj++) {
                    int colL = warp_n0 + 8 * nj + 2 * tig;
                    S[rl * 132 + colL]     = c[mi][nj][2 * hh];
                    S[rl * 132 + colL + 1] = c[mi][nj][2 * hh + 1];
                }
            }
        __syncthreads();
        int isK = (n0 >= 4096);
        int head = (isK ? (n0 - 4096) : n0) >> 7;
        const float* sc = isK ? arg1 : arg0;
        f16* dsth = isK ? g_kh : g_qh;
        f16* dstl = isK ? g_kl : g_ql;
        // hoisted per-thread constants (d-dependent only)
        float invf[4], scd[4], scod[4];
        int odx[4];
#pragma unroll
        for (int k = 0; k < 4; k++) {
            int d = lane * 4 + k;
            int j = d & 63;
            invf[k] = expf(-0.21586735246819178f * (float)j);
            scd[k] = sc[d];
            odx[k] = (d < 64) ? d + 64 : d - 64;
            scod[k] = sc[odx[k]];
        }
        float qscale = isK ? 1.0f : 0.08838834764831845f;
        for (int rr = 0; rr < 16; rr++) {
            int row = wid * 16 + rr;
            const float* Sr = S + row * 132;
            float v[4];
            float ss = 0.f;
#pragma unroll
            for (int k = 0; k < 4; k++) { v[k] = Sr[lane * 4 + k]; ss += v[k] * v[k]; }
#pragma unroll
            for (int o = 16; o; o >>= 1) ss += __shfl_xor_sync(0xffffffffu, ss, o);
            float inv = rsqrtf(ss * (1.0f / 128.0f) + EPSV);
            int sg = m0 + row;
            uint32_t hiW[2], loW[2];
#pragma unroll
            for (int kp = 0; kp < 2; kp++) {
                float outv[2], remv[2];
#pragma unroll
                for (int k2 = 0; k2 < 2; k2++) {
                    int k = kp * 2 + k2;
                    int d = lane * 4 + k;
                    float n = v[k] * inv * scd[k];
                    float ang = (float)sg * invf[k];
                    float si, co;
                    sincosf(ang, &si, &co);
                    float no = Sr[odx[k]] * inv * scod[k];
                    float rot = (d < 64) ? -no : no;
                    float val = (n * co + rot * si) * qscale;
                    outv[k2] = hhi(val, remv[k2]);
                }
                hiW[kp] = pkhf(outv[0], outv[1]);
                loW[kp] = pkhf(remv[0], remv[1]);
            }
            size_t o = isK ? (((size_t)head * S_LEN + sg) * HDIM + lane * 4)
                           : (((size_t)sg * NHQ + head) * HDIM + lane * 4);
            *(uint2*)(dsth + o) = make_uint2(hiW[0], hiW[1]);
            *(uint2*)(dstl + o) = make_uint2(loW[0], loW[1]);
        }
        return;
    }

    // ---------------- generic epilogue ----------------
#pragma unroll
    for (int mi = 0; mi < 4; mi++) {
#pragma unroll
        for (int hh = 0; hh < 2; hh++) {
            int rl = warp_m0 + 16 * mi + 8 * hh + g;
            int grow = m0 + rl;
            bool valid = true;
            int slot = 0;
            if (MODE >= 2) { valid = grow < cnt; slot = rows_s[rl]; }
#pragma unroll
            for (int nj = 0; nj < 4; nj++) {
                int col = n0 + warp_n0 + 8 * nj + 2 * tig;
                float v0 = c[mi][nj][2 * hh];
                float v1 = c[mi][nj][2 * hh + 1];
                if (MODE == 0) {
                    // V columns only (n0 >= 4608)
                    int cc = col - 4608;
                    int kvh = cc >> 7, d = cc & 127;
                    size_t o = ((size_t)kvh * S_LEN + grow) * HDIM + d;
                    float r0, r1;
                    float h0 = hhi(v0, r0), h1 = hhi(v1, r1);
                    *(uint32_t*)(g_vh + o) = pkhf(h0, h1);
                    *(uint32_t*)(g_vl + o) = pkhf(r0, r1);
                } else if (MODE == 1) {
                    size_t base = (size_t)grow * DMODEL + col;
                    g_hidden2[base]     = v0 + arg0[base];
                    g_hidden2[base + 1] = v1 + arg0[base + 1];
                } else if (MODE == 2) {
                    if (valid) {
                        const float* bia = arg1 + e * FDIM;
                        float va = v0 + bia[col], vb = v1 + bia[col + 1];
                        float sa = va / (1.0f + expf(-va));
                        float sb = vb / (1.0f + expf(-vb));
                        *(uint32_t*)(g_h_hi + (size_t)slot * FDIM + col) = pkhf(sa, sb);
                    }
                } else {
                    if (valid) {
                        const float* bia = arg1 + e * DMODEL;
                        float gt = g_gate[slot];
                        *(float2*)(g_moepart + (size_t)slot * DMODEL + col) =
                            make_float2(gt * (v0 + bia[col]), gt * (v1 + bia[col + 1]));
                    }
                }
            }
        }
    }
}

// ================= HMMA flash attention (fp16, 3-term, masked-warp skip) =================
#define ATT_SMEM (65536 + 2 * 65536)
__global__ __launch_bounds__(256, 1) void attn_mma_k() {
    extern __shared__ char sm[];
    uint32_t sb = smem_u32(sm);
    int qi = gridDim.x - 1 - blockIdx.x;   // heaviest tiles first
    int h = blockIdx.y;
    int q0 = qi * 128, kvh = h >> 3;
    int nkv = 2 * (qi + 1);
    int tid = threadIdx.x, wid = tid >> 5, lane = tid & 31;
    int g = lane >> 2, tig = lane & 3;
    int wq0 = wid * 16;

    for (int l = tid; l < 2048; l += 256) {
        int row = l >> 4, seg = l & 15;
        int off = off256(row, seg);
        size_t src = ((size_t)(q0 + row) * NHQ + h) * HDIM + seg * 8;
        __pipeline_memcpy_async(sm + off,         g_qh + src, 16);
        __pipeline_memcpy_async(sm + 32768 + off, g_ql + src, 16);
    }

    auto fill_kv = [&](int t, int st) {
        char* base = sm + 65536 + st * 65536;
        int kv0 = t * 64;
        for (int l = tid; l < 1024; l += 256) {
            int row = l >> 4, seg = l & 15;
            int off = off256(row, seg);
            size_t src = ((size_t)kvh * S_LEN + kv0 + row) * HDIM + seg * 8;
            __pipeline_memcpy_async(base + off,         g_kh + src, 16);
            __pipeline_memcpy_async(base + 16384 + off, g_kl + src, 16);
            __pipeline_memcpy_async(base + 32768 + off, g_vh + src, 16);
            __pipeline_memcpy_async(base + 49152 + off, g_vl + src, 16);
        }
    };

    float o[16][4];
#pragma unroll
    for (int dj = 0; dj < 16; dj++)
#pragma unroll
        for (int q = 0; q < 4; q++) o[dj][q] = 0.f;
    float m0 = -3e38f, m1 = -3e38f, l0 = 0.f, l1 = 0.f;

    fill_kv(0, 0);
    __pipeline_commit();

    for (int t = 0; t < nkv; t++) {
        __pipeline_wait_prior(0);      // fill t (and Q on t=0) complete
        __syncthreads();               // all warps past compute t-1
        if (t + 1 < nkv) { fill_kv(t + 1, (t + 1) & 1); __pipeline_commit(); }

        int k0 = t * 64;
        // warp's rows are q0+wq0 .. q0+wq0+15; tile fully masked if k0 > last row
        if (k0 > q0 + wq0 + 15) continue;   // identity: P=0, alpha=1 (no syncs in body)

        uint32_t st  = sb + 65536 + (uint32_t)(t & 1) * 65536;

        float s[8][4];
#pragma unroll
        for (int nj = 0; nj < 8; nj++)
#pragma unroll
            for (int q = 0; q < 4; q++) s[nj][q] = 0.f;

#pragma unroll
        for (int kk = 0; kk < 8; kk++) {
            uint32_t aqh[4], aql[4];
            int a_row = wq0 + (lane & 15);
            int a_sb  = kk * 2 + ((lane >> 4) & 1);
            uint32_t aaddr = sb + off256(a_row, a_sb);
            ldsm4(aaddr, aqh);
            ldsm4(aaddr + 32768, aql);
            // K fragments: x4 pairs — lanes 16-31 fetch nj+1's rows
            uint32_t Bh[8][2], Bl[8][2];
#pragma unroll
            for (int njp = 0; njp < 4; njp++) {
                int nj = njp * 2;
                int b_row = (nj + (lane >> 4)) * 8 + (lane & 7);
                int b_sb  = kk * 2 + ((lane >> 3) & 1);
                uint32_t baddr = st + off256(b_row, b_sb);
                uint32_t r[4];
                ldsm4(baddr, r);
                Bh[nj][0] = r[0]; Bh[nj][1] = r[1];
                Bh[nj + 1][0] = r[2]; Bh[nj + 1][1] = r[3];
                ldsm4(baddr + 16384, r);
                Bl[nj][0] = r[0]; Bl[nj][1] = r[1];
                Bl[nj + 1][0] = r[2]; Bl[nj + 1][1] = r[3];
            }
#pragma unroll
            for (int nj = 0; nj < 8; nj++) {
                mma16816(s[nj], aqh, Bh[nj]);
                mma16816(s[nj], aql, Bh[nj]);
                mma16816(s[nj], aqh, Bl[nj]);
            }
        }

        if (k0 + 63 > q0 + wq0) {
            int r0 = q0 + wq0 + g, r1 = r0 + 8;
#pragma unroll
            for (int nj = 0; nj < 8; nj++) {
                int col = k0 + nj * 8 + 2 * tig;
                if (col > r0)     s[nj][0] = -1e9f;
                if (col + 1 > r0) s[nj][1] = -1e9f;
                if (col > r1)     s[nj][2] = -1e9f;
                if (col + 1 > r1) s[nj][3] = -1e9f;
            }
        }

        float mx0 = m0, mx1 = m1;
#pragma unroll
        for (int nj = 0; nj < 8; nj++) {
            mx0 = fmaxf(mx0, fmaxf(s[nj][0], s[nj][1]));
            mx1 = fmaxf(mx1, fmaxf(s[nj][2], s[nj][3]));
        }
        mx0 = fmaxf(mx0, __shfl_xor_sync(0xffffffffu, mx0, 1));
        mx0 = fmaxf(mx0, __shfl_xor_sync(0xffffffffu, mx0, 2));
        mx1 = fmaxf(mx1, __shfl_xor_sync(0xffffffffu, mx1, 1));
        mx1 = fmaxf(mx1, __shfl_xor_sync(0xffffffffu, mx1, 2));
        float a0 = __expf(m0 - mx0), a1 = __expf(m1 - mx1);
        m0 = mx0; m1 = mx1;
        l0 *= a0; l1 *= a1;
#pragma unroll
        for (int dj = 0; dj < 16; dj++) {
            o[dj][0] *= a0; o[dj][1] *= a0;
            o[dj][2] *= a1; o[dj][3] *= a1;
        }

        uint32_t phi[8][2], plo[8][2];
#pragma unroll
        for (int nj = 0; nj < 8; nj++) {
            float p00 = __expf(s[nj][0] - mx0), p01 = __expf(s[nj][1] - mx0);
            float p10 = __expf(s[nj][2] - mx1), p11 = __expf(s[nj][3] - mx1);
            l0 += p00 + p01; l1 += p10 + p11;
            float r00, r01, r10, r11;
            float h00 = hhi(p00, r00), h01 = hhi(p01, r01);
            float h10 = hhi(p10, r10), h11 = hhi(p11, r11);
            phi[nj][0] = pkhf(h00, h01); phi[nj][1] = pkhf(h10, h11);
            plo[nj][0] = pkhf(r00, r01); plo[nj][1] = pkhf(r10, r11);
        }

        uint32_t vh_b = st + 32768;
#pragma unroll
        for (int kc = 0; kc < 4; kc++) {
            uint32_t aph[4] = { phi[2 * kc][0], phi[2 * kc][1], phi[2 * kc + 1][0], phi[2 * kc + 1][1] };
            uint32_t apl[4] = { plo[2 * kc][0], plo[2 * kc][1], plo[2 * kc + 1][0], plo[2 * kc + 1][1] };
            // V fragments: x4.trans pairs — lanes 16-31 fetch dj+1's segment
#pragma unroll
            for (int djp = 0; djp < 8; djp++) {
                int dj = djp * 2;
                int v_row = kc * 16 + (lane & 15);
                uint32_t vaddr = vh_b + off256(v_row, dj + (lane >> 4));
                uint32_t rh[4], rl[4];
                ldsm4t(vaddr, rh);
                ldsm4t(vaddr + 16384, rl);
                uint32_t b0[2] = { rh[0], rh[1] }, b1[2] = { rh[2], rh[3] };
                uint32_t c0[2] = { rl[0], rl[1] }, c1[2] = { rl[2], rl[3] };
                mma16816(o[dj], aph, b0);
                mma16816(o[dj], apl, b0);
                mma16816(o[dj], aph, c0);
                mma16816(o[dj + 1], aph, b1);
                mma16816(o[dj + 1], apl, b1);
                mma16816(o[dj + 1], aph, c1);
            }
        }
    }

    l0 += __shfl_xor_sync(0xffffffffu, l0, 1);
    l0 += __shfl_xor_sync(0xffffffffu, l0, 2);
    l1 += __shfl_xor_sync(0xffffffffu, l1, 1);
    l1 += __shfl_xor_sync(0xffffffffu, l1, 2);
    float i0 = 1.0f / l0, i1 = 1.0f / l1;
    int r0 = q0 + wq0 + g, r1 = r0 + 8;
#pragma unroll
    for (int dj = 0; dj < 16; dj++) {
        int cc = dj * 8 + 2 * tig;
        size_t o0 = (size_t)r0 * ATTN_D + h * HDIM + cc;
        size_t o1 = (size_t)r1 * ATTN_D + h * HDIM + cc;
        float ra, rb;
        float v0 = o[dj][0] * i0, v1 = o[dj][1] * i0;
        float h0 = hhi(v0, ra), h1 = hhi(v1, rb);
        *(uint32_t*)(g_attn_hi + o0) = pkhf(h0, h1);
        *(uint32_t*)(g_attn_lo + o0) = pkhf(ra, rb);
        float w0 = o[dj][2] * i1, w1 = o[dj][3] * i1;
        h0 = hhi(w0, ra); h1 = hhi(w1, rb);
        *(uint32_t*)(g_attn_hi + o1) = pkhf(h0, h1);
        *(uint32_t*)(g_attn_lo + o1) = pkhf(ra, rb);
    }
}

// ================= init / final =================
__global__ void init_k(float* __restrict__ out) {
    if (threadIdx.x < NEXP) g_cnt[threadIdx.x] = 0;
    if (threadIdx.x == 0) out[(size_t)S_LEN * DMODEL + S_LEN * NEXP] = 1.0f;
}

__global__ void final_k(float* __restrict__ out) {
    int i = blockIdx.x * 256 + threadIdx.x;   // float4 index
    int t = i / (DMODEL / 4);
    int d = i - t * (DMODEL / 4);
    const float4* h2 = (const float4*)g_hidden2;
    const float4* mp = (const float4*)g_moepart;
    float4 a = h2[i];
    float4 b = mp[(size_t)(2 * t) * (DMODEL / 4) + d];
    float4 c = mp[(size_t)(2 * t + 1) * (DMODEL / 4) + d];
    float4 w;
    w.x = a.x + b.x + c.x; w.y = a.y + b.y + c.y;
    w.z = a.z + b.z + c.z; w.w = a.w + b.w + c.w;
    ((float4*)out)[i] = w;
}

// ================= launch =================
extern "C" void kernel_launch(void* const* d_in, const int* in_sizes, int n_in,
                              void* d_out, int out_size) {
    const float* hs  = (const float*)d_in[0];
    const float* ln1 = (const float*)d_in[1];
    const float* ln2 = (const float*)d_in[2];
    const float* Wq  = (const float*)d_in[3];
    const float* Wk  = (const float*)d_in[4];
    const float* Wv  = (const float*)d_in[5];
    const float* Wo  = (const float*)d_in[6];
    const float* qns = (const float*)d_in[7];
    const float* kns = (const float*)d_in[8];
    const float* rW  = (const float*)d_in[9];
    const float* upW = (const float*)d_in[10];
    const float* upb = (const float*)d_in[11];
    const float* dnW = (const float*)d_in[12];
    const float* dnb = (const float*)d_in[13];
    float* out = (float*)d_out;

    void *wq_hi, *wq_lo, *wk_hi, *wk_lo, *wv_hi, *wv_lo, *wo_hi, *wo_lo, *wup, *wdn;
    cudaGetSymbolAddress(&wq_hi, g_wq_hi);  cudaGetSymbolAddress(&wq_lo, g_wq_lo);
    cudaGetSymbolAddress(&wk_hi, g_wk_hi);  cudaGetSymbolAddress(&wk_lo, g_wk_lo);
    cudaGetSymbolAddress(&wv_hi, g_wv_hi);  cudaGetSymbolAddress(&wv_lo, g_wv_lo);
    cudaGetSymbolAddress(&wo_hi, g_wo_hi);  cudaGetSymbolAddress(&wo_lo, g_wo_lo);
    cudaGetSymbolAddress(&wup, g_wup);      cudaGetSymbolAddress(&wdn, g_wdn);

    cudaFuncSetAttribute(attn_mma_k, cudaFuncAttributeMaxDynamicSharedMemorySize, ATT_SMEM);
    cudaFuncSetAttribute(mma_gemm_k<0>, cudaFuncAttributeMaxDynamicSharedMemorySize, DSMEM);
    cudaFuncSetAttribute(mma_gemm_k<1>, cudaFuncAttributeMaxDynamicSharedMemorySize, DSMEM);
    cudaFuncSetAttribute(mma_gemm_k<2>, cudaFuncAttributeMaxDynamicSharedMemorySize, DSMEM);
    cudaFuncSetAttribute(mma_gemm_k<3>, cudaFuncAttributeMaxDynamicSharedMemorySize, DSMEM);

    // side stream (created once; host objects only)
    static cudaStream_t s2 = nullptr;
    static cudaEvent_t evFork = nullptr, evJoin = nullptr;
    if (!s2) {
        cudaStreamCreate(&s2);
        cudaEventCreateWithFlags(&evFork, cudaEventDisableTiming);
        cudaEventCreateWithFlags(&evJoin, cudaEventDisableTiming);
    }

    cudaEventRecord(evFork, 0);

    // ---- main chain on stream 0 ----
    split_k<<<(DMODEL * ATTN_D) / 4096, 256>>>((const float4*)Wq, (uint2*)wq_hi, (uint2*)wq_lo);
    split_k<<<(DMODEL * 512) / 4096, 256>>>((const float4*)Wk, (uint2*)wk_hi, (uint2*)wk_lo);
    split_k<<<(DMODEL * 512) / 4096, 256>>>((const float4*)Wv, (uint2*)wv_hi, (uint2*)wv_lo);
    rmsnorm1_split_k<<<S_LEN, 256>>>(hs, ln1);
    mma_gemm_k<0><<<dim3(QKV_N / 128, S_LEN / 128), 256, DSMEM>>>(qns, kns);
    attn_mma_k<<<dim3(S_LEN / 128, NHQ), 256, ATT_SMEM>>>();

    // ---- deferred weight prep on s2 (independent; joined before Wo GEMM) ----
    cudaStreamWaitEvent(s2, evFork, 0);
    split_k<<<(ATTN_D * DMODEL) / 4096, 256, 0, s2>>>((const float4*)Wo, (uint2*)wo_hi, (uint2*)wo_lo);
    convert_k<<<(NEXP * DMODEL * FDIM) / 4096, 256, 0, s2>>>((const float4*)upW, (uint2*)wup);
    convert_k<<<(NEXP * FDIM * DMODEL) / 4096, 256, 0, s2>>>((const float4*)dnW, (uint2*)wdn);
    cudaEventRecord(evJoin, s2);
    cudaStreamWaitEvent(0, evJoin, 0);

    // output projection + residual
    mma_gemm_k<1><<<dim3(DMODEL / 128, S_LEN / 128), 256, DSMEM>>>(hs, nullptr);
    // fused rmsnorm2 + router (init first: zero counts, write aux)
    init_k<<<1, 32>>>(out);
    rmsnorm2_router_k<<<S_LEN, 256>>>(ln2, rW, out);
    // MoE (gathered rows, 1-term fp16)
    mma_gemm_k<2><<<dim3(FDIM / 128, 16, NEXP), 256, DSMEM>>>(nullptr, upb);
    mma_gemm_k<3><<<dim3(DMODEL / 128, 16, NEXP), 256, DSMEM>>>(nullptr, dnb);
    // final residual + MoE sum
    final_k<<<(S_LEN * DMODEL / 4) / 256, 256>>>(out);
}